// round 1
// baseline (speedup 1.0000x reference)
#include <cuda_runtime.h>
#include <math.h>
#include <stdint.h>

// ---------------------------------------------------------------------------
// Mamba3Block on GB300 — round 1: correct fp32 baseline.
//   out = OutProj( Scan( ... ) ), see reference. All big ops as tiled SGEMM,
//   scans parallelized via 3-pass chunked scan over L.
// ---------------------------------------------------------------------------

namespace {
constexpr int B_   = 2;
constexpr int L_   = 4096;
constexpr int DM   = 1024;   // d_model
constexpr int DI   = 2048;   // d_inner == d_state
constexpr int M_   = B_ * L_;        // 8192 rows
constexpr int NCH  = 32;             // scan chunks per sequence
constexpr int CH   = L_ / NCH;       // 128
}

// ------------------------- scratch (static device mem) ---------------------
__device__ float g_xz[(size_t)M_ * 2 * DI];   // in_proj output [M, 4096]
__device__ float g_x [(size_t)M_ * DI];       // conv+silu output; later reused as out_pre
__device__ float g_x2[(size_t)M_ * DI];       // x + x@A_real
__device__ float g_bx[(size_t)M_ * DI];       // Bx -> states (cumsum in place)
__device__ float g_u [(size_t)M_ * DI];       // x2 + mimo (scan input u)
__device__ float g_dc[(size_t)M_ * DI];       // decay
__device__ float g_p1[B_ * NCH * DI];         // cumsum chunk sums
__device__ float g_p2[B_ * NCH * DI];         // scan chunk P (prod decay)
__device__ float g_p3[B_ * NCH * DI];         // scan chunk S (local state)
__device__ float g_cr[B_ * NCH * DI];         // carry-in per chunk

__device__ __forceinline__ float siluf(float v) { return v / (1.f + expf(-v)); }

// ------------------------------- SGEMM -------------------------------------
// C[M,N] = A[M,K] * op(B)   op(B): TB ? B[N,K] (transposed) : B[K,N]
// EPI: 0 none, 1 C = acc + R, 2 C += acc (beta=1), 3 decay epilogue
template<bool TB, int EPI>
__global__ __launch_bounds__(256)
void sgemm_kernel(const float* __restrict__ A, const float* __restrict__ Bm,
                  float* __restrict__ C, const float* __restrict__ R,
                  const float* __restrict__ v1, const float* __restrict__ v2,
                  int M, int N, int K)
{
    constexpr int BK = 8;
    __shared__ float As[BK][128];
    __shared__ float Bs[BK][128];
    const int tid = threadIdx.x;
    const int bn  = blockIdx.x * 128;
    const int bm  = blockIdx.y * 128;
    const int tx  = tid & 15;    // 16 threads across N
    const int ty  = tid >> 4;    // 16 threads across M

    // loader indices (all dims here are exact multiples of tile sizes)
    const int lRow  = tid >> 1;          // 0..127
    const int lCol  = (tid & 1) << 2;    // 0 or 4
    const int bkRow = tid >> 5;          // 0..7
    const int bnCol = (tid & 31) << 2;   // 0..124

    float acc[8][8];
    #pragma unroll
    for (int i = 0; i < 8; i++)
        #pragma unroll
        for (int j = 0; j < 8; j++) acc[i][j] = 0.f;

    for (int k0 = 0; k0 < K; k0 += BK) {
        float4 av = *reinterpret_cast<const float4*>(&A[(size_t)(bm + lRow) * K + k0 + lCol]);
        As[lCol + 0][lRow] = av.x; As[lCol + 1][lRow] = av.y;
        As[lCol + 2][lRow] = av.z; As[lCol + 3][lRow] = av.w;
        if (TB) {
            float4 bv = *reinterpret_cast<const float4*>(&Bm[(size_t)(bn + lRow) * K + k0 + lCol]);
            Bs[lCol + 0][lRow] = bv.x; Bs[lCol + 1][lRow] = bv.y;
            Bs[lCol + 2][lRow] = bv.z; Bs[lCol + 3][lRow] = bv.w;
        } else {
            float4 bv = *reinterpret_cast<const float4*>(&Bm[(size_t)(k0 + bkRow) * N + bn + bnCol]);
            *reinterpret_cast<float4*>(&Bs[bkRow][bnCol]) = bv;
        }
        __syncthreads();
        #pragma unroll
        for (int kk = 0; kk < BK; kk++) {
            float ar[8], br[8];
            #pragma unroll
            for (int i = 0; i < 8; i++) ar[i] = As[kk][ty * 8 + i];
            #pragma unroll
            for (int j = 0; j < 8; j++) br[j] = Bs[kk][tx * 8 + j];
            #pragma unroll
            for (int i = 0; i < 8; i++)
                #pragma unroll
                for (int j = 0; j < 8; j++)
                    acc[i][j] = fmaf(ar[i], br[j], acc[i][j]);
        }
        __syncthreads();
    }

    #pragma unroll
    for (int i = 0; i < 8; i++) {
        const int row = bm + ty * 8 + i;
        #pragma unroll
        for (int j0 = 0; j0 < 8; j0 += 4) {
            const int col = bn + tx * 8 + j0;
            float v[4];
            #pragma unroll
            for (int j = 0; j < 4; j++) v[j] = acc[i][j0 + j];
            if constexpr (EPI == 1) {
                float4 rv = *reinterpret_cast<const float4*>(&R[(size_t)row * N + col]);
                v[0] += rv.x; v[1] += rv.y; v[2] += rv.z; v[3] += rv.w;
            } else if constexpr (EPI == 2) {
                float4 cv = *reinterpret_cast<const float4*>(&C[(size_t)row * N + col]);
                v[0] += cv.x; v[1] += cv.y; v[2] += cv.z; v[3] += cv.w;
            } else if constexpr (EPI == 3) {
                #pragma unroll
                for (int j = 0; j < 4; j++) {
                    float t  = v[j] + v1[col + j];
                    float sp = (t > 20.f) ? t : log1pf(expf(t));
                    v[j] = expf(-expf(v2[col + j]) * sp);
                }
            }
            *reinterpret_cast<float4*>(&C[(size_t)row * N + col]) =
                make_float4(v[0], v[1], v[2], v[3]);
        }
    }
}

// ------------------------- conv (depthwise, causal, k=4) + SiLU ------------
__global__ void conv_silu_kernel(const float* __restrict__ w, const float* __restrict__ bias)
{
    int i = blockIdx.x * blockDim.x + threadIdx.x;
    if (i >= M_ * DI) return;
    int c  = i % DI;
    int l  = (i / DI) % L_;
    int bb = i / (DI * L_);
    const float* base = g_xz + (size_t)bb * L_ * (2 * DI) + c;  // x part, row stride 2*DI
    float acc = bias[c];
    #pragma unroll
    for (int k = 0; k < 4; k++) {
        int ll = l - 3 + k;
        if (ll >= 0) acc = fmaf(w[c * 4 + k], base[(size_t)ll * (2 * DI)], acc);
    }
    g_x[i] = siluf(acc);
}

// ------------------------------ cumsum over L (3 passes) -------------------
__global__ void cumsum_p1()
{
    int c   = blockIdx.x * blockDim.x + threadIdx.x;   // channel
    int seq = blockIdx.y;                              // b*NCH + chunk
    int bb = seq / NCH, ch = seq % NCH;
    size_t base = ((size_t)(bb * L_ + ch * CH)) * DI + c;
    float s = 0.f;
    for (int i = 0; i < CH; i++) s += g_bx[base + (size_t)i * DI];
    g_p1[seq * DI + c] = s;
}
__global__ void cumsum_p2()
{
    int i = blockIdx.x * blockDim.x + threadIdx.x;     // b*DI + c
    if (i >= B_ * DI) return;
    int bb = i / DI, c = i % DI;
    float carry = 0.f;
    for (int ch = 0; ch < NCH; ch++) {
        int idx = (bb * NCH + ch) * DI + c;
        g_cr[idx] = carry;
        carry += g_p1[idx];
    }
}
__global__ void cumsum_p3()
{
    int c   = blockIdx.x * blockDim.x + threadIdx.x;
    int seq = blockIdx.y;
    int bb = seq / NCH, ch = seq % NCH;
    size_t base = ((size_t)(bb * L_ + ch * CH)) * DI + c;
    float carry = g_cr[seq * DI + c];
    for (int i = 0; i < CH; i++) {
        size_t idx = base + (size_t)i * DI;
        carry += g_bx[idx];
        g_bx[idx] = carry;          // in-place: Bx -> states
    }
}

// ----------------------- decay recurrence scan (3 passes) ------------------
// state[l] = decay[l]*state[l-1] + u[l]
__global__ void scan_p1()
{
    int c   = blockIdx.x * blockDim.x + threadIdx.x;
    int seq = blockIdx.y;
    int bb = seq / NCH, ch = seq % NCH;
    size_t base = ((size_t)(bb * L_ + ch * CH)) * DI + c;
    float P = 1.f, S = 0.f;
    for (int i = 0; i < CH; i++) {
        size_t idx = base + (size_t)i * DI;
        float d = g_dc[idx];
        S = fmaf(d, S, g_u[idx]);
        P *= d;
    }
    g_p2[seq * DI + c] = P;
    g_p3[seq * DI + c] = S;
}
__global__ void scan_p2()
{
    int i = blockIdx.x * blockDim.x + threadIdx.x;
    if (i >= B_ * DI) return;
    int bb = i / DI, c = i % DI;
    float carry = 0.f;
    for (int ch = 0; ch < NCH; ch++) {
        int idx = (bb * NCH + ch) * DI + c;
        g_cr[idx] = carry;
        carry = fmaf(g_p2[idx], carry, g_p3[idx]);
    }
}
// pass 3 fuses: out_pre = (state + u*D_ss) * silu(z)   (written into g_x)
__global__ void scan_p3(const float* __restrict__ D_ss)
{
    int c   = blockIdx.x * blockDim.x + threadIdx.x;
    int seq = blockIdx.y;
    int bb = seq / NCH, ch = seq % NCH;
    int l0 = ch * CH;
    size_t base = ((size_t)(bb * L_ + l0)) * DI + c;
    float state = g_cr[seq * DI + c];
    float dss = D_ss[c];
    for (int i = 0; i < CH; i++) {
        size_t idx = base + (size_t)i * DI;
        float u = g_u[idx];
        state = fmaf(g_dc[idx], state, u);
        float z = g_xz[(size_t)(bb * L_ + l0 + i) * (2 * DI) + DI + c];
        g_x[idx] = (state + u * dss) * siluf(z);
    }
}

// ------------------------------- launcher ----------------------------------
extern "C" void kernel_launch(void* const* d_in, const int* in_sizes, int n_in,
                              void* d_out, int out_size)
{
    const float* h         = (const float*)d_in[0];
    const float* delta     = (const float*)d_in[1];
    const float* in_proj_w = (const float*)d_in[2];
    const float* conv_w    = (const float*)d_in[3];
    const float* conv_b    = (const float*)d_in[4];
    const float* A_real    = (const float*)d_in[5];
    const float* B_w       = (const float*)d_in[6];
    const float* C_w       = (const float*)d_in[7];
    const float* D_w       = (const float*)d_in[8];
    const float* dt_proj_w = (const float*)d_in[9];
    const float* dt_proj_b = (const float*)d_in[10];
    const float* A_log     = (const float*)d_in[11];
    const float* D_ss      = (const float*)d_in[12];
    const float* out_proj_w= (const float*)d_in[13];
    float* out = (float*)d_out;

    float *xz, *x, *x2, *bx, *u, *dc;
    cudaGetSymbolAddress((void**)&xz, g_xz);
    cudaGetSymbolAddress((void**)&x,  g_x);
    cudaGetSymbolAddress((void**)&x2, g_x2);
    cudaGetSymbolAddress((void**)&bx, g_bx);
    cudaGetSymbolAddress((void**)&u,  g_u);
    cudaGetSymbolAddress((void**)&dc, g_dc);

    const dim3 blk(256);
    const dim3 gSeq(DI / 256, B_ * NCH);

    // 1) xz = h @ in_proj_w^T            [8192,4096]
    sgemm_kernel<true, 0><<<dim3(2 * DI / 128, M_ / 128), blk>>>(
        h, in_proj_w, xz, nullptr, nullptr, nullptr, M_, 2 * DI, DM);

    // 2) depthwise causal conv + bias + SiLU -> g_x
    conv_silu_kernel<<<(M_ * DI) / 256, 256>>>(conv_w, conv_b);

    // 3) x2 = x + x @ A_real             (A_real not transposed)
    sgemm_kernel<false, 1><<<dim3(DI / 128, M_ / 128), blk>>>(
        x, A_real, x2, x, nullptr, nullptr, M_, DI, DI);

    // 4) Bx = x2 @ B_w^T
    sgemm_kernel<true, 0><<<dim3(DI / 128, M_ / 128), blk>>>(
        x2, B_w, bx, nullptr, nullptr, nullptr, M_, DI, DI);

    // 5) states = cumsum_L(Bx)  (in place in g_bx)
    cumsum_p1<<<gSeq, 256>>>();
    cumsum_p2<<<(B_ * DI) / 256, 256>>>();
    cumsum_p3<<<gSeq, 256>>>();

    // 6) u = x2 + states @ C_w^T
    sgemm_kernel<true, 1><<<dim3(DI / 128, M_ / 128), blk>>>(
        bx, C_w, u, x2, nullptr, nullptr, M_, DI, DI);

    // 7) u += x2 @ D_w^T
    sgemm_kernel<true, 2><<<dim3(DI / 128, M_ / 128), blk>>>(
        x2, D_w, u, nullptr, nullptr, nullptr, M_, DI, DI);

    // 8) decay = exp(-exp(A_log) * softplus(delta @ dt_proj_w^T + dt_proj_b))
    sgemm_kernel<true, 3><<<dim3(DI / 128, M_ / 128), blk>>>(
        delta, dt_proj_w, dc, nullptr, dt_proj_b, A_log, M_, DI, 64);

    // 9) decay scan; pass3 fuses (+ u*D_ss) * silu(z) -> g_x (out_pre)
    scan_p1<<<gSeq, 256>>>();
    scan_p2<<<(B_ * DI) / 256, 256>>>();
    scan_p3<<<gSeq, 256>>>(D_ss);

    // 10) out = out_pre @ out_proj_w^T   [8192,1024]
    sgemm_kernel<true, 0><<<dim3(DM / 128, M_ / 128), blk>>>(
        x, out_proj_w, out, nullptr, nullptr, nullptr, M_, DM, DI);
}

// round 3
// speedup vs baseline: 2.7559x; 2.7559x over previous
#include <cuda_runtime.h>
#include <cuda_bf16.h>
#include <math.h>
#include <stdint.h>

// ---------------------------------------------------------------------------
// Mamba3Block on GB300 — round 3: mma.sync bf16x3 (split) GEMMs.
// (tcgen05 is sm_103a-only and this toolchain targets plain sm_103 PTX.)
// ---------------------------------------------------------------------------

namespace {
constexpr int B_   = 2;
constexpr int L_   = 4096;
constexpr int DM   = 1024;
constexpr int DI   = 2048;
constexpr int M_   = B_ * L_;        // 8192
constexpr int NCH  = 32;
constexpr int CH   = L_ / NCH;       // 128
constexpr int TWO_DI = 2 * DI;       // 4096
}

// ------------------------- fp32 scratch ------------------------------------
__device__ float g_xz[(size_t)M_ * TWO_DI];
__device__ float g_x [(size_t)M_ * DI];
__device__ float g_x2[(size_t)M_ * DI];
__device__ float g_bx[(size_t)M_ * DI];
__device__ float g_u [(size_t)M_ * DI];
__device__ float g_dc[(size_t)M_ * DI];
__device__ float g_p1[B_ * NCH * DI];
__device__ float g_p2[B_ * NCH * DI];
__device__ float g_p3[B_ * NCH * DI];
__device__ float g_cr[B_ * NCH * DI];

// ------------------------- bf16 split scratch ------------------------------
__device__ __nv_bfloat16 g_h_hi [(size_t)M_ * DM],  g_h_lo [(size_t)M_ * DM];
__device__ __nv_bfloat16 g_x_hi [(size_t)M_ * DI],  g_x_lo [(size_t)M_ * DI];
__device__ __nv_bfloat16 g_x2_hi[(size_t)M_ * DI],  g_x2_lo[(size_t)M_ * DI];
__device__ __nv_bfloat16 g_st_hi[(size_t)M_ * DI],  g_st_lo[(size_t)M_ * DI];
__device__ __nv_bfloat16 g_op_hi[(size_t)M_ * DI],  g_op_lo[(size_t)M_ * DI];
__device__ __nv_bfloat16 g_w1_hi[(size_t)TWO_DI * DM], g_w1_lo[(size_t)TWO_DI * DM];
__device__ __nv_bfloat16 g_at_hi[(size_t)DI * DI],  g_at_lo[(size_t)DI * DI];
__device__ __nv_bfloat16 g_bw_hi[(size_t)DI * DI],  g_bw_lo[(size_t)DI * DI];
__device__ __nv_bfloat16 g_cw_hi[(size_t)DI * DI],  g_cw_lo[(size_t)DI * DI];
__device__ __nv_bfloat16 g_dw_hi[(size_t)DI * DI],  g_dw_lo[(size_t)DI * DI];
__device__ __nv_bfloat16 g_wo_hi[(size_t)DM * DI],  g_wo_lo[(size_t)DM * DI];

__device__ __forceinline__ float siluf(float v) { return v / (1.f + expf(-v)); }

__device__ __forceinline__ void split1(float v, __nv_bfloat16& h, __nv_bfloat16& l) {
    h = __float2bfloat16(v);
    l = __float2bfloat16(v - __bfloat162float(h));
}

// --------------------------- PTX helpers ------------------------------------
__device__ __forceinline__ uint32_t cvta_smem(const void* p) {
    uint32_t a;
    asm("{ .reg .u64 t; cvta.to.shared.u64 t, %1; cvt.u32.u64 %0, t; }" : "=r"(a) : "l"(p));
    return a;
}
__device__ __forceinline__ void cp16(uint32_t dst, const void* src) {
    asm volatile("cp.async.cg.shared.global [%0], [%1], 16;" :: "r"(dst), "l"(src) : "memory");
}
__device__ __forceinline__ void cp_commit() {
    asm volatile("cp.async.commit_group;" ::: "memory");
}
template<int N>
__device__ __forceinline__ void cp_wait() {
    asm volatile("cp.async.wait_group %0;" :: "n"(N) : "memory");
}
__device__ __forceinline__ void ldsm4(uint32_t* r, uint32_t addr) {
    asm volatile("ldmatrix.sync.aligned.m8n8.x4.shared.b16 {%0,%1,%2,%3}, [%4];"
                 : "=r"(r[0]), "=r"(r[1]), "=r"(r[2]), "=r"(r[3]) : "r"(addr));
}
__device__ __forceinline__ void mma_bf16(float* d, const uint32_t* a, const uint32_t* b) {
    asm volatile(
        "mma.sync.aligned.m16n8k16.row.col.f32.bf16.bf16.f32 "
        "{%0,%1,%2,%3}, {%4,%5,%6,%7}, {%8,%9}, {%0,%1,%2,%3};"
        : "+f"(d[0]), "+f"(d[1]), "+f"(d[2]), "+f"(d[3])
        : "r"(a[0]), "r"(a[1]), "r"(a[2]), "r"(a[3]), "r"(b[0]), "r"(b[1]));
}
#define SW128(o) ((o) ^ (((o) >> 3) & 0x70))

// =====================  mma.sync bf16x3 GEMM  ================================
// C[M,N] = fp32( (Ah+Al)[M,K] @ (Bh+Bl)[N,K]^T ), tile 128x128, BK=32.
// Smem rows: 128B = [32 bf16 hi | 32 bf16 lo], SW128 swizzled.
// EPI: 0 store; 1 C = acc + R; 2 C += acc.  WB: also write bf16 hi/lo split.
template<int EPI, bool WB>
__global__ __launch_bounds__(256, 1)
void gemm_bf16x3(const __nv_bfloat16* __restrict__ Ah, const __nv_bfloat16* __restrict__ Al,
                 const __nv_bfloat16* __restrict__ Bh, const __nv_bfloat16* __restrict__ Bl,
                 float* __restrict__ C, const float* __restrict__ R,
                 __nv_bfloat16* __restrict__ Oh, __nv_bfloat16* __restrict__ Ol,
                 int N, int K)
{
    constexpr int STAGES = 4;
    constexpr int STAGE_BYTES = 32 * 1024;           // A 16K + B 16K
    extern __shared__ __align__(1024) char sm_raw[];

    const int tid = threadIdx.x;
    const int wid = tid >> 5;
    const int l   = tid & 31;
    const int wm  = wid >> 1;          // 0..3  (M)
    const int wn  = wid & 1;           // 0..1  (N)
    const int bm  = blockIdx.y * 128;
    const int bn  = blockIdx.x * 128;
    const uint32_t sb = cvta_smem(sm_raw);

    const int KT = K >> 5;             // BK = 32

    // ---- cp.async loader: 1024 chunks of 16B per operand tile ----
    const int ldRow = tid >> 3;        // 0..31 per iter step of 32 rows
    const int ldCh  = tid & 7;         // chunk 0..7 within 128B row
    auto load_tile = [&](int kt, int st) {
        const uint32_t aBase = sb + st * STAGE_BYTES;
        const uint32_t bBase = aBase + 16 * 1024;
        const size_t kof = (size_t)kt * 32 + (size_t)(ldCh & 3) * 8;
        const bool lo = ldCh >= 4;
        #pragma unroll
        for (int i = 0; i < 4; i++) {
            const int r = ldRow + i * 32;
            const uint32_t so = SW128((uint32_t)(r * 128 + ldCh * 16));
            const size_t ga = (size_t)(bm + r) * K + kof;
            const size_t gb = (size_t)(bn + r) * K + kof;
            cp16(aBase + so, (lo ? Al : Ah) + ga);
            cp16(bBase + so, (lo ? Bl : Bh) + gb);
        }
        cp_commit();
    };

    // ---- ldmatrix lane addressing (precomputed, swizzle-aware) ----
    // A frag (mf in 0..1): rows wm*32 + mf*16 + ((l>>3)&1)*8 + (l&7)
    int aRow[2], aXr[2];
    #pragma unroll
    for (int mf = 0; mf < 2; mf++) {
        aRow[mf] = wm * 32 + mf * 16 + ((l >> 3) & 1) * 8 + (l & 7);
        aXr[mf]  = (aRow[mf] & 7) << 4;
    }
    const int aChunk = ((l >> 4) & 1) * 16;
    // B frag pairs (p in 0..3 covering nf=2p,2p+1): rows wn*64 + p*16 + ((l>>4)&1)*8 + (l&7)
    int bRow[4], bXr[4];
    #pragma unroll
    for (int p = 0; p < 4; p++) {
        bRow[p] = wn * 64 + p * 16 + ((l >> 4) & 1) * 8 + (l & 7);
        bXr[p]  = (bRow[p] & 7) << 4;
    }
    const int bChunk = ((l >> 3) & 1) * 16;

    float acc[2][8][4];
    #pragma unroll
    for (int mf = 0; mf < 2; mf++)
        #pragma unroll
        for (int nf = 0; nf < 8; nf++)
            #pragma unroll
            for (int k = 0; k < 4; k++) acc[mf][nf][k] = 0.f;

    // prologue: stages 0..2
    load_tile(0, 0);
    load_tile(1, 1);
    load_tile(2, 2);

    for (int kt = 0; kt < KT; kt++) {
        // prefetch stage kt+3, then wait for stage kt
        if (kt + 3 < KT) { load_tile(kt + 3, (kt + 3) & 3); cp_wait<3>(); }
        else {
            const int rem = KT - 1 - kt;
            if (rem == 2) cp_wait<2>();
            else if (rem == 1) cp_wait<1>();
            else cp_wait<0>();
        }
        __syncthreads();

        const uint32_t aBase = sb + (kt & 3) * STAGE_BYTES;
        const uint32_t bBase = aBase + 16 * 1024;

        #pragma unroll
        for (int s = 0; s < 2; s++) {
            uint32_t aH[2][4], aL[2][4];
            #pragma unroll
            for (int mf = 0; mf < 2; mf++) {
                ldsm4(aH[mf], aBase + aRow[mf] * 128 + (uint32_t)(((0 << 6) | (s << 5) | aChunk) ^ aXr[mf]));
                ldsm4(aL[mf], aBase + aRow[mf] * 128 + (uint32_t)(((1 << 6) | (s << 5) | aChunk) ^ aXr[mf]));
            }
            uint32_t bH[8][2], bL[8][2];
            #pragma unroll
            for (int p = 0; p < 4; p++) {
                uint32_t r4[4];
                ldsm4(r4, bBase + bRow[p] * 128 + (uint32_t)(((0 << 6) | (s << 5) | bChunk) ^ bXr[p]));
                bH[2 * p][0] = r4[0]; bH[2 * p][1] = r4[1];
                bH[2 * p + 1][0] = r4[2]; bH[2 * p + 1][1] = r4[3];
                ldsm4(r4, bBase + bRow[p] * 128 + (uint32_t)(((1 << 6) | (s << 5) | bChunk) ^ bXr[p]));
                bL[2 * p][0] = r4[0]; bL[2 * p][1] = r4[1];
                bL[2 * p + 1][0] = r4[2]; bL[2 * p + 1][1] = r4[3];
            }
            #pragma unroll
            for (int mf = 0; mf < 2; mf++)
                #pragma unroll
                for (int nf = 0; nf < 8; nf++) {
                    mma_bf16(acc[mf][nf], aH[mf], bH[nf]);
                    mma_bf16(acc[mf][nf], aH[mf], bL[nf]);
                    mma_bf16(acc[mf][nf], aL[mf], bH[nf]);
                }
        }
        __syncthreads();
    }

    // ---- epilogue (register fragments -> global) ----
    const int g   = l >> 2;
    const int tig = l & 3;
    #pragma unroll
    for (int mf = 0; mf < 2; mf++) {
        #pragma unroll
        for (int half = 0; half < 2; half++) {
            const int row = bm + wm * 32 + mf * 16 + g + half * 8;
            #pragma unroll
            for (int nf = 0; nf < 8; nf++) {
                const int col = bn + wn * 64 + nf * 8 + tig * 2;
                float vx = acc[mf][nf][2 * half + 0];
                float vy = acc[mf][nf][2 * half + 1];
                const size_t o = (size_t)row * N + col;
                if constexpr (EPI == 1) {
                    float2 rv = *reinterpret_cast<const float2*>(R + o);
                    vx += rv.x; vy += rv.y;
                } else if constexpr (EPI == 2) {
                    float2 cv = *reinterpret_cast<const float2*>(C + o);
                    vx += cv.x; vy += cv.y;
                }
                *reinterpret_cast<float2*>(C + o) = make_float2(vx, vy);
                if constexpr (WB) {
                    __nv_bfloat162 hv = __float22bfloat162_rn(make_float2(vx, vy));
                    float2 hf = __bfloat1622float2(hv);
                    __nv_bfloat162 lv = __float22bfloat162_rn(make_float2(vx - hf.x, vy - hf.y));
                    *reinterpret_cast<__nv_bfloat162*>(Oh + o) = hv;
                    *reinterpret_cast<__nv_bfloat162*>(Ol + o) = lv;
                }
            }
        }
    }
}

// =====================  fp32 SGEMM (dt path only) ===========================
template<bool TB, int EPI>
__global__ __launch_bounds__(256)
void sgemm_kernel(const float* __restrict__ A, const float* __restrict__ Bm,
                  float* __restrict__ C, const float* __restrict__ R,
                  const float* __restrict__ v1, const float* __restrict__ v2,
                  int M, int N, int K)
{
    constexpr int BK = 8;
    __shared__ float As[BK][128];
    __shared__ float Bs[BK][128];
    const int tid = threadIdx.x;
    const int bn  = blockIdx.x * 128;
    const int bm  = blockIdx.y * 128;
    const int tx  = tid & 15;
    const int ty  = tid >> 4;
    const int lRow = tid >> 1;
    const int lCol = (tid & 1) << 2;

    float acc[8][8];
    #pragma unroll
    for (int i = 0; i < 8; i++)
        #pragma unroll
        for (int j = 0; j < 8; j++) acc[i][j] = 0.f;

    for (int k0 = 0; k0 < K; k0 += BK) {
        float4 av = *reinterpret_cast<const float4*>(&A[(size_t)(bm + lRow) * K + k0 + lCol]);
        As[lCol + 0][lRow] = av.x; As[lCol + 1][lRow] = av.y;
        As[lCol + 2][lRow] = av.z; As[lCol + 3][lRow] = av.w;
        float4 bv = *reinterpret_cast<const float4*>(&Bm[(size_t)(bn + lRow) * K + k0 + lCol]);
        Bs[lCol + 0][lRow] = bv.x; Bs[lCol + 1][lRow] = bv.y;
        Bs[lCol + 2][lRow] = bv.z; Bs[lCol + 3][lRow] = bv.w;
        __syncthreads();
        #pragma unroll
        for (int kk = 0; kk < BK; kk++) {
            float ar[8], br[8];
            #pragma unroll
            for (int i = 0; i < 8; i++) ar[i] = As[kk][ty * 8 + i];
            #pragma unroll
            for (int j = 0; j < 8; j++) br[j] = Bs[kk][tx * 8 + j];
            #pragma unroll
            for (int i = 0; i < 8; i++)
                #pragma unroll
                for (int j = 0; j < 8; j++)
                    acc[i][j] = fmaf(ar[i], br[j], acc[i][j]);
        }
        __syncthreads();
    }

    #pragma unroll
    for (int i = 0; i < 8; i++) {
        const int row = bm + ty * 8 + i;
        #pragma unroll
        for (int j0 = 0; j0 < 8; j0 += 4) {
            const int col = bn + tx * 8 + j0;
            float v[4];
            #pragma unroll
            for (int j = 0; j < 4; j++) v[j] = acc[i][j0 + j];
            if constexpr (EPI == 3) {
                #pragma unroll
                for (int j = 0; j < 4; j++) {
                    float t  = v[j] + v1[col + j];
                    float sp = (t > 20.f) ? t : log1pf(expf(t));
                    v[j] = expf(-expf(v2[col + j]) * sp);
                }
            }
            *reinterpret_cast<float4*>(&C[(size_t)row * N + col]) =
                make_float4(v[0], v[1], v[2], v[3]);
        }
    }
}

// -------------------- fp32 -> bf16 hi/lo split (vectorized) -----------------
__global__ void split_f32_kernel(const float* __restrict__ src,
                                 __nv_bfloat16* __restrict__ hi,
                                 __nv_bfloat16* __restrict__ lo, int n4)
{
    int i = blockIdx.x * blockDim.x + threadIdx.x;
    if (i >= n4) return;
    float4 v = reinterpret_cast<const float4*>(src)[i];
    __nv_bfloat162 h0 = __float22bfloat162_rn(make_float2(v.x, v.y));
    __nv_bfloat162 h1 = __float22bfloat162_rn(make_float2(v.z, v.w));
    float2 f0 = __bfloat1622float2(h0);
    float2 f1 = __bfloat1622float2(h1);
    __nv_bfloat162 l0 = __float22bfloat162_rn(make_float2(v.x - f0.x, v.y - f0.y));
    __nv_bfloat162 l1 = __float22bfloat162_rn(make_float2(v.z - f1.x, v.w - f1.y));
    reinterpret_cast<__nv_bfloat162*>(hi)[2 * i]     = h0;
    reinterpret_cast<__nv_bfloat162*>(hi)[2 * i + 1] = h1;
    reinterpret_cast<__nv_bfloat162*>(lo)[2 * i]     = l0;
    reinterpret_cast<__nv_bfloat162*>(lo)[2 * i + 1] = l1;
}

// -------------------- transpose(A_real) + split ----------------------------
__global__ void transpose_split_kernel(const float* __restrict__ src,
                                       __nv_bfloat16* __restrict__ hi,
                                       __nv_bfloat16* __restrict__ lo)
{
    __shared__ float t[32][33];
    int x = blockIdx.x * 32 + threadIdx.x;
    int y = blockIdx.y * 32 + threadIdx.y;
    #pragma unroll
    for (int j = 0; j < 32; j += 8)
        t[threadIdx.y + j][threadIdx.x] = src[(size_t)(y + j) * DI + x];
    __syncthreads();
    int ox = blockIdx.y * 32 + threadIdx.x;
    int oy = blockIdx.x * 32 + threadIdx.y;
    #pragma unroll
    for (int j = 0; j < 32; j += 8) {
        float v = t[threadIdx.x][threadIdx.y + j];
        size_t o = (size_t)(oy + j) * DI + ox;
        split1(v, hi[o], lo[o]);
    }
}

// -------------------- conv + bias + SiLU (+ split of x) ---------------------
__global__ void conv_silu_kernel(const float* __restrict__ w, const float* __restrict__ bias)
{
    int i = blockIdx.x * blockDim.x + threadIdx.x;
    if (i >= M_ * DI) return;
    int c  = i % DI;
    int l  = (i / DI) % L_;
    int bb = i / (DI * L_);
    const float* base = g_xz + (size_t)bb * L_ * TWO_DI + c;
    float acc = bias[c];
    #pragma unroll
    for (int k = 0; k < 4; k++) {
        int ll = l - 3 + k;
        if (ll >= 0) acc = fmaf(w[c * 4 + k], base[(size_t)ll * TWO_DI], acc);
    }
    float v = siluf(acc);
    g_x[i] = v;
    split1(v, g_x_hi[i], g_x_lo[i]);
}

// ------------------------------ cumsum over L -------------------------------
__global__ void cumsum_p1()
{
    int c   = blockIdx.x * blockDim.x + threadIdx.x;
    int seq = blockIdx.y;
    int bb = seq / NCH, ch = seq % NCH;
    size_t base = ((size_t)(bb * L_ + ch * CH)) * DI + c;
    float s = 0.f;
    for (int i = 0; i < CH; i++) s += g_bx[base + (size_t)i * DI];
    g_p1[seq * DI + c] = s;
}
__global__ void cumsum_p2()
{
    int i = blockIdx.x * blockDim.x + threadIdx.x;
    if (i >= B_ * DI) return;
    int bb = i / DI, c = i % DI;
    float carry = 0.f;
    for (int ch = 0; ch < NCH; ch++) {
        int idx = (bb * NCH + ch) * DI + c;
        g_cr[idx] = carry;
        carry += g_p1[idx];
    }
}
__global__ void cumsum_p3()   // states fp32 in-place + bf16 split
{
    int c   = blockIdx.x * blockDim.x + threadIdx.x;
    int seq = blockIdx.y;
    int bb = seq / NCH, ch = seq % NCH;
    size_t base = ((size_t)(bb * L_ + ch * CH)) * DI + c;
    float carry = g_cr[seq * DI + c];
    for (int i = 0; i < CH; i++) {
        size_t idx = base + (size_t)i * DI;
        carry += g_bx[idx];
        g_bx[idx] = carry;
        split1(carry, g_st_hi[idx], g_st_lo[idx]);
    }
}

// ----------------------- decay recurrence scan ------------------------------
__global__ void scan_p1()
{
    int c   = blockIdx.x * blockDim.x + threadIdx.x;
    int seq = blockIdx.y;
    int bb = seq / NCH, ch = seq % NCH;
    size_t base = ((size_t)(bb * L_ + ch * CH)) * DI + c;
    float P = 1.f, S = 0.f;
    for (int i = 0; i < CH; i++) {
        size_t idx = base + (size_t)i * DI;
        float d = g_dc[idx];
        S = fmaf(d, S, g_u[idx]);
        P *= d;
    }
    g_p2[seq * DI + c] = P;
    g_p3[seq * DI + c] = S;
}
__global__ void scan_p2()
{
    int i = blockIdx.x * blockDim.x + threadIdx.x;
    if (i >= B_ * DI) return;
    int bb = i / DI, c = i % DI;
    float carry = 0.f;
    for (int ch = 0; ch < NCH; ch++) {
        int idx = (bb * NCH + ch) * DI + c;
        g_cr[idx] = carry;
        carry = fmaf(g_p2[idx], carry, g_p3[idx]);
    }
}
__global__ void scan_p3(const float* __restrict__ D_ss)  // out_pre -> bf16 split
{
    int c   = blockIdx.x * blockDim.x + threadIdx.x;
    int seq = blockIdx.y;
    int bb = seq / NCH, ch = seq % NCH;
    int l0 = ch * CH;
    size_t base = ((size_t)(bb * L_ + l0)) * DI + c;
    float state = g_cr[seq * DI + c];
    float dss = D_ss[c];
    for (int i = 0; i < CH; i++) {
        size_t idx = base + (size_t)i * DI;
        float u = g_u[idx];
        state = fmaf(g_dc[idx], state, u);
        float z = g_xz[(size_t)(bb * L_ + l0 + i) * TWO_DI + DI + c];
        float v = (state + u * dss) * siluf(z);
        split1(v, g_op_hi[idx], g_op_lo[idx]);
    }
}

// ------------------------------- launcher ----------------------------------
extern "C" void kernel_launch(void* const* d_in, const int* in_sizes, int n_in,
                              void* d_out, int out_size)
{
    const float* h         = (const float*)d_in[0];
    const float* delta     = (const float*)d_in[1];
    const float* in_proj_w = (const float*)d_in[2];
    const float* conv_w    = (const float*)d_in[3];
    const float* conv_b    = (const float*)d_in[4];
    const float* A_real    = (const float*)d_in[5];
    const float* B_w       = (const float*)d_in[6];
    const float* C_w       = (const float*)d_in[7];
    const float* D_w       = (const float*)d_in[8];
    const float* dt_proj_w = (const float*)d_in[9];
    const float* dt_proj_b = (const float*)d_in[10];
    const float* A_log     = (const float*)d_in[11];
    const float* D_ss      = (const float*)d_in[12];
    const float* out_proj_w= (const float*)d_in[13];
    float* out = (float*)d_out;

    float *xz, *x, *x2, *bx, *u, *dc;
    cudaGetSymbolAddress((void**)&xz, g_xz);
    cudaGetSymbolAddress((void**)&x,  g_x);
    cudaGetSymbolAddress((void**)&x2, g_x2);
    cudaGetSymbolAddress((void**)&bx, g_bx);
    cudaGetSymbolAddress((void**)&u,  g_u);
    cudaGetSymbolAddress((void**)&dc, g_dc);
    __nv_bfloat16 *hH,*hL,*xH,*xL,*x2H,*x2L,*stH,*stL,*opH,*opL;
    __nv_bfloat16 *w1H,*w1L,*atH,*atL,*bwH,*bwL,*cwH,*cwL,*dwH,*dwL,*woH,*woL;
    cudaGetSymbolAddress((void**)&hH,  g_h_hi);  cudaGetSymbolAddress((void**)&hL,  g_h_lo);
    cudaGetSymbolAddress((void**)&xH,  g_x_hi);  cudaGetSymbolAddress((void**)&xL,  g_x_lo);
    cudaGetSymbolAddress((void**)&x2H, g_x2_hi); cudaGetSymbolAddress((void**)&x2L, g_x2_lo);
    cudaGetSymbolAddress((void**)&stH, g_st_hi); cudaGetSymbolAddress((void**)&stL, g_st_lo);
    cudaGetSymbolAddress((void**)&opH, g_op_hi); cudaGetSymbolAddress((void**)&opL, g_op_lo);
    cudaGetSymbolAddress((void**)&w1H, g_w1_hi); cudaGetSymbolAddress((void**)&w1L, g_w1_lo);
    cudaGetSymbolAddress((void**)&atH, g_at_hi); cudaGetSymbolAddress((void**)&atL, g_at_lo);
    cudaGetSymbolAddress((void**)&bwH, g_bw_hi); cudaGetSymbolAddress((void**)&bwL, g_bw_lo);
    cudaGetSymbolAddress((void**)&cwH, g_cw_hi); cudaGetSymbolAddress((void**)&cwL, g_cw_lo);
    cudaGetSymbolAddress((void**)&dwH, g_dw_hi); cudaGetSymbolAddress((void**)&dwL, g_dw_lo);
    cudaGetSymbolAddress((void**)&woH, g_wo_hi); cudaGetSymbolAddress((void**)&woL, g_wo_lo);

    constexpr int SMEM = 128 * 1024;
    cudaFuncSetAttribute(gemm_bf16x3<0, false>, cudaFuncAttributeMaxDynamicSharedMemorySize, SMEM);
    cudaFuncSetAttribute(gemm_bf16x3<1, true>,  cudaFuncAttributeMaxDynamicSharedMemorySize, SMEM);
    cudaFuncSetAttribute(gemm_bf16x3<1, false>, cudaFuncAttributeMaxDynamicSharedMemorySize, SMEM);
    cudaFuncSetAttribute(gemm_bf16x3<2, false>, cudaFuncAttributeMaxDynamicSharedMemorySize, SMEM);

    auto split = [&](const float* s, __nv_bfloat16* hi_, __nv_bfloat16* lo_, size_t n) {
        int n4 = (int)(n / 4);
        split_f32_kernel<<<(n4 + 255) / 256, 256>>>(s, hi_, lo_, n4);
    };
    split(h,          hH,  hL,  (size_t)M_ * DM);
    split(in_proj_w,  w1H, w1L, (size_t)TWO_DI * DM);
    split(B_w,        bwH, bwL, (size_t)DI * DI);
    split(C_w,        cwH, cwL, (size_t)DI * DI);
    split(D_w,        dwH, dwL, (size_t)DI * DI);
    split(out_proj_w, woH, woL, (size_t)DM * DI);
    transpose_split_kernel<<<dim3(DI / 32, DI / 32), dim3(32, 8)>>>(A_real, atH, atL);

    const int GY = M_ / 128;   // 64

    // 1) xz = h @ in_proj_w^T     [8192, 4096]
    gemm_bf16x3<0, false><<<dim3(TWO_DI / 128, GY), 256, SMEM>>>(
        hH, hL, w1H, w1L, xz, nullptr, nullptr, nullptr, TWO_DI, DM);

    // 2) conv + SiLU -> g_x (+ split)
    conv_silu_kernel<<<(M_ * DI) / 256, 256>>>(conv_w, conv_b);

    // 3) x2 = x + x @ A_real      (B = A_real^T, split)
    gemm_bf16x3<1, true><<<dim3(DI / 128, GY), 256, SMEM>>>(
        xH, xL, atH, atL, x2, x, x2H, x2L, DI, DI);

    // 4) Bx = x2 @ B_w^T
    gemm_bf16x3<0, false><<<dim3(DI / 128, GY), 256, SMEM>>>(
        x2H, x2L, bwH, bwL, bx, nullptr, nullptr, nullptr, DI, DI);

    // 5) states = cumsum_L(Bx)
    dim3 gSeq(DI / 256, B_ * NCH);
    cumsum_p1<<<gSeq, 256>>>();
    cumsum_p2<<<(B_ * DI) / 256, 256>>>();
    cumsum_p3<<<gSeq, 256>>>();

    // 6) u = x2 + states @ C_w^T
    gemm_bf16x3<1, false><<<dim3(DI / 128, GY), 256, SMEM>>>(
        stH, stL, cwH, cwL, u, x2, nullptr, nullptr, DI, DI);

    // 7) u += x2 @ D_w^T
    gemm_bf16x3<2, false><<<dim3(DI / 128, GY), 256, SMEM>>>(
        x2H, x2L, dwH, dwL, u, nullptr, nullptr, nullptr, DI, DI);

    // 8) decay (fp32, K=64)
    sgemm_kernel<true, 3><<<dim3(DI / 128, M_ / 128), 256>>>(
        delta, dt_proj_w, dc, nullptr, dt_proj_b, A_log, M_, DI, 64);

    // 9) scan; pass3 fuses (+ u*D_ss) * silu(z) -> out_pre split
    scan_p1<<<gSeq, 256>>>();
    scan_p2<<<(B_ * DI) / 256, 256>>>();
    scan_p3<<<gSeq, 256>>>(D_ss);

    // 10) out = out_pre @ out_proj_w^T  [8192, 1024]
    gemm_bf16x3<0, false><<<dim3(DM / 128, GY), 256, SMEM>>>(
        opH, opL, woH, woL, out, nullptr, nullptr, nullptr, DM, DI);
}

// round 4
// speedup vs baseline: 3.2224x; 1.1693x over previous
#include <cuda_runtime.h>
#include <cuda_bf16.h>
#include <math.h>
#include <stdint.h>

// ---------------------------------------------------------------------------
// Mamba3Block on GB300 — round 4: mma.sync bf16x3, 3-stage/2-CTA pipeline,
// merged C|D GEMM, dt on tensor path, split-residuals (no fp32 x/x2).
// ---------------------------------------------------------------------------

namespace {
constexpr int B_   = 2;
constexpr int L_   = 4096;
constexpr int DM   = 1024;
constexpr int DI   = 2048;
constexpr int M_   = B_ * L_;        // 8192
constexpr int NCH  = 32;
constexpr int CH   = L_ / NCH;       // 128
constexpr int TWO_DI = 2 * DI;       // 4096
constexpr int DTR  = 64;
}

// ------------------------- fp32 scratch ------------------------------------
__device__ float g_xz[(size_t)M_ * TWO_DI];
__device__ float g_bx[(size_t)M_ * DI];
__device__ float g_u [(size_t)M_ * DI];
__device__ float g_dc[(size_t)M_ * DI];
__device__ float g_p1[B_ * NCH * DI];
__device__ float g_p2[B_ * NCH * DI];
__device__ float g_p3[B_ * NCH * DI];
__device__ float g_cr[B_ * NCH * DI];

// ------------------------- bf16 split scratch ------------------------------
__device__ __nv_bfloat16 g_h_hi [(size_t)M_ * DM],   g_h_lo [(size_t)M_ * DM];
__device__ __nv_bfloat16 g_x_hi [(size_t)M_ * DI],   g_x_lo [(size_t)M_ * DI];
__device__ __nv_bfloat16 g_cat_hi[(size_t)M_ * TWO_DI], g_cat_lo[(size_t)M_ * TWO_DI]; // [states|x2]
__device__ __nv_bfloat16 g_op_hi[(size_t)M_ * DI],   g_op_lo[(size_t)M_ * DI];
__device__ __nv_bfloat16 g_dl_hi[(size_t)M_ * DTR],  g_dl_lo[(size_t)M_ * DTR];
__device__ __nv_bfloat16 g_w1_hi[(size_t)TWO_DI * DM], g_w1_lo[(size_t)TWO_DI * DM];
__device__ __nv_bfloat16 g_at_hi[(size_t)DI * DI],   g_at_lo[(size_t)DI * DI];
__device__ __nv_bfloat16 g_bw_hi[(size_t)DI * DI],   g_bw_lo[(size_t)DI * DI];
__device__ __nv_bfloat16 g_wc_hi[(size_t)DI * TWO_DI], g_wc_lo[(size_t)DI * TWO_DI];  // [C_w|D_w]
__device__ __nv_bfloat16 g_wo_hi[(size_t)DM * DI],   g_wo_lo[(size_t)DM * DI];
__device__ __nv_bfloat16 g_dt_hi[(size_t)DI * DTR],  g_dt_lo[(size_t)DI * DTR];

__device__ __forceinline__ float siluf(float v) { return v / (1.f + expf(-v)); }

__device__ __forceinline__ void split1(float v, __nv_bfloat16& h, __nv_bfloat16& l) {
    h = __float2bfloat16(v);
    l = __float2bfloat16(v - __bfloat162float(h));
}

// --------------------------- PTX helpers ------------------------------------
__device__ __forceinline__ uint32_t cvta_smem(const void* p) {
    uint32_t a;
    asm("{ .reg .u64 t; cvta.to.shared.u64 t, %1; cvt.u32.u64 %0, t; }" : "=r"(a) : "l"(p));
    return a;
}
__device__ __forceinline__ void cp16(uint32_t dst, const void* src) {
    asm volatile("cp.async.cg.shared.global [%0], [%1], 16;" :: "r"(dst), "l"(src) : "memory");
}
__device__ __forceinline__ void cp_commit() {
    asm volatile("cp.async.commit_group;" ::: "memory");
}
template<int N>
__device__ __forceinline__ void cp_wait() {
    asm volatile("cp.async.wait_group %0;" :: "n"(N) : "memory");
}
__device__ __forceinline__ void ldsm4(uint32_t* r, uint32_t addr) {
    asm volatile("ldmatrix.sync.aligned.m8n8.x4.shared.b16 {%0,%1,%2,%3}, [%4];"
                 : "=r"(r[0]), "=r"(r[1]), "=r"(r[2]), "=r"(r[3]) : "r"(addr));
}
__device__ __forceinline__ void mma_bf16(float* d, const uint32_t* a, uint32_t b0, uint32_t b1) {
    asm volatile(
        "mma.sync.aligned.m16n8k16.row.col.f32.bf16.bf16.f32 "
        "{%0,%1,%2,%3}, {%4,%5,%6,%7}, {%8,%9}, {%0,%1,%2,%3};"
        : "+f"(d[0]), "+f"(d[1]), "+f"(d[2]), "+f"(d[3])
        : "r"(a[0]), "r"(a[1]), "r"(a[2]), "r"(a[3]), "r"(b0), "r"(b1));
}
#define SW128(o) ((o) ^ (((o) >> 3) & 0x70))

// =====================  mma.sync bf16x3 GEMM  ================================
// C[M,N] = fp32( (Ah+Al)[M,K] @ (Bh+Bl)[N,K]^T ), tile 128x128, BK=32, 3 stages.
// A rows read at (row*lda + abase + k). Smem rows: 128B = [32 hi | 32 lo], SW128.
// EPI: 0 none; 1 acc += (Rh+Rl) read at row*ldr+rbase+col; 3 decay epilogue.
// WC: write C fp32. WB: write bf16 hi/lo split at row*ldo + obase + col.
template<int EPI, bool WB, bool WC>
__global__ __launch_bounds__(256, 2)
void gemm_bf16x3(const __nv_bfloat16* __restrict__ Ah, const __nv_bfloat16* __restrict__ Al,
                 int lda, int abase,
                 const __nv_bfloat16* __restrict__ Bh, const __nv_bfloat16* __restrict__ Bl,
                 float* __restrict__ C,
                 const __nv_bfloat16* __restrict__ Rh, const __nv_bfloat16* __restrict__ Rl,
                 int ldr, int rbase,
                 __nv_bfloat16* __restrict__ Oh, __nv_bfloat16* __restrict__ Ol,
                 int ldo, int obase,
                 const float* __restrict__ v1, const float* __restrict__ v2,
                 int N, int K)
{
    constexpr int STAGE_BYTES = 32 * 1024;   // A 16K + B 16K
    extern __shared__ __align__(1024) char sm_raw[];

    const int tid = threadIdx.x;
    const int wid = tid >> 5;
    const int l   = tid & 31;
    const int wm  = wid >> 1;          // 0..3  (M)
    const int wn  = wid & 1;           // 0..1  (N)
    const int bm  = blockIdx.y * 128;
    const int bn  = blockIdx.x * 128;
    const uint32_t sb = cvta_smem(sm_raw);

    const int KT = K >> 5;             // BK = 32

    // ---- cp.async loader ----
    const int ldRow = tid >> 3;        // 0..31
    const int ldCh  = tid & 7;         // chunk within 128B row
    auto load_tile = [&](int kt, int st) {
        const uint32_t aBase = sb + st * STAGE_BYTES;
        const uint32_t bBase = aBase + 16 * 1024;
        const int kof = kt * 32 + (ldCh & 3) * 8;
        const bool lo = ldCh >= 4;
        #pragma unroll
        for (int i = 0; i < 4; i++) {
            const int r = ldRow + i * 32;
            const uint32_t so = SW128((uint32_t)(r * 128 + ldCh * 16));
            const size_t ga = (size_t)(bm + r) * lda + abase + kof;
            const size_t gb = (size_t)(bn + r) * K + kof;
            cp16(aBase + so, (lo ? Al : Ah) + ga);
            cp16(bBase + so, (lo ? Bl : Bh) + gb);
        }
        cp_commit();
    };

    // ---- ldmatrix lane addressing ----
    int aRow[2], aXr[2];
    #pragma unroll
    for (int mf = 0; mf < 2; mf++) {
        aRow[mf] = wm * 32 + mf * 16 + ((l >> 3) & 1) * 8 + (l & 7);
        aXr[mf]  = (aRow[mf] & 7) << 4;
    }
    const int aChunk = ((l >> 4) & 1) * 16;
    int bRow[4], bXr[4];
    #pragma unroll
    for (int p = 0; p < 4; p++) {
        bRow[p] = wn * 64 + p * 16 + ((l >> 4) & 1) * 8 + (l & 7);
        bXr[p]  = (bRow[p] & 7) << 4;
    }
    const int bChunk = ((l >> 3) & 1) * 16;

    float acc[2][8][4];
    #pragma unroll
    for (int mf = 0; mf < 2; mf++)
        #pragma unroll
        for (int nf = 0; nf < 8; nf++)
            #pragma unroll
            for (int k = 0; k < 4; k++) acc[mf][nf][k] = 0.f;

    // prologue: 2 stages in flight
    load_tile(0, 0);
    if (KT > 1) load_tile(1, 1);

    for (int kt = 0; kt < KT; kt++) {
        if (kt + 2 < KT) cp_wait<1>();
        else             cp_wait<0>();
        __syncthreads();
        if (kt + 2 < KT) load_tile(kt + 2, (kt + 2) % 3);

        const uint32_t aBase = sb + (uint32_t)(kt % 3) * STAGE_BYTES;
        const uint32_t bBase = aBase + 16 * 1024;

        #pragma unroll
        for (int s = 0; s < 2; s++) {
            uint32_t aH[2][4], aL[2][4];
            #pragma unroll
            for (int mf = 0; mf < 2; mf++) {
                ldsm4(aH[mf], aBase + aRow[mf] * 128 + (uint32_t)(((0 << 6) | (s << 5) | aChunk) ^ aXr[mf]));
                ldsm4(aL[mf], aBase + aRow[mf] * 128 + (uint32_t)(((1 << 6) | (s << 5) | aChunk) ^ aXr[mf]));
            }
            #pragma unroll
            for (int p = 0; p < 4; p++) {
                uint32_t rH[4], rL[4];
                ldsm4(rH, bBase + bRow[p] * 128 + (uint32_t)(((0 << 6) | (s << 5) | bChunk) ^ bXr[p]));
                ldsm4(rL, bBase + bRow[p] * 128 + (uint32_t)(((1 << 6) | (s << 5) | bChunk) ^ bXr[p]));
                #pragma unroll
                for (int mf = 0; mf < 2; mf++) {
                    mma_bf16(acc[mf][2 * p],     aH[mf], rH[0], rH[1]);
                    mma_bf16(acc[mf][2 * p + 1], aH[mf], rH[2], rH[3]);
                    mma_bf16(acc[mf][2 * p],     aH[mf], rL[0], rL[1]);
                    mma_bf16(acc[mf][2 * p + 1], aH[mf], rL[2], rL[3]);
                    mma_bf16(acc[mf][2 * p],     aL[mf], rH[0], rH[1]);
                    mma_bf16(acc[mf][2 * p + 1], aL[mf], rH[2], rH[3]);
                }
            }
        }
    }

    // ---- epilogue ----
    const int g   = l >> 2;
    const int tig = l & 3;
    #pragma unroll
    for (int mf = 0; mf < 2; mf++) {
        #pragma unroll
        for (int half = 0; half < 2; half++) {
            const int row = bm + wm * 32 + mf * 16 + g + half * 8;
            #pragma unroll
            for (int nf = 0; nf < 8; nf++) {
                const int col = bn + wn * 64 + nf * 8 + tig * 2;
                float vx = acc[mf][nf][2 * half + 0];
                float vy = acc[mf][nf][2 * half + 1];
                if constexpr (EPI == 1) {
                    const size_t ro = (size_t)row * ldr + rbase + col;
                    float2 rh = __bfloat1622float2(*reinterpret_cast<const __nv_bfloat162*>(Rh + ro));
                    float2 rl = __bfloat1622float2(*reinterpret_cast<const __nv_bfloat162*>(Rl + ro));
                    vx += rh.x + rl.x; vy += rh.y + rl.y;
                } else if constexpr (EPI == 3) {
                    float tx = vx + v1[col], ty = vy + v1[col + 1];
                    float sx = (tx > 20.f) ? tx : log1pf(expf(tx));
                    float sy = (ty > 20.f) ? ty : log1pf(expf(ty));
                    vx = expf(-expf(v2[col]) * sx);
                    vy = expf(-expf(v2[col + 1]) * sy);
                }
                if constexpr (WC) {
                    *reinterpret_cast<float2*>(C + (size_t)row * N + col) = make_float2(vx, vy);
                }
                if constexpr (WB) {
                    const size_t o = (size_t)row * ldo + obase + col;
                    __nv_bfloat162 hv = __float22bfloat162_rn(make_float2(vx, vy));
                    float2 hf = __bfloat1622float2(hv);
                    __nv_bfloat162 lv = __float22bfloat162_rn(make_float2(vx - hf.x, vy - hf.y));
                    *reinterpret_cast<__nv_bfloat162*>(Oh + o) = hv;
                    *reinterpret_cast<__nv_bfloat162*>(Ol + o) = lv;
                }
            }
        }
    }
}

// -------------------- fp32 -> bf16 hi/lo strided split ----------------------
__global__ void split_strided_kernel(const float* __restrict__ src,
                                     __nv_bfloat16* __restrict__ hi,
                                     __nv_bfloat16* __restrict__ lo,
                                     int rowlen, int ld, int colofs, int n4)
{
    int i = blockIdx.x * blockDim.x + threadIdx.x;
    if (i >= n4) return;
    float4 v = reinterpret_cast<const float4*>(src)[i];
    int e = i * 4;
    int row = e / rowlen;
    int col = e - row * rowlen;
    size_t o = (size_t)row * ld + colofs + col;
    __nv_bfloat162 h0 = __float22bfloat162_rn(make_float2(v.x, v.y));
    __nv_bfloat162 h1 = __float22bfloat162_rn(make_float2(v.z, v.w));
    float2 f0 = __bfloat1622float2(h0);
    float2 f1 = __bfloat1622float2(h1);
    __nv_bfloat162 l0 = __float22bfloat162_rn(make_float2(v.x - f0.x, v.y - f0.y));
    __nv_bfloat162 l1 = __float22bfloat162_rn(make_float2(v.z - f1.x, v.w - f1.y));
    *reinterpret_cast<__nv_bfloat162*>(hi + o)     = h0;
    *reinterpret_cast<__nv_bfloat162*>(hi + o + 2) = h1;
    *reinterpret_cast<__nv_bfloat162*>(lo + o)     = l0;
    *reinterpret_cast<__nv_bfloat162*>(lo + o + 2) = l1;
}

// -------------------- transpose(A_real) + split ----------------------------
__global__ void transpose_split_kernel(const float* __restrict__ src,
                                       __nv_bfloat16* __restrict__ hi,
                                       __nv_bfloat16* __restrict__ lo)
{
    __shared__ float t[32][33];
    int x = blockIdx.x * 32 + threadIdx.x;
    int y = blockIdx.y * 32 + threadIdx.y;
    #pragma unroll
    for (int j = 0; j < 32; j += 8)
        t[threadIdx.y + j][threadIdx.x] = src[(size_t)(y + j) * DI + x];
    __syncthreads();
    int ox = blockIdx.y * 32 + threadIdx.x;
    int oy = blockIdx.x * 32 + threadIdx.y;
    #pragma unroll
    for (int j = 0; j < 32; j += 8) {
        float v = t[threadIdx.x][threadIdx.y + j];
        size_t o = (size_t)(oy + j) * DI + ox;
        split1(v, hi[o], lo[o]);
    }
}

// -------------------- conv + bias + SiLU -> x splits ------------------------
__global__ void conv_silu_kernel(const float* __restrict__ w, const float* __restrict__ bias)
{
    int i = blockIdx.x * blockDim.x + threadIdx.x;
    if (i >= M_ * DI) return;
    int c  = i % DI;
    int l  = (i / DI) % L_;
    int bb = i / (DI * L_);
    const float* base = g_xz + (size_t)bb * L_ * TWO_DI + c;
    float acc = bias[c];
    #pragma unroll
    for (int k = 0; k < 4; k++) {
        int ll = l - 3 + k;
        if (ll >= 0) acc = fmaf(w[c * 4 + k], base[(size_t)ll * TWO_DI], acc);
    }
    float v = siluf(acc);
    split1(v, g_x_hi[i], g_x_lo[i]);
}

// ------------------------------ cumsum over L -------------------------------
__global__ void cumsum_p1()
{
    int c   = blockIdx.x * blockDim.x + threadIdx.x;
    int seq = blockIdx.y;
    int bb = seq / NCH, ch = seq % NCH;
    size_t base = ((size_t)(bb * L_ + ch * CH)) * DI + c;
    float s = 0.f;
    for (int i = 0; i < CH; i++) s += g_bx[base + (size_t)i * DI];
    g_p1[seq * DI + c] = s;
}
__global__ void cumsum_p2()
{
    int i = blockIdx.x * blockDim.x + threadIdx.x;
    if (i >= B_ * DI) return;
    int bb = i / DI, c = i % DI;
    float carry = 0.f;
    for (int ch = 0; ch < NCH; ch++) {
        int idx = (bb * NCH + ch) * DI + c;
        g_cr[idx] = carry;
        carry += g_p1[idx];
    }
}
__global__ void cumsum_p3()   // states -> cat splits cols [0, DI)
{
    int c   = blockIdx.x * blockDim.x + threadIdx.x;
    int seq = blockIdx.y;
    int bb = seq / NCH, ch = seq % NCH;
    int gl0 = bb * L_ + ch * CH;
    float carry = g_cr[seq * DI + c];
    for (int i = 0; i < CH; i++) {
        size_t idx = (size_t)(gl0 + i) * DI + c;
        carry += g_bx[idx];
        size_t co = (size_t)(gl0 + i) * TWO_DI + c;
        split1(carry, g_cat_hi[co], g_cat_lo[co]);
    }
}

// ----------------------- decay recurrence scan ------------------------------
__global__ void scan_p1()
{
    int c   = blockIdx.x * blockDim.x + threadIdx.x;
    int seq = blockIdx.y;
    int bb = seq / NCH, ch = seq % NCH;
    size_t base = ((size_t)(bb * L_ + ch * CH)) * DI + c;
    float P = 1.f, S = 0.f;
    for (int i = 0; i < CH; i++) {
        size_t idx = base + (size_t)i * DI;
        float d = g_dc[idx];
        S = fmaf(d, S, g_u[idx]);
        P *= d;
    }
    g_p2[seq * DI + c] = P;
    g_p3[seq * DI + c] = S;
}
__global__ void scan_p2()
{
    int i = blockIdx.x * blockDim.x + threadIdx.x;
    if (i >= B_ * DI) return;
    int bb = i / DI, c = i % DI;
    float carry = 0.f;
    for (int ch = 0; ch < NCH; ch++) {
        int idx = (bb * NCH + ch) * DI + c;
        g_cr[idx] = carry;
        carry = fmaf(g_p2[idx], carry, g_p3[idx]);
    }
}
__global__ void scan_p3(const float* __restrict__ D_ss)  // out_pre -> op splits
{
    int c   = blockIdx.x * blockDim.x + threadIdx.x;
    int seq = blockIdx.y;
    int bb = seq / NCH, ch = seq % NCH;
    int l0 = ch * CH;
    size_t base = ((size_t)(bb * L_ + l0)) * DI + c;
    float state = g_cr[seq * DI + c];
    float dss = D_ss[c];
    for (int i = 0; i < CH; i++) {
        size_t idx = base + (size_t)i * DI;
        float u = g_u[idx];
        state = fmaf(g_dc[idx], state, u);
        float z = g_xz[(size_t)(bb * L_ + l0 + i) * TWO_DI + DI + c];
        float v = (state + u * dss) * siluf(z);
        split1(v, g_op_hi[idx], g_op_lo[idx]);
    }
}

// ------------------------------- launcher ----------------------------------
extern "C" void kernel_launch(void* const* d_in, const int* in_sizes, int n_in,
                              void* d_out, int out_size)
{
    const float* h         = (const float*)d_in[0];
    const float* delta     = (const float*)d_in[1];
    const float* in_proj_w = (const float*)d_in[2];
    const float* conv_w    = (const float*)d_in[3];
    const float* conv_b    = (const float*)d_in[4];
    const float* A_real    = (const float*)d_in[5];
    const float* B_w       = (const float*)d_in[6];
    const float* C_w       = (const float*)d_in[7];
    const float* D_w       = (const float*)d_in[8];
    const float* dt_proj_w = (const float*)d_in[9];
    const float* dt_proj_b = (const float*)d_in[10];
    const float* A_log     = (const float*)d_in[11];
    const float* D_ss      = (const float*)d_in[12];
    const float* out_proj_w= (const float*)d_in[13];
    float* out = (float*)d_out;

    float *xz, *bx, *u, *dc;
    cudaGetSymbolAddress((void**)&xz, g_xz);
    cudaGetSymbolAddress((void**)&bx, g_bx);
    cudaGetSymbolAddress((void**)&u,  g_u);
    cudaGetSymbolAddress((void**)&dc, g_dc);
    __nv_bfloat16 *hH,*hL,*xH,*xL,*catH,*catL,*opH,*opL,*dlH,*dlL;
    __nv_bfloat16 *w1H,*w1L,*atH,*atL,*bwH,*bwL,*wcH,*wcL,*woH,*woL,*dtH,*dtL;
    cudaGetSymbolAddress((void**)&hH,   g_h_hi);   cudaGetSymbolAddress((void**)&hL,   g_h_lo);
    cudaGetSymbolAddress((void**)&xH,   g_x_hi);   cudaGetSymbolAddress((void**)&xL,   g_x_lo);
    cudaGetSymbolAddress((void**)&catH, g_cat_hi); cudaGetSymbolAddress((void**)&catL, g_cat_lo);
    cudaGetSymbolAddress((void**)&opH,  g_op_hi);  cudaGetSymbolAddress((void**)&opL,  g_op_lo);
    cudaGetSymbolAddress((void**)&dlH,  g_dl_hi);  cudaGetSymbolAddress((void**)&dlL,  g_dl_lo);
    cudaGetSymbolAddress((void**)&w1H,  g_w1_hi);  cudaGetSymbolAddress((void**)&w1L,  g_w1_lo);
    cudaGetSymbolAddress((void**)&atH,  g_at_hi);  cudaGetSymbolAddress((void**)&atL,  g_at_lo);
    cudaGetSymbolAddress((void**)&bwH,  g_bw_hi);  cudaGetSymbolAddress((void**)&bwL,  g_bw_lo);
    cudaGetSymbolAddress((void**)&wcH,  g_wc_hi);  cudaGetSymbolAddress((void**)&wcL,  g_wc_lo);
    cudaGetSymbolAddress((void**)&woH,  g_wo_hi);  cudaGetSymbolAddress((void**)&woL,  g_wo_lo);
    cudaGetSymbolAddress((void**)&dtH,  g_dt_hi);  cudaGetSymbolAddress((void**)&dtL,  g_dt_lo);

    constexpr int SMEM = 96 * 1024;
    cudaFuncSetAttribute(gemm_bf16x3<0, false, true>,  cudaFuncAttributeMaxDynamicSharedMemorySize, SMEM);
    cudaFuncSetAttribute(gemm_bf16x3<1, true,  false>, cudaFuncAttributeMaxDynamicSharedMemorySize, SMEM);
    cudaFuncSetAttribute(gemm_bf16x3<1, false, true>,  cudaFuncAttributeMaxDynamicSharedMemorySize, SMEM);
    cudaFuncSetAttribute(gemm_bf16x3<3, false, true>,  cudaFuncAttributeMaxDynamicSharedMemorySize, SMEM);

    auto split = [&](const float* s, __nv_bfloat16* hi_, __nv_bfloat16* lo_,
                     int rowlen, int ld, int colofs, size_t n) {
        int n4 = (int)(n / 4);
        split_strided_kernel<<<(n4 + 255) / 256, 256>>>(s, hi_, lo_, rowlen, ld, colofs, n4);
    };

    const int GY = M_ / 128;   // 64
    const dim3 gSeq(DI / 256, B_ * NCH);

    // launches 0..4 (so that launch #5 = big GEMM for ncu)
    transpose_split_kernel<<<dim3(DI / 32, DI / 32), dim3(32, 8)>>>(A_real, atH, atL);   // 0
    split(h,         hH,  hL,  DM, DM, 0, (size_t)M_ * DM);                              // 1
    split(in_proj_w, w1H, w1L, DM, DM, 0, (size_t)TWO_DI * DM);                          // 2
    split(delta,     dlH, dlL, DTR, DTR, 0, (size_t)M_ * DTR);                           // 3
    split(dt_proj_w, dtH, dtL, DTR, DTR, 0, (size_t)DI * DTR);                           // 4

    // 5) xz = h @ in_proj_w^T   [8192, 4096]
    gemm_bf16x3<0, false, true><<<dim3(TWO_DI / 128, GY), 256, SMEM>>>(
        hH, hL, DM, 0, w1H, w1L, xz, nullptr, nullptr, 0, 0,
        nullptr, nullptr, 0, 0, nullptr, nullptr, TWO_DI, DM);

    // remaining weight splits
    split(B_w, bwH, bwL, DI, DI, 0, (size_t)DI * DI);
    split(C_w, wcH, wcL, DI, TWO_DI, 0,  (size_t)DI * DI);
    split(D_w, wcH, wcL, DI, TWO_DI, DI, (size_t)DI * DI);
    split(out_proj_w, woH, woL, DI, DI, 0, (size_t)DM * DI);

    // conv + SiLU -> x splits
    conv_silu_kernel<<<(M_ * DI) / 256, 256>>>(conv_w, conv_b);

    // x2 = x + x @ A_real  -> cat cols [DI, 2*DI)
    gemm_bf16x3<1, true, false><<<dim3(DI / 128, GY), 256, SMEM>>>(
        xH, xL, DI, 0, atH, atL, nullptr, xH, xL, DI, 0,
        catH, catL, TWO_DI, DI, nullptr, nullptr, DI, DI);

    // Bx = x2 @ B_w^T
    gemm_bf16x3<0, false, true><<<dim3(DI / 128, GY), 256, SMEM>>>(
        catH, catL, TWO_DI, DI, bwH, bwL, bx, nullptr, nullptr, 0, 0,
        nullptr, nullptr, 0, 0, nullptr, nullptr, DI, DI);

    // states = cumsum_L(Bx) -> cat cols [0, DI)
    cumsum_p1<<<gSeq, 256>>>();
    cumsum_p2<<<(B_ * DI) / 256, 256>>>();
    cumsum_p3<<<gSeq, 256>>>();

    // u = x2 + [states|x2] @ [C_w|D_w]^T   (K = 4096)
    gemm_bf16x3<1, false, true><<<dim3(DI / 128, GY), 256, SMEM>>>(
        catH, catL, TWO_DI, 0, wcH, wcL, u, catH, catL, TWO_DI, DI,
        nullptr, nullptr, 0, 0, nullptr, nullptr, DI, TWO_DI);

    // decay = exp(-exp(A_log) * softplus(delta @ dt_proj_w^T + b))  (K = 64)
    gemm_bf16x3<3, false, true><<<dim3(DI / 128, GY), 256, SMEM>>>(
        dlH, dlL, DTR, 0, dtH, dtL, dc, nullptr, nullptr, 0, 0,
        nullptr, nullptr, 0, 0, dt_proj_b, A_log, DI, DTR);

    // scan; pass3 fuses (+ u*D_ss) * silu(z) -> op splits
    scan_p1<<<gSeq, 256>>>();
    scan_p2<<<(B_ * DI) / 256, 256>>>();
    scan_p3<<<gSeq, 256>>>(D_ss);

    // out = out_pre @ out_proj_w^T  [8192, 1024]
    gemm_bf16x3<0, false, true><<<dim3(DM / 128, GY), 256, SMEM>>>(
        opH, opL, DI, 0, woH, woL, out, nullptr, nullptr, 0, 0,
        nullptr, nullptr, 0, 0, nullptr, nullptr, DM, DI);
}

// round 5
// speedup vs baseline: 3.5006x; 1.0863x over previous
#include <cuda_runtime.h>
#include <cuda_bf16.h>
#include <math.h>
#include <stdint.h>

// ---------------------------------------------------------------------------
// Mamba3Block on GB300 — round 5: weight folding removes the x@A GEMM.
//   H = B_w (I+A)^T          -> Bx = x @ H^T
//   G = (I+D_w)(I+A)^T       -> u  = x @ G^T + states @ C_w^T   (no residual)
// All big GEMMs on mma.sync bf16x3 (hi/lo split), 3-stage cp.async, 2 CTA/SM.
// ---------------------------------------------------------------------------

namespace {
constexpr int B_   = 2;
constexpr int L_   = 4096;
constexpr int DM   = 1024;
constexpr int DI   = 2048;
constexpr int M_   = B_ * L_;        // 8192
constexpr int NCH  = 32;
constexpr int CH   = L_ / NCH;       // 128
constexpr int TWO_DI = 2 * DI;       // 4096
constexpr int DTR  = 64;
}

// ------------------------- fp32 scratch ------------------------------------
__device__ float g_xz[(size_t)M_ * TWO_DI];
__device__ float g_bx[(size_t)M_ * DI];
__device__ float g_u [(size_t)M_ * DI];
__device__ float g_dc[(size_t)M_ * DI];
__device__ float g_p1[B_ * NCH * DI];
__device__ float g_p2[B_ * NCH * DI];
__device__ float g_p3[B_ * NCH * DI];
__device__ float g_cr[B_ * NCH * DI];

// ------------------------- bf16 split scratch ------------------------------
__device__ __nv_bfloat16 g_h_hi [(size_t)M_ * DM],   g_h_lo [(size_t)M_ * DM];
__device__ __nv_bfloat16 g_cat_hi[(size_t)M_ * TWO_DI], g_cat_lo[(size_t)M_ * TWO_DI]; // [states|x]
__device__ __nv_bfloat16 g_op_hi[(size_t)M_ * DI],   g_op_lo[(size_t)M_ * DI];
__device__ __nv_bfloat16 g_dl_hi[(size_t)M_ * DTR],  g_dl_lo[(size_t)M_ * DTR];
__device__ __nv_bfloat16 g_w1_hi[(size_t)TWO_DI * DM], g_w1_lo[(size_t)TWO_DI * DM];
__device__ __nv_bfloat16 g_ia_hi[(size_t)DI * DI],   g_ia_lo[(size_t)DI * DI];   // I + A_real
__device__ __nv_bfloat16 g_id_hi[(size_t)DI * DI],   g_id_lo[(size_t)DI * DI];   // I + D_w
__device__ __nv_bfloat16 g_hw_hi[(size_t)DI * DI],   g_hw_lo[(size_t)DI * DI];   // H = B_w(I+A)^T
__device__ __nv_bfloat16 g_wc_hi[(size_t)DI * TWO_DI], g_wc_lo[(size_t)DI * TWO_DI];  // [C_w | G]
__device__ __nv_bfloat16 g_wo_hi[(size_t)DM * DI],   g_wo_lo[(size_t)DM * DI];
__device__ __nv_bfloat16 g_bw_hi[(size_t)DI * DI],   g_bw_lo[(size_t)DI * DI];   // B_w plain
__device__ __nv_bfloat16 g_dt_hi[(size_t)DI * DTR],  g_dt_lo[(size_t)DI * DTR];

__device__ __forceinline__ float siluf(float v) { return v / (1.f + expf(-v)); }

__device__ __forceinline__ void split1(float v, __nv_bfloat16& h, __nv_bfloat16& l) {
    h = __float2bfloat16(v);
    l = __float2bfloat16(v - __bfloat162float(h));
}

// --------------------------- PTX helpers ------------------------------------
__device__ __forceinline__ uint32_t cvta_smem(const void* p) {
    uint32_t a;
    asm("{ .reg .u64 t; cvta.to.shared.u64 t, %1; cvt.u32.u64 %0, t; }" : "=r"(a) : "l"(p));
    return a;
}
__device__ __forceinline__ void cp16(uint32_t dst, const void* src) {
    asm volatile("cp.async.cg.shared.global [%0], [%1], 16;" :: "r"(dst), "l"(src) : "memory");
}
__device__ __forceinline__ void cp_commit() {
    asm volatile("cp.async.commit_group;" ::: "memory");
}
template<int N>
__device__ __forceinline__ void cp_wait() {
    asm volatile("cp.async.wait_group %0;" :: "n"(N) : "memory");
}
__device__ __forceinline__ void ldsm4(uint32_t* r, uint32_t addr) {
    asm volatile("ldmatrix.sync.aligned.m8n8.x4.shared.b16 {%0,%1,%2,%3}, [%4];"
                 : "=r"(r[0]), "=r"(r[1]), "=r"(r[2]), "=r"(r[3]) : "r"(addr));
}
__device__ __forceinline__ void mma_bf16(float* d, const uint32_t* a, uint32_t b0, uint32_t b1) {
    asm volatile(
        "mma.sync.aligned.m16n8k16.row.col.f32.bf16.bf16.f32 "
        "{%0,%1,%2,%3}, {%4,%5,%6,%7}, {%8,%9}, {%0,%1,%2,%3};"
        : "+f"(d[0]), "+f"(d[1]), "+f"(d[2]), "+f"(d[3])
        : "r"(a[0]), "r"(a[1]), "r"(a[2]), "r"(a[3]), "r"(b0), "r"(b1));
}
#define SW128(o) ((o) ^ (((o) >> 3) & 0x70))

// =====================  mma.sync bf16x3 GEMM  ================================
// C[M,N] = fp32( (Ah+Al)[M,K] @ (Bh+Bl)[N,K]^T ), tile 128x128, BK=32, 3 stages.
// A rows read at (row*lda + abase + k). Smem rows: 128B = [32 hi | 32 lo], SW128.
// EPI: 0 none; 3 decay epilogue exp(-exp(v2)*softplus(acc+v1)).
// WC: write C fp32 [row*N+col]. WB: write bf16 hi/lo split at row*ldo+obase+col.
template<int EPI, bool WB, bool WC>
__global__ __launch_bounds__(256, 2)
void gemm_bf16x3(const __nv_bfloat16* __restrict__ Ah, const __nv_bfloat16* __restrict__ Al,
                 int lda, int abase,
                 const __nv_bfloat16* __restrict__ Bh, const __nv_bfloat16* __restrict__ Bl,
                 float* __restrict__ C,
                 __nv_bfloat16* __restrict__ Oh, __nv_bfloat16* __restrict__ Ol,
                 int ldo, int obase,
                 const float* __restrict__ v1, const float* __restrict__ v2,
                 int N, int K)
{
    constexpr int STAGE_BYTES = 32 * 1024;   // A 16K + B 16K
    extern __shared__ __align__(1024) char sm_raw[];

    const int tid = threadIdx.x;
    const int wid = tid >> 5;
    const int l   = tid & 31;
    const int wm  = wid >> 1;          // 0..3  (M)
    const int wn  = wid & 1;           // 0..1  (N)
    const int bm  = blockIdx.y * 128;
    const int bn  = blockIdx.x * 128;
    const uint32_t sb = cvta_smem(sm_raw);

    const int KT = K >> 5;             // BK = 32

    // ---- cp.async loader ----
    const int ldRow = tid >> 3;        // 0..31
    const int ldCh  = tid & 7;         // chunk within 128B row
    auto load_tile = [&](int kt, int st) {
        const uint32_t aBase = sb + st * STAGE_BYTES;
        const uint32_t bBase = aBase + 16 * 1024;
        const int kof = kt * 32 + (ldCh & 3) * 8;
        const bool lo = ldCh >= 4;
        #pragma unroll
        for (int i = 0; i < 4; i++) {
            const int r = ldRow + i * 32;
            const uint32_t so = SW128((uint32_t)(r * 128 + ldCh * 16));
            const size_t ga = (size_t)(bm + r) * lda + abase + kof;
            const size_t gb = (size_t)(bn + r) * K + kof;
            cp16(aBase + so, (lo ? Al : Ah) + ga);
            cp16(bBase + so, (lo ? Bl : Bh) + gb);
        }
        cp_commit();
    };

    // ---- ldmatrix lane addressing ----
    int aRow[2], aXr[2];
    #pragma unroll
    for (int mf = 0; mf < 2; mf++) {
        aRow[mf] = wm * 32 + mf * 16 + ((l >> 3) & 1) * 8 + (l & 7);
        aXr[mf]  = (aRow[mf] & 7) << 4;
    }
    const int aChunk = ((l >> 4) & 1) * 16;
    int bRow[4], bXr[4];
    #pragma unroll
    for (int p = 0; p < 4; p++) {
        bRow[p] = wn * 64 + p * 16 + ((l >> 4) & 1) * 8 + (l & 7);
        bXr[p]  = (bRow[p] & 7) << 4;
    }
    const int bChunk = ((l >> 3) & 1) * 16;

    float acc[2][8][4];
    #pragma unroll
    for (int mf = 0; mf < 2; mf++)
        #pragma unroll
        for (int nf = 0; nf < 8; nf++)
            #pragma unroll
            for (int k = 0; k < 4; k++) acc[mf][nf][k] = 0.f;

    // prologue: 2 stages in flight
    load_tile(0, 0);
    if (KT > 1) load_tile(1, 1);

    for (int kt = 0; kt < KT; kt++) {
        if (kt + 2 < KT) cp_wait<1>();
        else             cp_wait<0>();
        __syncthreads();
        if (kt + 2 < KT) load_tile(kt + 2, (kt + 2) % 3);

        const uint32_t aBase = sb + (uint32_t)(kt % 3) * STAGE_BYTES;
        const uint32_t bBase = aBase + 16 * 1024;

        #pragma unroll
        for (int s = 0; s < 2; s++) {
            uint32_t aH[2][4], aL[2][4];
            #pragma unroll
            for (int mf = 0; mf < 2; mf++) {
                ldsm4(aH[mf], aBase + aRow[mf] * 128 + (uint32_t)(((0 << 6) | (s << 5) | aChunk) ^ aXr[mf]));
                ldsm4(aL[mf], aBase + aRow[mf] * 128 + (uint32_t)(((1 << 6) | (s << 5) | aChunk) ^ aXr[mf]));
            }
            #pragma unroll
            for (int p = 0; p < 4; p++) {
                uint32_t rH[4], rL[4];
                ldsm4(rH, bBase + bRow[p] * 128 + (uint32_t)(((0 << 6) | (s << 5) | bChunk) ^ bXr[p]));
                ldsm4(rL, bBase + bRow[p] * 128 + (uint32_t)(((1 << 6) | (s << 5) | bChunk) ^ bXr[p]));
                #pragma unroll
                for (int mf = 0; mf < 2; mf++) {
                    mma_bf16(acc[mf][2 * p],     aH[mf], rH[0], rH[1]);
                    mma_bf16(acc[mf][2 * p + 1], aH[mf], rH[2], rH[3]);
                    mma_bf16(acc[mf][2 * p],     aH[mf], rL[0], rL[1]);
                    mma_bf16(acc[mf][2 * p + 1], aH[mf], rL[2], rL[3]);
                    mma_bf16(acc[mf][2 * p],     aL[mf], rH[0], rH[1]);
                    mma_bf16(acc[mf][2 * p + 1], aL[mf], rH[2], rH[3]);
                }
            }
        }
    }

    // ---- epilogue ----
    const int g   = l >> 2;
    const int tig = l & 3;
    #pragma unroll
    for (int mf = 0; mf < 2; mf++) {
        #pragma unroll
        for (int half = 0; half < 2; half++) {
            const int row = bm + wm * 32 + mf * 16 + g + half * 8;
            #pragma unroll
            for (int nf = 0; nf < 8; nf++) {
                const int col = bn + wn * 64 + nf * 8 + tig * 2;
                float vx = acc[mf][nf][2 * half + 0];
                float vy = acc[mf][nf][2 * half + 1];
                if constexpr (EPI == 3) {
                    float tx = vx + v1[col], ty = vy + v1[col + 1];
                    float sx = (tx > 20.f) ? tx : log1pf(expf(tx));
                    float sy = (ty > 20.f) ? ty : log1pf(expf(ty));
                    vx = expf(-expf(v2[col]) * sx);
                    vy = expf(-expf(v2[col + 1]) * sy);
                }
                if constexpr (WC) {
                    *reinterpret_cast<float2*>(C + (size_t)row * N + col) = make_float2(vx, vy);
                }
                if constexpr (WB) {
                    const size_t o = (size_t)row * ldo + obase + col;
                    __nv_bfloat162 hv = __float22bfloat162_rn(make_float2(vx, vy));
                    float2 hf = __bfloat1622float2(hv);
                    __nv_bfloat162 lv = __float22bfloat162_rn(make_float2(vx - hf.x, vy - hf.y));
                    *reinterpret_cast<__nv_bfloat162*>(Oh + o) = hv;
                    *reinterpret_cast<__nv_bfloat162*>(Ol + o) = lv;
                }
            }
        }
    }
}

// -------------------- fp32 -> bf16 hi/lo strided split ----------------------
__global__ void split_strided_kernel(const float* __restrict__ src,
                                     __nv_bfloat16* __restrict__ hi,
                                     __nv_bfloat16* __restrict__ lo,
                                     int rowlen, int ld, int colofs, int n4)
{
    int i = blockIdx.x * blockDim.x + threadIdx.x;
    if (i >= n4) return;
    float4 v = reinterpret_cast<const float4*>(src)[i];
    int e = i * 4;
    int row = e / rowlen;
    int col = e - row * rowlen;
    size_t o = (size_t)row * ld + colofs + col;
    __nv_bfloat162 h0 = __float22bfloat162_rn(make_float2(v.x, v.y));
    __nv_bfloat162 h1 = __float22bfloat162_rn(make_float2(v.z, v.w));
    float2 f0 = __bfloat1622float2(h0);
    float2 f1 = __bfloat1622float2(h1);
    __nv_bfloat162 l0 = __float22bfloat162_rn(make_float2(v.x - f0.x, v.y - f0.y));
    __nv_bfloat162 l1 = __float22bfloat162_rn(make_float2(v.z - f1.x, v.w - f1.y));
    *reinterpret_cast<__nv_bfloat162*>(hi + o)     = h0;
    *reinterpret_cast<__nv_bfloat162*>(hi + o + 2) = h1;
    *reinterpret_cast<__nv_bfloat162*>(lo + o)     = l0;
    *reinterpret_cast<__nv_bfloat162*>(lo + o + 2) = l1;
}

// -------------------- fp32 [DI x DI] + I -> bf16 hi/lo split ----------------
__global__ void split_eye_kernel(const float* __restrict__ src,
                                 __nv_bfloat16* __restrict__ hi,
                                 __nv_bfloat16* __restrict__ lo)
{
    int i = blockIdx.x * blockDim.x + threadIdx.x;   // float4 index
    if (i >= DI * DI / 4) return;
    float4 v = reinterpret_cast<const float4*>(src)[i];
    int e = i * 4;
    int row = e / DI;
    int col = e - row * DI;
    if (row == col)     v.x += 1.f;
    if (row == col + 1) v.y += 1.f;
    if (row == col + 2) v.z += 1.f;
    if (row == col + 3) v.w += 1.f;
    __nv_bfloat162 h0 = __float22bfloat162_rn(make_float2(v.x, v.y));
    __nv_bfloat162 h1 = __float22bfloat162_rn(make_float2(v.z, v.w));
    float2 f0 = __bfloat1622float2(h0);
    float2 f1 = __bfloat1622float2(h1);
    __nv_bfloat162 l0 = __float22bfloat162_rn(make_float2(v.x - f0.x, v.y - f0.y));
    __nv_bfloat162 l1 = __float22bfloat162_rn(make_float2(v.z - f1.x, v.w - f1.y));
    size_t o = (size_t)e;
    *reinterpret_cast<__nv_bfloat162*>(hi + o)     = h0;
    *reinterpret_cast<__nv_bfloat162*>(hi + o + 2) = h1;
    *reinterpret_cast<__nv_bfloat162*>(lo + o)     = l0;
    *reinterpret_cast<__nv_bfloat162*>(lo + o + 2) = l1;
}

// -------------------- conv + bias + SiLU -> cat cols [DI, 2*DI) -------------
__global__ void conv_silu_kernel(const float* __restrict__ w, const float* __restrict__ bias)
{
    int i = blockIdx.x * blockDim.x + threadIdx.x;
    if (i >= M_ * DI) return;
    int c  = i % DI;
    int l  = (i / DI) % L_;
    int bb = i / (DI * L_);
    const float* base = g_xz + (size_t)bb * L_ * TWO_DI + c;
    float acc = bias[c];
    #pragma unroll
    for (int k = 0; k < 4; k++) {
        int ll = l - 3 + k;
        if (ll >= 0) acc = fmaf(w[c * 4 + k], base[(size_t)ll * TWO_DI], acc);
    }
    float v = siluf(acc);
    size_t co = (size_t)(i / DI) * TWO_DI + DI + c;
    split1(v, g_cat_hi[co], g_cat_lo[co]);
}

// ------------------------------ cumsum over L -------------------------------
__global__ void cumsum_p1()
{
    int c   = blockIdx.x * blockDim.x + threadIdx.x;
    int seq = blockIdx.y;
    int bb = seq / NCH, ch = seq % NCH;
    size_t base = ((size_t)(bb * L_ + ch * CH)) * DI + c;
    float s = 0.f;
    for (int i = 0; i < CH; i++) s += g_bx[base + (size_t)i * DI];
    g_p1[seq * DI + c] = s;
}
__global__ void cumsum_p2()
{
    int i = blockIdx.x * blockDim.x + threadIdx.x;
    if (i >= B_ * DI) return;
    int bb = i / DI, c = i % DI;
    float carry = 0.f;
    for (int ch = 0; ch < NCH; ch++) {
        int idx = (bb * NCH + ch) * DI + c;
        g_cr[idx] = carry;
        carry += g_p1[idx];
    }
}
__global__ void cumsum_p3()   // states -> cat splits cols [0, DI)
{
    int c   = blockIdx.x * blockDim.x + threadIdx.x;
    int seq = blockIdx.y;
    int bb = seq / NCH, ch = seq % NCH;
    int gl0 = bb * L_ + ch * CH;
    float carry = g_cr[seq * DI + c];
    for (int i = 0; i < CH; i++) {
        size_t idx = (size_t)(gl0 + i) * DI + c;
        carry += g_bx[idx];
        size_t co = (size_t)(gl0 + i) * TWO_DI + c;
        split1(carry, g_cat_hi[co], g_cat_lo[co]);
    }
}

// ----------------------- decay recurrence scan ------------------------------
__global__ void scan_p1()
{
    int c   = blockIdx.x * blockDim.x + threadIdx.x;
    int seq = blockIdx.y;
    int bb = seq / NCH, ch = seq % NCH;
    size_t base = ((size_t)(bb * L_ + ch * CH)) * DI + c;
    float P = 1.f, S = 0.f;
    for (int i = 0; i < CH; i++) {
        size_t idx = base + (size_t)i * DI;
        float d = g_dc[idx];
        S = fmaf(d, S, g_u[idx]);
        P *= d;
    }
    g_p2[seq * DI + c] = P;
    g_p3[seq * DI + c] = S;
}
__global__ void scan_p2()
{
    int i = blockIdx.x * blockDim.x + threadIdx.x;
    if (i >= B_ * DI) return;
    int bb = i / DI, c = i % DI;
    float carry = 0.f;
    for (int ch = 0; ch < NCH; ch++) {
        int idx = (bb * NCH + ch) * DI + c;
        g_cr[idx] = carry;
        carry = fmaf(g_p2[idx], carry, g_p3[idx]);
    }
}
__global__ void scan_p3(const float* __restrict__ D_ss)  // out_pre -> op splits
{
    int c   = blockIdx.x * blockDim.x + threadIdx.x;
    int seq = blockIdx.y;
    int bb = seq / NCH, ch = seq % NCH;
    int l0 = ch * CH;
    size_t base = ((size_t)(bb * L_ + l0)) * DI + c;
    float state = g_cr[seq * DI + c];
    float dss = D_ss[c];
    for (int i = 0; i < CH; i++) {
        size_t idx = base + (size_t)i * DI;
        float u = g_u[idx];
        state = fmaf(g_dc[idx], state, u);
        float z = g_xz[(size_t)(bb * L_ + l0 + i) * TWO_DI + DI + c];
        float v = (state + u * dss) * siluf(z);
        split1(v, g_op_hi[idx], g_op_lo[idx]);
    }
}

// ------------------------------- launcher ----------------------------------
extern "C" void kernel_launch(void* const* d_in, const int* in_sizes, int n_in,
                              void* d_out, int out_size)
{
    const float* h         = (const float*)d_in[0];
    const float* delta     = (const float*)d_in[1];
    const float* in_proj_w = (const float*)d_in[2];
    const float* conv_w    = (const float*)d_in[3];
    const float* conv_b    = (const float*)d_in[4];
    const float* A_real    = (const float*)d_in[5];
    const float* B_w       = (const float*)d_in[6];
    const float* C_w       = (const float*)d_in[7];
    const float* D_w       = (const float*)d_in[8];
    const float* dt_proj_w = (const float*)d_in[9];
    const float* dt_proj_b = (const float*)d_in[10];
    const float* A_log     = (const float*)d_in[11];
    const float* D_ss      = (const float*)d_in[12];
    const float* out_proj_w= (const float*)d_in[13];
    float* out = (float*)d_out;

    float *xz, *bx, *u, *dc;
    cudaGetSymbolAddress((void**)&xz, g_xz);
    cudaGetSymbolAddress((void**)&bx, g_bx);
    cudaGetSymbolAddress((void**)&u,  g_u);
    cudaGetSymbolAddress((void**)&dc, g_dc);
    __nv_bfloat16 *hH,*hL,*catH,*catL,*opH,*opL,*dlH,*dlL;
    __nv_bfloat16 *w1H,*w1L,*iaH,*iaL,*idH,*idL,*hwH,*hwL,*wcH,*wcL,*woH,*woL,*bwH,*bwL,*dtH,*dtL;
    cudaGetSymbolAddress((void**)&hH,   g_h_hi);   cudaGetSymbolAddress((void**)&hL,   g_h_lo);
    cudaGetSymbolAddress((void**)&catH, g_cat_hi); cudaGetSymbolAddress((void**)&catL, g_cat_lo);
    cudaGetSymbolAddress((void**)&opH,  g_op_hi);  cudaGetSymbolAddress((void**)&opL,  g_op_lo);
    cudaGetSymbolAddress((void**)&dlH,  g_dl_hi);  cudaGetSymbolAddress((void**)&dlL,  g_dl_lo);
    cudaGetSymbolAddress((void**)&w1H,  g_w1_hi);  cudaGetSymbolAddress((void**)&w1L,  g_w1_lo);
    cudaGetSymbolAddress((void**)&iaH,  g_ia_hi);  cudaGetSymbolAddress((void**)&iaL,  g_ia_lo);
    cudaGetSymbolAddress((void**)&idH,  g_id_hi);  cudaGetSymbolAddress((void**)&idL,  g_id_lo);
    cudaGetSymbolAddress((void**)&hwH,  g_hw_hi);  cudaGetSymbolAddress((void**)&hwL,  g_hw_lo);
    cudaGetSymbolAddress((void**)&wcH,  g_wc_hi);  cudaGetSymbolAddress((void**)&wcL,  g_wc_lo);
    cudaGetSymbolAddress((void**)&woH,  g_wo_hi);  cudaGetSymbolAddress((void**)&woL,  g_wo_lo);
    cudaGetSymbolAddress((void**)&bwH,  g_bw_hi);  cudaGetSymbolAddress((void**)&bwL,  g_bw_lo);
    cudaGetSymbolAddress((void**)&dtH,  g_dt_hi);  cudaGetSymbolAddress((void**)&dtL,  g_dt_lo);

    constexpr int SMEM = 96 * 1024;
    cudaFuncSetAttribute(gemm_bf16x3<0, false, true>, cudaFuncAttributeMaxDynamicSharedMemorySize, SMEM);
    cudaFuncSetAttribute(gemm_bf16x3<0, true, false>, cudaFuncAttributeMaxDynamicSharedMemorySize, SMEM);
    cudaFuncSetAttribute(gemm_bf16x3<3, false, true>, cudaFuncAttributeMaxDynamicSharedMemorySize, SMEM);

    auto split = [&](const float* s, __nv_bfloat16* hi_, __nv_bfloat16* lo_,
                     int rowlen, int ld, int colofs, size_t n) {
        int n4 = (int)(n / 4);
        split_strided_kernel<<<(n4 + 255) / 256, 256>>>(s, hi_, lo_, rowlen, ld, colofs, n4);
    };

    const int GY = M_ / 128;   // 64
    const dim3 gSeq(DI / 256, B_ * NCH);

    // ---- input / weight conversions ----
    split(h,         hH,  hL,  DM, DM, 0, (size_t)M_ * DM);
    split(in_proj_w, w1H, w1L, DM, DM, 0, (size_t)TWO_DI * DM);
    split(delta,     dlH, dlL, DTR, DTR, 0, (size_t)M_ * DTR);
    split(dt_proj_w, dtH, dtL, DTR, DTR, 0, (size_t)DI * DTR);
    split_eye_kernel<<<(DI * DI / 4) / 256, 256>>>(A_real, iaH, iaL);  // I + A
    split_eye_kernel<<<(DI * DI / 4) / 256, 256>>>(D_w,    idH, idL);  // I + D
    split(B_w, bwH, bwL, DI, DI, 0, (size_t)DI * DI);
    split(C_w, wcH, wcL, DI, TWO_DI, 0, (size_t)DI * DI);
    split(out_proj_w, woH, woL, DI, DI, 0, (size_t)DM * DI);

    // ---- weight folds (bf16x3 GEMMs on 2048^3) ----
    // H[s',s] = sum_k B_w[s',k] (I+A)[s,k]   -> Bx = x @ H^T
    gemm_bf16x3<0, true, false><<<dim3(DI / 128, DI / 128), 256, SMEM>>>(
        bwH, bwL, DI, 0, iaH, iaL, nullptr, hwH, hwL, DI, 0,
        nullptr, nullptr, DI, DI);
    // G[e,s] = sum_k (I+D)[e,k] (I+A)[s,k]   -> u = x @ G^T + states @ C_w^T
    gemm_bf16x3<0, true, false><<<dim3(DI / 128, DI / 128), 256, SMEM>>>(
        idH, idL, DI, 0, iaH, iaL, nullptr, wcH, wcL, TWO_DI, DI,
        nullptr, nullptr, DI, DI);

    // ---- main sequence ----
    // xz = h @ in_proj_w^T   [8192, 4096]
    gemm_bf16x3<0, false, true><<<dim3(TWO_DI / 128, GY), 256, SMEM>>>(
        hH, hL, DM, 0, w1H, w1L, xz, nullptr, nullptr, 0, 0,
        nullptr, nullptr, TWO_DI, DM);

    // conv + SiLU -> cat cols [DI, 2*DI)
    conv_silu_kernel<<<(M_ * DI) / 256, 256>>>(conv_w, conv_b);

    // Bx = x @ H^T
    gemm_bf16x3<0, false, true><<<dim3(DI / 128, GY), 256, SMEM>>>(
        catH, catL, TWO_DI, DI, hwH, hwL, bx, nullptr, nullptr, 0, 0,
        nullptr, nullptr, DI, DI);

    // states = cumsum_L(Bx) -> cat cols [0, DI)
    cumsum_p1<<<gSeq, 256>>>();
    cumsum_p2<<<(B_ * DI) / 256, 256>>>();
    cumsum_p3<<<gSeq, 256>>>();

    // u = [states|x] @ [C_w|G]^T   (K = 4096, no residual)
    gemm_bf16x3<0, false, true><<<dim3(DI / 128, GY), 256, SMEM>>>(
        catH, catL, TWO_DI, 0, wcH, wcL, u, nullptr, nullptr, 0, 0,
        nullptr, nullptr, DI, TWO_DI);

    // decay = exp(-exp(A_log) * softplus(delta @ dt_proj_w^T + b))  (K = 64)
    gemm_bf16x3<3, false, true><<<dim3(DI / 128, GY), 256, SMEM>>>(
        dlH, dlL, DTR, 0, dtH, dtL, dc, nullptr, nullptr, 0, 0,
        dt_proj_b, A_log, DI, DTR);

    // scan; pass3 fuses (+ u*D_ss) * silu(z) -> op splits
    scan_p1<<<gSeq, 256>>>();
    scan_p2<<<(B_ * DI) / 256, 256>>>();
    scan_p3<<<gSeq, 256>>>(D_ss);

    // out = out_pre @ out_proj_w^T  [8192, 1024]
    gemm_bf16x3<0, false, true><<<dim3(DM / 128, GY), 256, SMEM>>>(
        opH, opL, DI, 0, woH, woL, out, nullptr, nullptr, 0, 0,
        nullptr, nullptr, DM, DI);
}

// round 6
// speedup vs baseline: 4.0260x; 1.1501x over previous
#include <cuda_runtime.h>
#include <cuda_bf16.h>
#include <math.h>
#include <stdint.h>

// ---------------------------------------------------------------------------
// Mamba3Block on GB300 — round 6: cumsum-linearity fold removes the Bx GEMM.
//   W2 = C_w B_w (I+A)^T ; G = (I+D)(I+A)^T ; cx = cumsum_L(x)
//   u  = [cx | x] @ [W2 | G]^T
// All big GEMMs on mma.sync bf16x3 (hi/lo split), 3-stage cp.async, 2 CTA/SM.
// ---------------------------------------------------------------------------

namespace {
constexpr int B_   = 2;
constexpr int L_   = 4096;
constexpr int DM   = 1024;
constexpr int DI   = 2048;
constexpr int M_   = B_ * L_;        // 8192
constexpr int NCH  = 64;
constexpr int CH   = L_ / NCH;       // 64
constexpr int TWO_DI = 2 * DI;       // 4096
constexpr int DTR  = 64;
}

// ------------------------- fp32 scratch ------------------------------------
__device__ float g_xz[(size_t)M_ * TWO_DI];
__device__ float g_u [(size_t)M_ * DI];
__device__ float g_dc[(size_t)M_ * DI];
__device__ float g_p1[B_ * NCH * DI];
__device__ float g_p2[B_ * NCH * DI];
__device__ float g_p3[B_ * NCH * DI];
__device__ float g_cr[B_ * NCH * DI];

// ------------------------- bf16 split scratch ------------------------------
__device__ __nv_bfloat16 g_h_hi [(size_t)M_ * DM],   g_h_lo [(size_t)M_ * DM];
__device__ __nv_bfloat16 g_cat_hi[(size_t)M_ * TWO_DI], g_cat_lo[(size_t)M_ * TWO_DI]; // [cx|x]
__device__ __nv_bfloat16 g_op_hi[(size_t)M_ * DI],   g_op_lo[(size_t)M_ * DI];
__device__ __nv_bfloat16 g_dl_hi[(size_t)M_ * DTR],  g_dl_lo[(size_t)M_ * DTR];
__device__ __nv_bfloat16 g_w1_hi[(size_t)TWO_DI * DM], g_w1_lo[(size_t)TWO_DI * DM];
__device__ __nv_bfloat16 g_ia_hi[(size_t)DI * DI],   g_ia_lo[(size_t)DI * DI];   // I + A_real
__device__ __nv_bfloat16 g_id_hi[(size_t)DI * DI],   g_id_lo[(size_t)DI * DI];   // I + D_w
__device__ __nv_bfloat16 g_cw_hi[(size_t)DI * DI],   g_cw_lo[(size_t)DI * DI];   // C_w
__device__ __nv_bfloat16 g_bt_hi[(size_t)DI * DI],   g_bt_lo[(size_t)DI * DI];   // B_w^T
__device__ __nv_bfloat16 g_hw_hi[(size_t)DI * DI],   g_hw_lo[(size_t)DI * DI];   // T = C_w B_w
__device__ __nv_bfloat16 g_wc_hi[(size_t)DI * TWO_DI], g_wc_lo[(size_t)DI * TWO_DI];  // [W2 | G]
__device__ __nv_bfloat16 g_wo_hi[(size_t)DM * DI],   g_wo_lo[(size_t)DM * DI];
__device__ __nv_bfloat16 g_dt_hi[(size_t)DI * DTR],  g_dt_lo[(size_t)DI * DTR];

__device__ __forceinline__ float siluf(float v) { return v / (1.f + expf(-v)); }

__device__ __forceinline__ void split1(float v, __nv_bfloat16& h, __nv_bfloat16& l) {
    h = __float2bfloat16(v);
    l = __float2bfloat16(v - __bfloat162float(h));
}

// --------------------------- PTX helpers ------------------------------------
__device__ __forceinline__ uint32_t cvta_smem(const void* p) {
    uint32_t a;
    asm("{ .reg .u64 t; cvta.to.shared.u64 t, %1; cvt.u32.u64 %0, t; }" : "=r"(a) : "l"(p));
    return a;
}
__device__ __forceinline__ void cp16(uint32_t dst, const void* src) {
    asm volatile("cp.async.cg.shared.global [%0], [%1], 16;" :: "r"(dst), "l"(src) : "memory");
}
__device__ __forceinline__ void cp_commit() {
    asm volatile("cp.async.commit_group;" ::: "memory");
}
template<int N>
__device__ __forceinline__ void cp_wait() {
    asm volatile("cp.async.wait_group %0;" :: "n"(N) : "memory");
}
__device__ __forceinline__ void ldsm4(uint32_t* r, uint32_t addr) {
    asm volatile("ldmatrix.sync.aligned.m8n8.x4.shared.b16 {%0,%1,%2,%3}, [%4];"
                 : "=r"(r[0]), "=r"(r[1]), "=r"(r[2]), "=r"(r[3]) : "r"(addr));
}
__device__ __forceinline__ void mma_bf16(float* d, const uint32_t* a, uint32_t b0, uint32_t b1) {
    asm volatile(
        "mma.sync.aligned.m16n8k16.row.col.f32.bf16.bf16.f32 "
        "{%0,%1,%2,%3}, {%4,%5,%6,%7}, {%8,%9}, {%0,%1,%2,%3};"
        : "+f"(d[0]), "+f"(d[1]), "+f"(d[2]), "+f"(d[3])
        : "r"(a[0]), "r"(a[1]), "r"(a[2]), "r"(a[3]), "r"(b0), "r"(b1));
}
#define SW128(o) ((o) ^ (((o) >> 3) & 0x70))

// =====================  mma.sync bf16x3 GEMM  ================================
// C[M,N] = fp32( (Ah+Al)[M,K] @ (Bh+Bl)[N,K]^T ), tile 128x128, BK=32, 3 stages.
// A rows read at (row*lda + abase + k). Smem rows: 128B = [32 hi | 32 lo], SW128.
// EPI: 0 none; 3 decay epilogue exp(-exp(v2)*softplus(acc+v1)).
// WC: write C fp32 [row*N+col]. WB: write bf16 hi/lo split at row*ldo+obase+col.
template<int EPI, bool WB, bool WC>
__global__ __launch_bounds__(256, 2)
void gemm_bf16x3(const __nv_bfloat16* __restrict__ Ah, const __nv_bfloat16* __restrict__ Al,
                 int lda, int abase,
                 const __nv_bfloat16* __restrict__ Bh, const __nv_bfloat16* __restrict__ Bl,
                 float* __restrict__ C,
                 __nv_bfloat16* __restrict__ Oh, __nv_bfloat16* __restrict__ Ol,
                 int ldo, int obase,
                 const float* __restrict__ v1, const float* __restrict__ v2,
                 int N, int K)
{
    constexpr int STAGE_BYTES = 32 * 1024;   // A 16K + B 16K
    extern __shared__ __align__(1024) char sm_raw[];

    const int tid = threadIdx.x;
    const int wid = tid >> 5;
    const int l   = tid & 31;
    const int wm  = wid >> 1;          // 0..3  (M)
    const int wn  = wid & 1;           // 0..1  (N)
    const int bm  = blockIdx.y * 128;
    const int bn  = blockIdx.x * 128;
    const uint32_t sb = cvta_smem(sm_raw);

    const int KT = K >> 5;             // BK = 32

    // ---- cp.async loader ----
    const int ldRow = tid >> 3;        // 0..31
    const int ldCh  = tid & 7;         // chunk within 128B row
    auto load_tile = [&](int kt, int st) {
        const uint32_t aBase = sb + st * STAGE_BYTES;
        const uint32_t bBase = aBase + 16 * 1024;
        const int kof = kt * 32 + (ldCh & 3) * 8;
        const bool lo = ldCh >= 4;
        #pragma unroll
        for (int i = 0; i < 4; i++) {
            const int r = ldRow + i * 32;
            const uint32_t so = SW128((uint32_t)(r * 128 + ldCh * 16));
            const size_t ga = (size_t)(bm + r) * lda + abase + kof;
            const size_t gb = (size_t)(bn + r) * K + kof;
            cp16(aBase + so, (lo ? Al : Ah) + ga);
            cp16(bBase + so, (lo ? Bl : Bh) + gb);
        }
        cp_commit();
    };

    // ---- ldmatrix lane addressing ----
    int aRow[2], aXr[2];
    #pragma unroll
    for (int mf = 0; mf < 2; mf++) {
        aRow[mf] = wm * 32 + mf * 16 + ((l >> 3) & 1) * 8 + (l & 7);
        aXr[mf]  = (aRow[mf] & 7) << 4;
    }
    const int aChunk = ((l >> 4) & 1) * 16;
    int bRow[4], bXr[4];
    #pragma unroll
    for (int p = 0; p < 4; p++) {
        bRow[p] = wn * 64 + p * 16 + ((l >> 4) & 1) * 8 + (l & 7);
        bXr[p]  = (bRow[p] & 7) << 4;
    }
    const int bChunk = ((l >> 3) & 1) * 16;

    float acc[2][8][4];
    #pragma unroll
    for (int mf = 0; mf < 2; mf++)
        #pragma unroll
        for (int nf = 0; nf < 8; nf++)
            #pragma unroll
            for (int k = 0; k < 4; k++) acc[mf][nf][k] = 0.f;

    // prologue: 2 stages in flight
    load_tile(0, 0);
    if (KT > 1) load_tile(1, 1);

    for (int kt = 0; kt < KT; kt++) {
        if (kt + 2 < KT) cp_wait<1>();
        else             cp_wait<0>();
        __syncthreads();
        if (kt + 2 < KT) load_tile(kt + 2, (kt + 2) % 3);

        const uint32_t aBase = sb + (uint32_t)(kt % 3) * STAGE_BYTES;
        const uint32_t bBase = aBase + 16 * 1024;

        #pragma unroll
        for (int s = 0; s < 2; s++) {
            uint32_t aH[2][4], aL[2][4];
            #pragma unroll
            for (int mf = 0; mf < 2; mf++) {
                ldsm4(aH[mf], aBase + aRow[mf] * 128 + (uint32_t)(((0 << 6) | (s << 5) | aChunk) ^ aXr[mf]));
                ldsm4(aL[mf], aBase + aRow[mf] * 128 + (uint32_t)(((1 << 6) | (s << 5) | aChunk) ^ aXr[mf]));
            }
            #pragma unroll
            for (int p = 0; p < 4; p++) {
                uint32_t rH[4], rL[4];
                ldsm4(rH, bBase + bRow[p] * 128 + (uint32_t)(((0 << 6) | (s << 5) | bChunk) ^ bXr[p]));
                ldsm4(rL, bBase + bRow[p] * 128 + (uint32_t)(((1 << 6) | (s << 5) | bChunk) ^ bXr[p]));
                #pragma unroll
                for (int mf = 0; mf < 2; mf++) {
                    mma_bf16(acc[mf][2 * p],     aH[mf], rH[0], rH[1]);
                    mma_bf16(acc[mf][2 * p + 1], aH[mf], rH[2], rH[3]);
                    mma_bf16(acc[mf][2 * p],     aH[mf], rL[0], rL[1]);
                    mma_bf16(acc[mf][2 * p + 1], aH[mf], rL[2], rL[3]);
                    mma_bf16(acc[mf][2 * p],     aL[mf], rH[0], rH[1]);
                    mma_bf16(acc[mf][2 * p + 1], aL[mf], rH[2], rH[3]);
                }
            }
        }
    }

    // ---- epilogue ----
    const int g   = l >> 2;
    const int tig = l & 3;
    #pragma unroll
    for (int mf = 0; mf < 2; mf++) {
        #pragma unroll
        for (int half = 0; half < 2; half++) {
            const int row = bm + wm * 32 + mf * 16 + g + half * 8;
            #pragma unroll
            for (int nf = 0; nf < 8; nf++) {
                const int col = bn + wn * 64 + nf * 8 + tig * 2;
                float vx = acc[mf][nf][2 * half + 0];
                float vy = acc[mf][nf][2 * half + 1];
                if constexpr (EPI == 3) {
                    float tx = vx + v1[col], ty = vy + v1[col + 1];
                    float sx = (tx > 20.f) ? tx : log1pf(expf(tx));
                    float sy = (ty > 20.f) ? ty : log1pf(expf(ty));
                    vx = expf(-expf(v2[col]) * sx);
                    vy = expf(-expf(v2[col + 1]) * sy);
                }
                if constexpr (WC) {
                    *reinterpret_cast<float2*>(C + (size_t)row * N + col) = make_float2(vx, vy);
                }
                if constexpr (WB) {
                    const size_t o = (size_t)row * ldo + obase + col;
                    __nv_bfloat162 hv = __float22bfloat162_rn(make_float2(vx, vy));
                    float2 hf = __bfloat1622float2(hv);
                    __nv_bfloat162 lv = __float22bfloat162_rn(make_float2(vx - hf.x, vy - hf.y));
                    *reinterpret_cast<__nv_bfloat162*>(Oh + o) = hv;
                    *reinterpret_cast<__nv_bfloat162*>(Ol + o) = lv;
                }
            }
        }
    }
}

// -------------------- fp32 -> bf16 hi/lo strided split ----------------------
__global__ void split_strided_kernel(const float* __restrict__ src,
                                     __nv_bfloat16* __restrict__ hi,
                                     __nv_bfloat16* __restrict__ lo,
                                     int rowlen, int ld, int colofs, int n4)
{
    int i = blockIdx.x * blockDim.x + threadIdx.x;
    if (i >= n4) return;
    float4 v = reinterpret_cast<const float4*>(src)[i];
    int e = i * 4;
    int row = e / rowlen;
    int col = e - row * rowlen;
    size_t o = (size_t)row * ld + colofs + col;
    __nv_bfloat162 h0 = __float22bfloat162_rn(make_float2(v.x, v.y));
    __nv_bfloat162 h1 = __float22bfloat162_rn(make_float2(v.z, v.w));
    float2 f0 = __bfloat1622float2(h0);
    float2 f1 = __bfloat1622float2(h1);
    __nv_bfloat162 l0 = __float22bfloat162_rn(make_float2(v.x - f0.x, v.y - f0.y));
    __nv_bfloat162 l1 = __float22bfloat162_rn(make_float2(v.z - f1.x, v.w - f1.y));
    *reinterpret_cast<__nv_bfloat162*>(hi + o)     = h0;
    *reinterpret_cast<__nv_bfloat162*>(hi + o + 2) = h1;
    *reinterpret_cast<__nv_bfloat162*>(lo + o)     = l0;
    *reinterpret_cast<__nv_bfloat162*>(lo + o + 2) = l1;
}

// -------------------- fp32 [DI x DI] + I -> bf16 hi/lo split ----------------
__global__ void split_eye_kernel(const float* __restrict__ src,
                                 __nv_bfloat16* __restrict__ hi,
                                 __nv_bfloat16* __restrict__ lo)
{
    int i = blockIdx.x * blockDim.x + threadIdx.x;   // float4 index
    if (i >= DI * DI / 4) return;
    float4 v = reinterpret_cast<const float4*>(src)[i];
    int e = i * 4;
    int row = e / DI;
    int col = e - row * DI;
    if (row == col)     v.x += 1.f;
    if (row == col + 1) v.y += 1.f;
    if (row == col + 2) v.z += 1.f;
    if (row == col + 3) v.w += 1.f;
    __nv_bfloat162 h0 = __float22bfloat162_rn(make_float2(v.x, v.y));
    __nv_bfloat162 h1 = __float22bfloat162_rn(make_float2(v.z, v.w));
    float2 f0 = __bfloat1622float2(h0);
    float2 f1 = __bfloat1622float2(h1);
    __nv_bfloat162 l0 = __float22bfloat162_rn(make_float2(v.x - f0.x, v.y - f0.y));
    __nv_bfloat162 l1 = __float22bfloat162_rn(make_float2(v.z - f1.x, v.w - f1.y));
    size_t o = (size_t)e;
    *reinterpret_cast<__nv_bfloat162*>(hi + o)     = h0;
    *reinterpret_cast<__nv_bfloat162*>(hi + o + 2) = h1;
    *reinterpret_cast<__nv_bfloat162*>(lo + o)     = l0;
    *reinterpret_cast<__nv_bfloat162*>(lo + o + 2) = l1;
}

// -------------------- transpose [DI x DI] + split ---------------------------
__global__ void transpose_split_kernel(const float* __restrict__ src,
                                       __nv_bfloat16* __restrict__ hi,
                                       __nv_bfloat16* __restrict__ lo)
{
    __shared__ float t[32][33];
    int x = blockIdx.x * 32 + threadIdx.x;
    int y = blockIdx.y * 32 + threadIdx.y;
    #pragma unroll
    for (int j = 0; j < 32; j += 8)
        t[threadIdx.y + j][threadIdx.x] = src[(size_t)(y + j) * DI + x];
    __syncthreads();
    int ox = blockIdx.y * 32 + threadIdx.x;
    int oy = blockIdx.x * 32 + threadIdx.y;
    #pragma unroll
    for (int j = 0; j < 32; j += 8) {
        float v = t[threadIdx.x][threadIdx.y + j];
        size_t o = (size_t)(oy + j) * DI + ox;
        split1(v, hi[o], lo[o]);
    }
}

// -------------------- conv + bias + SiLU -> cat cols [DI, 2*DI) -------------
__global__ void conv_silu_kernel(const float* __restrict__ w, const float* __restrict__ bias)
{
    int i = blockIdx.x * blockDim.x + threadIdx.x;
    if (i >= M_ * DI) return;
    int c  = i % DI;
    int l  = (i / DI) % L_;
    int bb = i / (DI * L_);
    const float* base = g_xz + (size_t)bb * L_ * TWO_DI + c;
    float acc = bias[c];
    #pragma unroll
    for (int k = 0; k < 4; k++) {
        int ll = l - 3 + k;
        if (ll >= 0) acc = fmaf(w[c * 4 + k], base[(size_t)ll * TWO_DI], acc);
    }
    float v = siluf(acc);
    size_t co = (size_t)(i / DI) * TWO_DI + DI + c;
    split1(v, g_cat_hi[co], g_cat_lo[co]);
}

// ------------------------ cumsum of x over L (3 passes) ----------------------
// reads x from cat splits cols [DI, 2*DI), writes cx splits to cols [0, DI)
__global__ void cumsum_p1()
{
    int c   = blockIdx.x * blockDim.x + threadIdx.x;
    int seq = blockIdx.y;
    int bb = seq / NCH, ch = seq % NCH;
    size_t base = ((size_t)(bb * L_ + ch * CH)) * TWO_DI + DI + c;
    float s = 0.f;
    for (int i = 0; i < CH; i++) {
        size_t o = base + (size_t)i * TWO_DI;
        s += __bfloat162float(g_cat_hi[o]) + __bfloat162float(g_cat_lo[o]);
    }
    g_p1[seq * DI + c] = s;
}
__global__ void cumsum_p2()
{
    int i = blockIdx.x * blockDim.x + threadIdx.x;
    if (i >= B_ * DI) return;
    int bb = i / DI, c = i % DI;
    float carry = 0.f;
    for (int ch = 0; ch < NCH; ch++) {
        int idx = (bb * NCH + ch) * DI + c;
        g_cr[idx] = carry;
        carry += g_p1[idx];
    }
}
__global__ void cumsum_p3()
{
    int c   = blockIdx.x * blockDim.x + threadIdx.x;
    int seq = blockIdx.y;
    int bb = seq / NCH, ch = seq % NCH;
    size_t base = ((size_t)(bb * L_ + ch * CH)) * TWO_DI;
    float carry = g_cr[seq * DI + c];
    for (int i = 0; i < CH; i++) {
        size_t ro = base + (size_t)i * TWO_DI;
        carry += __bfloat162float(g_cat_hi[ro + DI + c]) + __bfloat162float(g_cat_lo[ro + DI + c]);
        split1(carry, g_cat_hi[ro + c], g_cat_lo[ro + c]);
    }
}

// ----------------------- decay recurrence scan ------------------------------
__global__ void scan_p1()
{
    int c   = blockIdx.x * blockDim.x + threadIdx.x;
    int seq = blockIdx.y;
    int bb = seq / NCH, ch = seq % NCH;
    size_t base = ((size_t)(bb * L_ + ch * CH)) * DI + c;
    float P = 1.f, S = 0.f;
    for (int i = 0; i < CH; i++) {
        size_t idx = base + (size_t)i * DI;
        float d = g_dc[idx];
        S = fmaf(d, S, g_u[idx]);
        P *= d;
    }
    g_p2[seq * DI + c] = P;
    g_p3[seq * DI + c] = S;
}
__global__ void scan_p2()
{
    int i = blockIdx.x * blockDim.x + threadIdx.x;
    if (i >= B_ * DI) return;
    int bb = i / DI, c = i % DI;
    float carry = 0.f;
    for (int ch = 0; ch < NCH; ch++) {
        int idx = (bb * NCH + ch) * DI + c;
        g_cr[idx] = carry;
        carry = fmaf(g_p2[idx], carry, g_p3[idx]);
    }
}
__global__ void scan_p3(const float* __restrict__ D_ss)  // out_pre -> op splits
{
    int c   = blockIdx.x * blockDim.x + threadIdx.x;
    int seq = blockIdx.y;
    int bb = seq / NCH, ch = seq % NCH;
    int l0 = ch * CH;
    size_t base = ((size_t)(bb * L_ + l0)) * DI + c;
    float state = g_cr[seq * DI + c];
    float dss = D_ss[c];
    for (int i = 0; i < CH; i++) {
        size_t idx = base + (size_t)i * DI;
        float u = g_u[idx];
        state = fmaf(g_dc[idx], state, u);
        float z = g_xz[(size_t)(bb * L_ + l0 + i) * TWO_DI + DI + c];
        float v = (state + u * dss) * siluf(z);
        split1(v, g_op_hi[idx], g_op_lo[idx]);
    }
}

// ------------------------------- launcher ----------------------------------
extern "C" void kernel_launch(void* const* d_in, const int* in_sizes, int n_in,
                              void* d_out, int out_size)
{
    const float* h         = (const float*)d_in[0];
    const float* delta     = (const float*)d_in[1];
    const float* in_proj_w = (const float*)d_in[2];
    const float* conv_w    = (const float*)d_in[3];
    const float* conv_b    = (const float*)d_in[4];
    const float* A_real    = (const float*)d_in[5];
    const float* B_w       = (const float*)d_in[6];
    const float* C_w       = (const float*)d_in[7];
    const float* D_w       = (const float*)d_in[8];
    const float* dt_proj_w = (const float*)d_in[9];
    const float* dt_proj_b = (const float*)d_in[10];
    const float* A_log     = (const float*)d_in[11];
    const float* D_ss      = (const float*)d_in[12];
    const float* out_proj_w= (const float*)d_in[13];
    float* out = (float*)d_out;

    float *xz, *u, *dc;
    cudaGetSymbolAddress((void**)&xz, g_xz);
    cudaGetSymbolAddress((void**)&u,  g_u);
    cudaGetSymbolAddress((void**)&dc, g_dc);
    __nv_bfloat16 *hH,*hL,*catH,*catL,*opH,*opL,*dlH,*dlL;
    __nv_bfloat16 *w1H,*w1L,*iaH,*iaL,*idH,*idL,*cwH,*cwL,*btH,*btL,*hwH,*hwL,*wcH,*wcL,*woH,*woL,*dtH,*dtL;
    cudaGetSymbolAddress((void**)&hH,   g_h_hi);   cudaGetSymbolAddress((void**)&hL,   g_h_lo);
    cudaGetSymbolAddress((void**)&catH, g_cat_hi); cudaGetSymbolAddress((void**)&catL, g_cat_lo);
    cudaGetSymbolAddress((void**)&opH,  g_op_hi);  cudaGetSymbolAddress((void**)&opL,  g_op_lo);
    cudaGetSymbolAddress((void**)&dlH,  g_dl_hi);  cudaGetSymbolAddress((void**)&dlL,  g_dl_lo);
    cudaGetSymbolAddress((void**)&w1H,  g_w1_hi);  cudaGetSymbolAddress((void**)&w1L,  g_w1_lo);
    cudaGetSymbolAddress((void**)&iaH,  g_ia_hi);  cudaGetSymbolAddress((void**)&iaL,  g_ia_lo);
    cudaGetSymbolAddress((void**)&idH,  g_id_hi);  cudaGetSymbolAddress((void**)&idL,  g_id_lo);
    cudaGetSymbolAddress((void**)&cwH,  g_cw_hi);  cudaGetSymbolAddress((void**)&cwL,  g_cw_lo);
    cudaGetSymbolAddress((void**)&btH,  g_bt_hi);  cudaGetSymbolAddress((void**)&btL,  g_bt_lo);
    cudaGetSymbolAddress((void**)&hwH,  g_hw_hi);  cudaGetSymbolAddress((void**)&hwL,  g_hw_lo);
    cudaGetSymbolAddress((void**)&wcH,  g_wc_hi);  cudaGetSymbolAddress((void**)&wcL,  g_wc_lo);
    cudaGetSymbolAddress((void**)&woH,  g_wo_hi);  cudaGetSymbolAddress((void**)&woL,  g_wo_lo);
    cudaGetSymbolAddress((void**)&dtH,  g_dt_hi);  cudaGetSymbolAddress((void**)&dtL,  g_dt_lo);

    constexpr int SMEM = 96 * 1024;
    cudaFuncSetAttribute(gemm_bf16x3<0, false, true>, cudaFuncAttributeMaxDynamicSharedMemorySize, SMEM);
    cudaFuncSetAttribute(gemm_bf16x3<0, true, false>, cudaFuncAttributeMaxDynamicSharedMemorySize, SMEM);
    cudaFuncSetAttribute(gemm_bf16x3<3, false, true>, cudaFuncAttributeMaxDynamicSharedMemorySize, SMEM);

    auto split = [&](const float* s, __nv_bfloat16* hi_, __nv_bfloat16* lo_,
                     int rowlen, int ld, int colofs, size_t n) {
        int n4 = (int)(n / 4);
        split_strided_kernel<<<(n4 + 255) / 256, 256>>>(s, hi_, lo_, rowlen, ld, colofs, n4);
    };

    const int GY = M_ / 128;   // 64
    const dim3 gSeq(DI / 256, B_ * NCH);

    // ---- input / weight conversions ----
    split(h,         hH,  hL,  DM, DM, 0, (size_t)M_ * DM);
    split(in_proj_w, w1H, w1L, DM, DM, 0, (size_t)TWO_DI * DM);
    split(delta,     dlH, dlL, DTR, DTR, 0, (size_t)M_ * DTR);
    split(dt_proj_w, dtH, dtL, DTR, DTR, 0, (size_t)DI * DTR);
    split(C_w,       cwH, cwL, DI, DI, 0, (size_t)DI * DI);
    split(out_proj_w, woH, woL, DI, DI, 0, (size_t)DM * DI);
    split_eye_kernel<<<(DI * DI / 4) / 256, 256>>>(A_real, iaH, iaL);              // I + A
    split_eye_kernel<<<(DI * DI / 4) / 256, 256>>>(D_w,    idH, idL);              // I + D
    transpose_split_kernel<<<dim3(DI / 32, DI / 32), dim3(32, 8)>>>(B_w, btH, btL); // B_w^T

    // ---- weight folds (bf16x3 GEMMs on 2048^3) ----
    // T[e,k] = sum_p C_w[e,p] * B_w^T[k,p] = (C_w B_w)[e,k]
    gemm_bf16x3<0, true, false><<<dim3(DI / 128, DI / 128), 256, SMEM>>>(
        cwH, cwL, DI, 0, btH, btL, nullptr, hwH, hwL, DI, 0,
        nullptr, nullptr, DI, DI);
    // W2[e,s] = sum_k T[e,k] * (I+A)[s,k]   -> wc cols [0, DI)
    gemm_bf16x3<0, true, false><<<dim3(DI / 128, DI / 128), 256, SMEM>>>(
        hwH, hwL, DI, 0, iaH, iaL, nullptr, wcH, wcL, TWO_DI, 0,
        nullptr, nullptr, DI, DI);
    // G[e,s] = sum_k (I+D)[e,k] * (I+A)[s,k] -> wc cols [DI, 2*DI)
    gemm_bf16x3<0, true, false><<<dim3(DI / 128, DI / 128), 256, SMEM>>>(
        idH, idL, DI, 0, iaH, iaL, nullptr, wcH, wcL, TWO_DI, DI,
        nullptr, nullptr, DI, DI);

    // ---- main sequence ----
    // xz = h @ in_proj_w^T   [8192, 4096]
    gemm_bf16x3<0, false, true><<<dim3(TWO_DI / 128, GY), 256, SMEM>>>(
        hH, hL, DM, 0, w1H, w1L, xz, nullptr, nullptr, 0, 0,
        nullptr, nullptr, TWO_DI, DM);

    // conv + SiLU -> x splits in cat cols [DI, 2*DI)
    conv_silu_kernel<<<(M_ * DI) / 256, 256>>>(conv_w, conv_b);

    // cx = cumsum_L(x) -> cat cols [0, DI)
    cumsum_p1<<<gSeq, 256>>>();
    cumsum_p2<<<(B_ * DI) / 256, 256>>>();
    cumsum_p3<<<gSeq, 256>>>();

    // u = [cx|x] @ [W2|G]^T   (K = 4096)
    gemm_bf16x3<0, false, true><<<dim3(DI / 128, GY), 256, SMEM>>>(
        catH, catL, TWO_DI, 0, wcH, wcL, u, nullptr, nullptr, 0, 0,
        nullptr, nullptr, DI, TWO_DI);

    // decay = exp(-exp(A_log) * softplus(delta @ dt_proj_w^T + b))  (K = 64)
    gemm_bf16x3<3, false, true><<<dim3(DI / 128, GY), 256, SMEM>>>(
        dlH, dlL, DTR, 0, dtH, dtL, dc, nullptr, nullptr, 0, 0,
        dt_proj_b, A_log, DI, DTR);

    // scan; pass3 fuses (+ u*D_ss) * silu(z) -> op splits
    scan_p1<<<gSeq, 256>>>();
    scan_p2<<<(B_ * DI) / 256, 256>>>();
    scan_p3<<<gSeq, 256>>>(D_ss);

    // out = out_pre @ out_proj_w^T  [8192, 1024]
    gemm_bf16x3<0, false, true><<<dim3(DM / 128, GY), 256, SMEM>>>(
        opH, opL, DI, 0, woH, woL, out, nullptr, nullptr, 0, 0,
        nullptr, nullptr, DM, DI);
}

// round 7
// speedup vs baseline: 4.2252x; 1.0495x over previous
#include <cuda_runtime.h>
#include <cuda_bf16.h>
#include <math.h>
#include <stdint.h>

// ---------------------------------------------------------------------------
// Mamba3Block on GB300 — round 7: fork-join stream overlap of weight-prep
// (splits/folds/dt-GEMM) with the main data chain. Algebra as round 6:
//   W2 = C_w B_w (I+A)^T ; G = (I+D)(I+A)^T ; cx = cumsum_L(x)
//   u  = [cx | x] @ [W2 | G]^T
// ---------------------------------------------------------------------------

namespace {
constexpr int B_   = 2;
constexpr int L_   = 4096;
constexpr int DM   = 1024;
constexpr int DI   = 2048;
constexpr int M_   = B_ * L_;        // 8192
constexpr int NCH  = 64;
constexpr int CH   = L_ / NCH;       // 64
constexpr int TWO_DI = 2 * DI;       // 4096
constexpr int DTR  = 64;
}

// ------------------------- fp32 scratch ------------------------------------
__device__ float g_xz[(size_t)M_ * TWO_DI];
__device__ float g_u [(size_t)M_ * DI];
__device__ float g_dc[(size_t)M_ * DI];
__device__ float g_p1[B_ * NCH * DI];
__device__ float g_p2[B_ * NCH * DI];
__device__ float g_p3[B_ * NCH * DI];
__device__ float g_cr[B_ * NCH * DI];

// ------------------------- bf16 split scratch ------------------------------
__device__ __nv_bfloat16 g_h_hi [(size_t)M_ * DM],   g_h_lo [(size_t)M_ * DM];
__device__ __nv_bfloat16 g_cat_hi[(size_t)M_ * TWO_DI], g_cat_lo[(size_t)M_ * TWO_DI]; // [cx|x]
__device__ __nv_bfloat16 g_op_hi[(size_t)M_ * DI],   g_op_lo[(size_t)M_ * DI];
__device__ __nv_bfloat16 g_dl_hi[(size_t)M_ * DTR],  g_dl_lo[(size_t)M_ * DTR];
__device__ __nv_bfloat16 g_w1_hi[(size_t)TWO_DI * DM], g_w1_lo[(size_t)TWO_DI * DM];
__device__ __nv_bfloat16 g_ia_hi[(size_t)DI * DI],   g_ia_lo[(size_t)DI * DI];   // I + A_real
__device__ __nv_bfloat16 g_id_hi[(size_t)DI * DI],   g_id_lo[(size_t)DI * DI];   // I + D_w
__device__ __nv_bfloat16 g_cw_hi[(size_t)DI * DI],   g_cw_lo[(size_t)DI * DI];   // C_w
__device__ __nv_bfloat16 g_bt_hi[(size_t)DI * DI],   g_bt_lo[(size_t)DI * DI];   // B_w^T
__device__ __nv_bfloat16 g_hw_hi[(size_t)DI * DI],   g_hw_lo[(size_t)DI * DI];   // T = C_w B_w
__device__ __nv_bfloat16 g_wc_hi[(size_t)DI * TWO_DI], g_wc_lo[(size_t)DI * TWO_DI];  // [W2 | G]
__device__ __nv_bfloat16 g_wo_hi[(size_t)DM * DI],   g_wo_lo[(size_t)DM * DI];
__device__ __nv_bfloat16 g_dt_hi[(size_t)DI * DTR],  g_dt_lo[(size_t)DI * DTR];

__device__ __forceinline__ float siluf(float v) { return v / (1.f + expf(-v)); }

__device__ __forceinline__ void split1(float v, __nv_bfloat16& h, __nv_bfloat16& l) {
    h = __float2bfloat16(v);
    l = __float2bfloat16(v - __bfloat162float(h));
}

// --------------------------- PTX helpers ------------------------------------
__device__ __forceinline__ uint32_t cvta_smem(const void* p) {
    uint32_t a;
    asm("{ .reg .u64 t; cvta.to.shared.u64 t, %1; cvt.u32.u64 %0, t; }" : "=r"(a) : "l"(p));
    return a;
}
__device__ __forceinline__ void cp16(uint32_t dst, const void* src) {
    asm volatile("cp.async.cg.shared.global [%0], [%1], 16;" :: "r"(dst), "l"(src) : "memory");
}
__device__ __forceinline__ void cp_commit() {
    asm volatile("cp.async.commit_group;" ::: "memory");
}
template<int N>
__device__ __forceinline__ void cp_wait() {
    asm volatile("cp.async.wait_group %0;" :: "n"(N) : "memory");
}
__device__ __forceinline__ void ldsm4(uint32_t* r, uint32_t addr) {
    asm volatile("ldmatrix.sync.aligned.m8n8.x4.shared.b16 {%0,%1,%2,%3}, [%4];"
                 : "=r"(r[0]), "=r"(r[1]), "=r"(r[2]), "=r"(r[3]) : "r"(addr));
}
__device__ __forceinline__ void mma_bf16(float* d, const uint32_t* a, uint32_t b0, uint32_t b1) {
    asm volatile(
        "mma.sync.aligned.m16n8k16.row.col.f32.bf16.bf16.f32 "
        "{%0,%1,%2,%3}, {%4,%5,%6,%7}, {%8,%9}, {%0,%1,%2,%3};"
        : "+f"(d[0]), "+f"(d[1]), "+f"(d[2]), "+f"(d[3])
        : "r"(a[0]), "r"(a[1]), "r"(a[2]), "r"(a[3]), "r"(b0), "r"(b1));
}
#define SW128(o) ((o) ^ (((o) >> 3) & 0x70))

// =====================  mma.sync bf16x3 GEMM  ================================
// C[M,N] = fp32( (Ah+Al)[M,K] @ (Bh+Bl)[N,K]^T ), tile 128x128, BK=32, 3 stages.
// A rows read at (row*lda + abase + k). Smem rows: 128B = [32 hi | 32 lo], SW128.
// EPI: 0 none; 3 decay epilogue exp(-exp(v2)*softplus(acc+v1)).
// WC: write C fp32 [row*N+col]. WB: write bf16 hi/lo split at row*ldo+obase+col.
template<int EPI, bool WB, bool WC>
__global__ __launch_bounds__(256, 2)
void gemm_bf16x3(const __nv_bfloat16* __restrict__ Ah, const __nv_bfloat16* __restrict__ Al,
                 int lda, int abase,
                 const __nv_bfloat16* __restrict__ Bh, const __nv_bfloat16* __restrict__ Bl,
                 float* __restrict__ C,
                 __nv_bfloat16* __restrict__ Oh, __nv_bfloat16* __restrict__ Ol,
                 int ldo, int obase,
                 const float* __restrict__ v1, const float* __restrict__ v2,
                 int N, int K)
{
    constexpr int STAGE_BYTES = 32 * 1024;   // A 16K + B 16K
    extern __shared__ __align__(1024) char sm_raw[];

    const int tid = threadIdx.x;
    const int wid = tid >> 5;
    const int l   = tid & 31;
    const int wm  = wid >> 1;          // 0..3  (M)
    const int wn  = wid & 1;           // 0..1  (N)
    const int bm  = blockIdx.y * 128;
    const int bn  = blockIdx.x * 128;
    const uint32_t sb = cvta_smem(sm_raw);

    const int KT = K >> 5;             // BK = 32

    // ---- cp.async loader ----
    const int ldRow = tid >> 3;        // 0..31
    const int ldCh  = tid & 7;         // chunk within 128B row
    auto load_tile = [&](int kt, int st) {
        const uint32_t aBase = sb + st * STAGE_BYTES;
        const uint32_t bBase = aBase + 16 * 1024;
        const int kof = kt * 32 + (ldCh & 3) * 8;
        const bool lo = ldCh >= 4;
        #pragma unroll
        for (int i = 0; i < 4; i++) {
            const int r = ldRow + i * 32;
            const uint32_t so = SW128((uint32_t)(r * 128 + ldCh * 16));
            const size_t ga = (size_t)(bm + r) * lda + abase + kof;
            const size_t gb = (size_t)(bn + r) * K + kof;
            cp16(aBase + so, (lo ? Al : Ah) + ga);
            cp16(bBase + so, (lo ? Bl : Bh) + gb);
        }
        cp_commit();
    };

    // ---- ldmatrix lane addressing ----
    int aRow[2], aXr[2];
    #pragma unroll
    for (int mf = 0; mf < 2; mf++) {
        aRow[mf] = wm * 32 + mf * 16 + ((l >> 3) & 1) * 8 + (l & 7);
        aXr[mf]  = (aRow[mf] & 7) << 4;
    }
    const int aChunk = ((l >> 4) & 1) * 16;
    int bRow[4], bXr[4];
    #pragma unroll
    for (int p = 0; p < 4; p++) {
        bRow[p] = wn * 64 + p * 16 + ((l >> 4) & 1) * 8 + (l & 7);
        bXr[p]  = (bRow[p] & 7) << 4;
    }
    const int bChunk = ((l >> 3) & 1) * 16;

    float acc[2][8][4];
    #pragma unroll
    for (int mf = 0; mf < 2; mf++)
        #pragma unroll
        for (int nf = 0; nf < 8; nf++)
            #pragma unroll
            for (int k = 0; k < 4; k++) acc[mf][nf][k] = 0.f;

    // prologue: 2 stages in flight
    load_tile(0, 0);
    if (KT > 1) load_tile(1, 1);

    for (int kt = 0; kt < KT; kt++) {
        if (kt + 2 < KT) cp_wait<1>();
        else             cp_wait<0>();
        __syncthreads();
        if (kt + 2 < KT) load_tile(kt + 2, (kt + 2) % 3);

        const uint32_t aBase = sb + (uint32_t)(kt % 3) * STAGE_BYTES;
        const uint32_t bBase = aBase + 16 * 1024;

        #pragma unroll
        for (int s = 0; s < 2; s++) {
            uint32_t aH[2][4], aL[2][4];
            #pragma unroll
            for (int mf = 0; mf < 2; mf++) {
                ldsm4(aH[mf], aBase + aRow[mf] * 128 + (uint32_t)(((0 << 6) | (s << 5) | aChunk) ^ aXr[mf]));
                ldsm4(aL[mf], aBase + aRow[mf] * 128 + (uint32_t)(((1 << 6) | (s << 5) | aChunk) ^ aXr[mf]));
            }
            #pragma unroll
            for (int p = 0; p < 4; p++) {
                uint32_t rH[4], rL[4];
                ldsm4(rH, bBase + bRow[p] * 128 + (uint32_t)(((0 << 6) | (s << 5) | bChunk) ^ bXr[p]));
                ldsm4(rL, bBase + bRow[p] * 128 + (uint32_t)(((1 << 6) | (s << 5) | bChunk) ^ bXr[p]));
                #pragma unroll
                for (int mf = 0; mf < 2; mf++) {
                    mma_bf16(acc[mf][2 * p],     aH[mf], rH[0], rH[1]);
                    mma_bf16(acc[mf][2 * p + 1], aH[mf], rH[2], rH[3]);
                    mma_bf16(acc[mf][2 * p],     aH[mf], rL[0], rL[1]);
                    mma_bf16(acc[mf][2 * p + 1], aH[mf], rL[2], rL[3]);
                    mma_bf16(acc[mf][2 * p],     aL[mf], rH[0], rH[1]);
                    mma_bf16(acc[mf][2 * p + 1], aL[mf], rH[2], rH[3]);
                }
            }
        }
    }

    // ---- epilogue ----
    const int g   = l >> 2;
    const int tig = l & 3;
    #pragma unroll
    for (int mf = 0; mf < 2; mf++) {
        #pragma unroll
        for (int half = 0; half < 2; half++) {
            const int row = bm + wm * 32 + mf * 16 + g + half * 8;
            #pragma unroll
            for (int nf = 0; nf < 8; nf++) {
                const int col = bn + wn * 64 + nf * 8 + tig * 2;
                float vx = acc[mf][nf][2 * half + 0];
                float vy = acc[mf][nf][2 * half + 1];
                if constexpr (EPI == 3) {
                    float tx = vx + v1[col], ty = vy + v1[col + 1];
                    float sx = (tx > 20.f) ? tx : log1pf(expf(tx));
                    float sy = (ty > 20.f) ? ty : log1pf(expf(ty));
                    vx = expf(-expf(v2[col]) * sx);
                    vy = expf(-expf(v2[col + 1]) * sy);
                }
                if constexpr (WC) {
                    *reinterpret_cast<float2*>(C + (size_t)row * N + col) = make_float2(vx, vy);
                }
                if constexpr (WB) {
                    const size_t o = (size_t)row * ldo + obase + col;
                    __nv_bfloat162 hv = __float22bfloat162_rn(make_float2(vx, vy));
                    float2 hf = __bfloat1622float2(hv);
                    __nv_bfloat162 lv = __float22bfloat162_rn(make_float2(vx - hf.x, vy - hf.y));
                    *reinterpret_cast<__nv_bfloat162*>(Oh + o) = hv;
                    *reinterpret_cast<__nv_bfloat162*>(Ol + o) = lv;
                }
            }
        }
    }
}

// -------------------- fp32 -> bf16 hi/lo strided split ----------------------
__global__ void split_strided_kernel(const float* __restrict__ src,
                                     __nv_bfloat16* __restrict__ hi,
                                     __nv_bfloat16* __restrict__ lo,
                                     int rowlen, int ld, int colofs, int n4)
{
    int i = blockIdx.x * blockDim.x + threadIdx.x;
    if (i >= n4) return;
    float4 v = reinterpret_cast<const float4*>(src)[i];
    int e = i * 4;
    int row = e / rowlen;
    int col = e - row * rowlen;
    size_t o = (size_t)row * ld + colofs + col;
    __nv_bfloat162 h0 = __float22bfloat162_rn(make_float2(v.x, v.y));
    __nv_bfloat162 h1 = __float22bfloat162_rn(make_float2(v.z, v.w));
    float2 f0 = __bfloat1622float2(h0);
    float2 f1 = __bfloat1622float2(h1);
    __nv_bfloat162 l0 = __float22bfloat162_rn(make_float2(v.x - f0.x, v.y - f0.y));
    __nv_bfloat162 l1 = __float22bfloat162_rn(make_float2(v.z - f1.x, v.w - f1.y));
    *reinterpret_cast<__nv_bfloat162*>(hi + o)     = h0;
    *reinterpret_cast<__nv_bfloat162*>(hi + o + 2) = h1;
    *reinterpret_cast<__nv_bfloat162*>(lo + o)     = l0;
    *reinterpret_cast<__nv_bfloat162*>(lo + o + 2) = l1;
}

// -------------------- fp32 [DI x DI] + I -> bf16 hi/lo split ----------------
__global__ void split_eye_kernel(const float* __restrict__ src,
                                 __nv_bfloat16* __restrict__ hi,
                                 __nv_bfloat16* __restrict__ lo)
{
    int i = blockIdx.x * blockDim.x + threadIdx.x;   // float4 index
    if (i >= DI * DI / 4) return;
    float4 v = reinterpret_cast<const float4*>(src)[i];
    int e = i * 4;
    int row = e / DI;
    int col = e - row * DI;
    if (row == col)     v.x += 1.f;
    if (row == col + 1) v.y += 1.f;
    if (row == col + 2) v.z += 1.f;
    if (row == col + 3) v.w += 1.f;
    __nv_bfloat162 h0 = __float22bfloat162_rn(make_float2(v.x, v.y));
    __nv_bfloat162 h1 = __float22bfloat162_rn(make_float2(v.z, v.w));
    float2 f0 = __bfloat1622float2(h0);
    float2 f1 = __bfloat1622float2(h1);
    __nv_bfloat162 l0 = __float22bfloat162_rn(make_float2(v.x - f0.x, v.y - f0.y));
    __nv_bfloat162 l1 = __float22bfloat162_rn(make_float2(v.z - f1.x, v.w - f1.y));
    size_t o = (size_t)e;
    *reinterpret_cast<__nv_bfloat162*>(hi + o)     = h0;
    *reinterpret_cast<__nv_bfloat162*>(hi + o + 2) = h1;
    *reinterpret_cast<__nv_bfloat162*>(lo + o)     = l0;
    *reinterpret_cast<__nv_bfloat162*>(lo + o + 2) = l1;
}

// -------------------- transpose [DI x DI] + split ---------------------------
__global__ void transpose_split_kernel(const float* __restrict__ src,
                                       __nv_bfloat16* __restrict__ hi,
                                       __nv_bfloat16* __restrict__ lo)
{
    __shared__ float t[32][33];
    int x = blockIdx.x * 32 + threadIdx.x;
    int y = blockIdx.y * 32 + threadIdx.y;
    #pragma unroll
    for (int j = 0; j < 32; j += 8)
        t[threadIdx.y + j][threadIdx.x] = src[(size_t)(y + j) * DI + x];
    __syncthreads();
    int ox = blockIdx.y * 32 + threadIdx.x;
    int oy = blockIdx.x * 32 + threadIdx.y;
    #pragma unroll
    for (int j = 0; j < 32; j += 8) {
        float v = t[threadIdx.x][threadIdx.y + j];
        size_t o = (size_t)(oy + j) * DI + ox;
        split1(v, hi[o], lo[o]);
    }
}

// -------------------- conv + bias + SiLU -> cat cols [DI, 2*DI) -------------
__global__ void conv_silu_kernel(const float* __restrict__ w, const float* __restrict__ bias)
{
    int i = blockIdx.x * blockDim.x + threadIdx.x;
    if (i >= M_ * DI) return;
    int c  = i % DI;
    int l  = (i / DI) % L_;
    int bb = i / (DI * L_);
    const float* base = g_xz + (size_t)bb * L_ * TWO_DI + c;
    float acc = bias[c];
    #pragma unroll
    for (int k = 0; k < 4; k++) {
        int ll = l - 3 + k;
        if (ll >= 0) acc = fmaf(w[c * 4 + k], base[(size_t)ll * TWO_DI], acc);
    }
    float v = siluf(acc);
    size_t co = (size_t)(i / DI) * TWO_DI + DI + c;
    split1(v, g_cat_hi[co], g_cat_lo[co]);
}

// ------------------------ cumsum of x over L (3 passes) ----------------------
__global__ void cumsum_p1()
{
    int c   = blockIdx.x * blockDim.x + threadIdx.x;
    int seq = blockIdx.y;
    int bb = seq / NCH, ch = seq % NCH;
    size_t base = ((size_t)(bb * L_ + ch * CH)) * TWO_DI + DI + c;
    float s = 0.f;
    #pragma unroll 8
    for (int i = 0; i < CH; i++) {
        size_t o = base + (size_t)i * TWO_DI;
        s += __bfloat162float(g_cat_hi[o]) + __bfloat162float(g_cat_lo[o]);
    }
    g_p1[seq * DI + c] = s;
}
__global__ void cumsum_p2()
{
    int i = blockIdx.x * blockDim.x + threadIdx.x;
    if (i >= B_ * DI) return;
    int bb = i / DI, c = i % DI;
    float carry = 0.f;
    #pragma unroll
    for (int ch = 0; ch < NCH; ch++) {
        int idx = (bb * NCH + ch) * DI + c;
        g_cr[idx] = carry;
        carry += g_p1[idx];
    }
}
__global__ void cumsum_p3()
{
    int c   = blockIdx.x * blockDim.x + threadIdx.x;
    int seq = blockIdx.y;
    int bb = seq / NCH, ch = seq % NCH;
    size_t base = ((size_t)(bb * L_ + ch * CH)) * TWO_DI;
    float carry = g_cr[seq * DI + c];
    #pragma unroll 4
    for (int i = 0; i < CH; i++) {
        size_t ro = base + (size_t)i * TWO_DI;
        carry += __bfloat162float(g_cat_hi[ro + DI + c]) + __bfloat162float(g_cat_lo[ro + DI + c]);
        split1(carry, g_cat_hi[ro + c], g_cat_lo[ro + c]);
    }
}

// ----------------------- decay recurrence scan ------------------------------
__global__ void scan_p1()
{
    int c   = blockIdx.x * blockDim.x + threadIdx.x;
    int seq = blockIdx.y;
    int bb = seq / NCH, ch = seq % NCH;
    size_t base = ((size_t)(bb * L_ + ch * CH)) * DI + c;
    float P = 1.f, S = 0.f;
    #pragma unroll 8
    for (int i = 0; i < CH; i++) {
        size_t idx = base + (size_t)i * DI;
        float d = g_dc[idx];
        S = fmaf(d, S, g_u[idx]);
        P *= d;
    }
    g_p2[seq * DI + c] = P;
    g_p3[seq * DI + c] = S;
}
__global__ void scan_p2()
{
    int i = blockIdx.x * blockDim.x + threadIdx.x;
    if (i >= B_ * DI) return;
    int bb = i / DI, c = i % DI;
    float carry = 0.f;
    #pragma unroll
    for (int ch = 0; ch < NCH; ch++) {
        int idx = (bb * NCH + ch) * DI + c;
        g_cr[idx] = carry;
        carry = fmaf(g_p2[idx], carry, g_p3[idx]);
    }
}
__global__ void scan_p3(const float* __restrict__ D_ss)  // out_pre -> op splits
{
    int c   = blockIdx.x * blockDim.x + threadIdx.x;
    int seq = blockIdx.y;
    int bb = seq / NCH, ch = seq % NCH;
    int l0 = ch * CH;
    size_t base = ((size_t)(bb * L_ + l0)) * DI + c;
    float state = g_cr[seq * DI + c];
    float dss = D_ss[c];
    #pragma unroll 4
    for (int i = 0; i < CH; i++) {
        size_t idx = base + (size_t)i * DI;
        float u = g_u[idx];
        state = fmaf(g_dc[idx], state, u);
        float z = g_xz[(size_t)(bb * L_ + l0 + i) * TWO_DI + DI + c];
        float v = (state + u * dss) * siluf(z);
        split1(v, g_op_hi[idx], g_op_lo[idx]);
    }
}

// ------------------------------- launcher ----------------------------------
extern "C" void kernel_launch(void* const* d_in, const int* in_sizes, int n_in,
                              void* d_out, int out_size)
{
    const float* h         = (const float*)d_in[0];
    const float* delta     = (const float*)d_in[1];
    const float* in_proj_w = (const float*)d_in[2];
    const float* conv_w    = (const float*)d_in[3];
    const float* conv_b    = (const float*)d_in[4];
    const float* A_real    = (const float*)d_in[5];
    const float* B_w       = (const float*)d_in[6];
    const float* C_w       = (const float*)d_in[7];
    const float* D_w       = (const float*)d_in[8];
    const float* dt_proj_w = (const float*)d_in[9];
    const float* dt_proj_b = (const float*)d_in[10];
    const float* A_log     = (const float*)d_in[11];
    const float* D_ss      = (const float*)d_in[12];
    const float* out_proj_w= (const float*)d_in[13];
    float* out = (float*)d_out;

    float *xz, *u, *dc;
    cudaGetSymbolAddress((void**)&xz, g_xz);
    cudaGetSymbolAddress((void**)&u,  g_u);
    cudaGetSymbolAddress((void**)&dc, g_dc);
    __nv_bfloat16 *hH,*hL,*catH,*catL,*opH,*opL,*dlH,*dlL;
    __nv_bfloat16 *w1H,*w1L,*iaH,*iaL,*idH,*idL,*cwH,*cwL,*btH,*btL,*hwH,*hwL,*wcH,*wcL,*woH,*woL,*dtH,*dtL;
    cudaGetSymbolAddress((void**)&hH,   g_h_hi);   cudaGetSymbolAddress((void**)&hL,   g_h_lo);
    cudaGetSymbolAddress((void**)&catH, g_cat_hi); cudaGetSymbolAddress((void**)&catL, g_cat_lo);
    cudaGetSymbolAddress((void**)&opH,  g_op_hi);  cudaGetSymbolAddress((void**)&opL,  g_op_lo);
    cudaGetSymbolAddress((void**)&dlH,  g_dl_hi);  cudaGetSymbolAddress((void**)&dlL,  g_dl_lo);
    cudaGetSymbolAddress((void**)&w1H,  g_w1_hi);  cudaGetSymbolAddress((void**)&w1L,  g_w1_lo);
    cudaGetSymbolAddress((void**)&iaH,  g_ia_hi);  cudaGetSymbolAddress((void**)&iaL,  g_ia_lo);
    cudaGetSymbolAddress((void**)&idH,  g_id_hi);  cudaGetSymbolAddress((void**)&idL,  g_id_lo);
    cudaGetSymbolAddress((void**)&cwH,  g_cw_hi);  cudaGetSymbolAddress((void**)&cwL,  g_cw_lo);
    cudaGetSymbolAddress((void**)&btH,  g_bt_hi);  cudaGetSymbolAddress((void**)&btL,  g_bt_lo);
    cudaGetSymbolAddress((void**)&hwH,  g_hw_hi);  cudaGetSymbolAddress((void**)&hwL,  g_hw_lo);
    cudaGetSymbolAddress((void**)&wcH,  g_wc_hi);  cudaGetSymbolAddress((void**)&wcL,  g_wc_lo);
    cudaGetSymbolAddress((void**)&woH,  g_wo_hi);  cudaGetSymbolAddress((void**)&woL,  g_wo_lo);
    cudaGetSymbolAddress((void**)&dtH,  g_dt_hi);  cudaGetSymbolAddress((void**)&dtL,  g_dt_lo);

    constexpr int SMEM = 96 * 1024;
    cudaFuncSetAttribute(gemm_bf16x3<0, false, true>, cudaFuncAttributeMaxDynamicSharedMemorySize, SMEM);
    cudaFuncSetAttribute(gemm_bf16x3<0, true, false>, cudaFuncAttributeMaxDynamicSharedMemorySize, SMEM);
    cudaFuncSetAttribute(gemm_bf16x3<3, false, true>, cudaFuncAttributeMaxDynamicSharedMemorySize, SMEM);

    // ---- fork-join streams (created once; host-side only, no device alloc) ----
    static cudaStream_t s2 = nullptr;
    static cudaEvent_t  eF = nullptr, eJ = nullptr;
    if (s2 == nullptr) {
        cudaStreamCreateWithFlags(&s2, cudaStreamNonBlocking);
        cudaEventCreateWithFlags(&eF, cudaEventDisableTiming);
        cudaEventCreateWithFlags(&eJ, cudaEventDisableTiming);
    }

    auto splitOn = [&](cudaStream_t st, const float* s, __nv_bfloat16* hi_, __nv_bfloat16* lo_,
                       int rowlen, int ld, int colofs, size_t n) {
        int n4 = (int)(n / 4);
        split_strided_kernel<<<(n4 + 255) / 256, 256, 0, st>>>(s, hi_, lo_, rowlen, ld, colofs, n4);
    };

    const int GY = M_ / 128;   // 64
    const dim3 gSeq(DI / 256, B_ * NCH);

    // fork: s2 handles all weight-prep independent of the main data chain
    cudaEventRecord(eF, 0);
    cudaStreamWaitEvent(s2, eF, 0);

    // main-stream inputs for the first big GEMM
    splitOn(0,  h,         hH,  hL,  DM, DM, 0, (size_t)M_ * DM);       // launch 0
    splitOn(0,  in_proj_w, w1H, w1L, DM, DM, 0, (size_t)TWO_DI * DM);   // launch 1
    splitOn(s2, delta,     dlH, dlL, DTR, DTR, 0, (size_t)M_ * DTR);    // launch 2
    splitOn(s2, dt_proj_w, dtH, dtL, DTR, DTR, 0, (size_t)DI * DTR);    // launch 3
    splitOn(s2, C_w,       cwH, cwL, DI, DI, 0, (size_t)DI * DI);       // launch 4

    // launch 5 (ncu capture slot): xz = h @ in_proj_w^T   [8192, 4096]
    gemm_bf16x3<0, false, true><<<dim3(TWO_DI / 128, GY), 256, SMEM>>>(
        hH, hL, DM, 0, w1H, w1L, xz, nullptr, nullptr, 0, 0,
        nullptr, nullptr, TWO_DI, DM);

    // ---- s2: rest of weight prep, folds, dt GEMM ----
    splitOn(s2, out_proj_w, woH, woL, DI, DI, 0, (size_t)DM * DI);
    split_eye_kernel<<<(DI * DI / 4) / 256, 256, 0, s2>>>(A_real, iaH, iaL);              // I + A
    split_eye_kernel<<<(DI * DI / 4) / 256, 256, 0, s2>>>(D_w,    idH, idL);              // I + D
    transpose_split_kernel<<<dim3(DI / 32, DI / 32), dim3(32, 8), 0, s2>>>(B_w, btH, btL); // B_w^T

    // T = C_w B_w
    gemm_bf16x3<0, true, false><<<dim3(DI / 128, DI / 128), 256, SMEM, s2>>>(
        cwH, cwL, DI, 0, btH, btL, nullptr, hwH, hwL, DI, 0,
        nullptr, nullptr, DI, DI);
    // W2 = T (I+A)^T -> wc cols [0, DI)
    gemm_bf16x3<0, true, false><<<dim3(DI / 128, DI / 128), 256, SMEM, s2>>>(
        hwH, hwL, DI, 0, iaH, iaL, nullptr, wcH, wcL, TWO_DI, 0,
        nullptr, nullptr, DI, DI);
    // G = (I+D)(I+A)^T -> wc cols [DI, 2*DI)
    gemm_bf16x3<0, true, false><<<dim3(DI / 128, DI / 128), 256, SMEM, s2>>>(
        idH, idL, DI, 0, iaH, iaL, nullptr, wcH, wcL, TWO_DI, DI,
        nullptr, nullptr, DI, DI);
    // decay = exp(-exp(A_log) * softplus(delta @ dt_proj_w^T + b))  (K = 64)
    gemm_bf16x3<3, false, true><<<dim3(DI / 128, GY), 256, SMEM, s2>>>(
        dlH, dlL, DTR, 0, dtH, dtL, dc, nullptr, nullptr, 0, 0,
        dt_proj_b, A_log, DI, DTR);
    cudaEventRecord(eJ, s2);

    // ---- main chain ----
    // conv + SiLU -> x splits in cat cols [DI, 2*DI)
    conv_silu_kernel<<<(M_ * DI) / 256, 256>>>(conv_w, conv_b);

    // cx = cumsum_L(x) -> cat cols [0, DI)
    cumsum_p1<<<gSeq, 256>>>();
    cumsum_p2<<<(B_ * DI) / 256, 256>>>();
    cumsum_p3<<<gSeq, 256>>>();

    // join: u GEMM needs [W2|G]; scan needs dc
    cudaStreamWaitEvent(0, eJ, 0);

    // u = [cx|x] @ [W2|G]^T   (K = 4096)
    gemm_bf16x3<0, false, true><<<dim3(DI / 128, GY), 256, SMEM>>>(
        catH, catL, TWO_DI, 0, wcH, wcL, u, nullptr, nullptr, 0, 0,
        nullptr, nullptr, DI, TWO_DI);

    // scan; pass3 fuses (+ u*D_ss) * silu(z) -> op splits
    scan_p1<<<gSeq, 256>>>();
    scan_p2<<<(B_ * DI) / 256, 256>>>();
    scan_p3<<<gSeq, 256>>>(D_ss);

    // out = out_pre @ out_proj_w^T  [8192, 1024]
    gemm_bf16x3<0, false, true><<<dim3(DM / 128, GY), 256, SMEM>>>(
        opH, opL, DI, 0, woH, woL, out, nullptr, nullptr, 0, 0,
        nullptr, nullptr, DM, DI);
}

// round 8
// speedup vs baseline: 4.2291x; 1.0009x over previous
#include <cuda_runtime.h>
#include <cuda_bf16.h>
#include <math.h>
#include <stdint.h>

// ---------------------------------------------------------------------------
// Mamba3Block on GB300 — round 8: cumsum commuted past the GEMM.
//   y = x @ [W2 | G]^T  (K=2048, starts right after conv)
//   u = cumsum_L(y_left) + y_right, fused with the decay scan (3 passes).
//   W2 = C_w B_w (I+A)^T ; G = (I+D)(I+A)^T  (folded on side stream)
// ---------------------------------------------------------------------------

namespace {
constexpr int B_   = 2;
constexpr int L_   = 4096;
constexpr int DM   = 1024;
constexpr int DI   = 2048;
constexpr int M_   = B_ * L_;        // 8192
constexpr int NCH  = 64;
constexpr int CH   = L_ / NCH;       // 64
constexpr int TWO_DI = 2 * DI;       // 4096
constexpr int DTR  = 64;
}

// ------------------------- fp32 scratch ------------------------------------
__device__ float g_xz[(size_t)M_ * TWO_DI];
__device__ float g_y [(size_t)M_ * TWO_DI];   // [yl | yr]
__device__ float g_dc[(size_t)M_ * DI];
__device__ float g_sy[B_ * NCH * DI];
__device__ float g_pp[B_ * NCH * DI];
__device__ float g_qq[B_ * NCH * DI];
__device__ float g_ss[B_ * NCH * DI];
__device__ float g_cxin[B_ * NCH * DI];
__device__ float g_stin[B_ * NCH * DI];

// ------------------------- bf16 split scratch ------------------------------
__device__ __nv_bfloat16 g_h_hi [(size_t)M_ * DM],   g_h_lo [(size_t)M_ * DM];
__device__ __nv_bfloat16 g_x_hi [(size_t)M_ * DI],   g_x_lo [(size_t)M_ * DI];
__device__ __nv_bfloat16 g_op_hi[(size_t)M_ * DI],   g_op_lo[(size_t)M_ * DI];
__device__ __nv_bfloat16 g_dl_hi[(size_t)M_ * DTR],  g_dl_lo[(size_t)M_ * DTR];
__device__ __nv_bfloat16 g_w1_hi[(size_t)TWO_DI * DM], g_w1_lo[(size_t)TWO_DI * DM];
__device__ __nv_bfloat16 g_ia_hi[(size_t)DI * DI],   g_ia_lo[(size_t)DI * DI];   // I + A_real
__device__ __nv_bfloat16 g_id_hi[(size_t)DI * DI],   g_id_lo[(size_t)DI * DI];   // I + D_w
__device__ __nv_bfloat16 g_cw_hi[(size_t)DI * DI],   g_cw_lo[(size_t)DI * DI];   // C_w
__device__ __nv_bfloat16 g_bt_hi[(size_t)DI * DI],   g_bt_lo[(size_t)DI * DI];   // B_w^T
__device__ __nv_bfloat16 g_tt_hi[(size_t)DI * DI],   g_tt_lo[(size_t)DI * DI];   // T = C_w B_w
__device__ __nv_bfloat16 g_wc_hi[(size_t)TWO_DI * DI], g_wc_lo[(size_t)TWO_DI * DI]; // rows: [W2 ; G]
__device__ __nv_bfloat16 g_wo_hi[(size_t)DM * DI],   g_wo_lo[(size_t)DM * DI];
__device__ __nv_bfloat16 g_dt_hi[(size_t)DI * DTR],  g_dt_lo[(size_t)DI * DTR];

__device__ __forceinline__ float siluf(float v) { return v / (1.f + expf(-v)); }

__device__ __forceinline__ void split1(float v, __nv_bfloat16& h, __nv_bfloat16& l) {
    h = __float2bfloat16(v);
    l = __float2bfloat16(v - __bfloat162float(h));
}

// --------------------------- PTX helpers ------------------------------------
__device__ __forceinline__ uint32_t cvta_smem(const void* p) {
    uint32_t a;
    asm("{ .reg .u64 t; cvta.to.shared.u64 t, %1; cvt.u32.u64 %0, t; }" : "=r"(a) : "l"(p));
    return a;
}
__device__ __forceinline__ void cp16(uint32_t dst, const void* src) {
    asm volatile("cp.async.cg.shared.global [%0], [%1], 16;" :: "r"(dst), "l"(src) : "memory");
}
__device__ __forceinline__ void cp_commit() {
    asm volatile("cp.async.commit_group;" ::: "memory");
}
template<int N>
__device__ __forceinline__ void cp_wait() {
    asm volatile("cp.async.wait_group %0;" :: "n"(N) : "memory");
}
__device__ __forceinline__ void ldsm4(uint32_t* r, uint32_t addr) {
    asm volatile("ldmatrix.sync.aligned.m8n8.x4.shared.b16 {%0,%1,%2,%3}, [%4];"
                 : "=r"(r[0]), "=r"(r[1]), "=r"(r[2]), "=r"(r[3]) : "r"(addr));
}
__device__ __forceinline__ void mma_bf16(float* d, const uint32_t* a, uint32_t b0, uint32_t b1) {
    asm volatile(
        "mma.sync.aligned.m16n8k16.row.col.f32.bf16.bf16.f32 "
        "{%0,%1,%2,%3}, {%4,%5,%6,%7}, {%8,%9}, {%0,%1,%2,%3};"
        : "+f"(d[0]), "+f"(d[1]), "+f"(d[2]), "+f"(d[3])
        : "r"(a[0]), "r"(a[1]), "r"(a[2]), "r"(a[3]), "r"(b0), "r"(b1));
}
#define SW128(o) ((o) ^ (((o) >> 3) & 0x70))

// =====================  mma.sync bf16x3 GEMM  ================================
// C[M,N] = fp32( (Ah+Al)[M,K] @ (Bh+Bl)[N,K]^T ), tile 128x128, BK=32, 3 stages.
// A rows read at (row*lda + abase + k). Smem rows: 128B = [32 hi | 32 lo], SW128.
// EPI: 0 none; 3 decay epilogue exp(-exp(v2)*softplus(acc+v1)).
// WC: write C fp32 [row*N+col]. WB: write bf16 hi/lo split at row*ldo+obase+col.
template<int EPI, bool WB, bool WC>
__global__ __launch_bounds__(256, 2)
void gemm_bf16x3(const __nv_bfloat16* __restrict__ Ah, const __nv_bfloat16* __restrict__ Al,
                 int lda, int abase,
                 const __nv_bfloat16* __restrict__ Bh, const __nv_bfloat16* __restrict__ Bl,
                 float* __restrict__ C,
                 __nv_bfloat16* __restrict__ Oh, __nv_bfloat16* __restrict__ Ol,
                 int ldo, int obase,
                 const float* __restrict__ v1, const float* __restrict__ v2,
                 int N, int K)
{
    constexpr int STAGE_BYTES = 32 * 1024;   // A 16K + B 16K
    extern __shared__ __align__(1024) char sm_raw[];

    const int tid = threadIdx.x;
    const int wid = tid >> 5;
    const int l   = tid & 31;
    const int wm  = wid >> 1;          // 0..3  (M)
    const int wn  = wid & 1;           // 0..1  (N)
    const int bm  = blockIdx.y * 128;
    const int bn  = blockIdx.x * 128;
    const uint32_t sb = cvta_smem(sm_raw);

    const int KT = K >> 5;             // BK = 32

    // ---- cp.async loader ----
    const int ldRow = tid >> 3;        // 0..31
    const int ldCh  = tid & 7;         // chunk within 128B row
    auto load_tile = [&](int kt, int st) {
        const uint32_t aBase = sb + st * STAGE_BYTES;
        const uint32_t bBase = aBase + 16 * 1024;
        const int kof = kt * 32 + (ldCh & 3) * 8;
        const bool lo = ldCh >= 4;
        #pragma unroll
        for (int i = 0; i < 4; i++) {
            const int r = ldRow + i * 32;
            const uint32_t so = SW128((uint32_t)(r * 128 + ldCh * 16));
            const size_t ga = (size_t)(bm + r) * lda + abase + kof;
            const size_t gb = (size_t)(bn + r) * K + kof;
            cp16(aBase + so, (lo ? Al : Ah) + ga);
            cp16(bBase + so, (lo ? Bl : Bh) + gb);
        }
        cp_commit();
    };

    // ---- ldmatrix lane addressing ----
    int aRow[2], aXr[2];
    #pragma unroll
    for (int mf = 0; mf < 2; mf++) {
        aRow[mf] = wm * 32 + mf * 16 + ((l >> 3) & 1) * 8 + (l & 7);
        aXr[mf]  = (aRow[mf] & 7) << 4;
    }
    const int aChunk = ((l >> 4) & 1) * 16;
    int bRow[4], bXr[4];
    #pragma unroll
    for (int p = 0; p < 4; p++) {
        bRow[p] = wn * 64 + p * 16 + ((l >> 4) & 1) * 8 + (l & 7);
        bXr[p]  = (bRow[p] & 7) << 4;
    }
    const int bChunk = ((l >> 3) & 1) * 16;

    float acc[2][8][4];
    #pragma unroll
    for (int mf = 0; mf < 2; mf++)
        #pragma unroll
        for (int nf = 0; nf < 8; nf++)
            #pragma unroll
            for (int k = 0; k < 4; k++) acc[mf][nf][k] = 0.f;

    load_tile(0, 0);
    if (KT > 1) load_tile(1, 1);

    for (int kt = 0; kt < KT; kt++) {
        if (kt + 2 < KT) cp_wait<1>();
        else             cp_wait<0>();
        __syncthreads();
        if (kt + 2 < KT) load_tile(kt + 2, (kt + 2) % 3);

        const uint32_t aBase = sb + (uint32_t)(kt % 3) * STAGE_BYTES;
        const uint32_t bBase = aBase + 16 * 1024;

        #pragma unroll
        for (int s = 0; s < 2; s++) {
            uint32_t aH[2][4], aL[2][4];
            #pragma unroll
            for (int mf = 0; mf < 2; mf++) {
                ldsm4(aH[mf], aBase + aRow[mf] * 128 + (uint32_t)(((0 << 6) | (s << 5) | aChunk) ^ aXr[mf]));
                ldsm4(aL[mf], aBase + aRow[mf] * 128 + (uint32_t)(((1 << 6) | (s << 5) | aChunk) ^ aXr[mf]));
            }
            #pragma unroll
            for (int p = 0; p < 4; p++) {
                uint32_t rH[4], rL[4];
                ldsm4(rH, bBase + bRow[p] * 128 + (uint32_t)(((0 << 6) | (s << 5) | bChunk) ^ bXr[p]));
                ldsm4(rL, bBase + bRow[p] * 128 + (uint32_t)(((1 << 6) | (s << 5) | bChunk) ^ bXr[p]));
                #pragma unroll
                for (int mf = 0; mf < 2; mf++) {
                    mma_bf16(acc[mf][2 * p],     aH[mf], rH[0], rH[1]);
                    mma_bf16(acc[mf][2 * p + 1], aH[mf], rH[2], rH[3]);
                    mma_bf16(acc[mf][2 * p],     aH[mf], rL[0], rL[1]);
                    mma_bf16(acc[mf][2 * p + 1], aH[mf], rL[2], rL[3]);
                    mma_bf16(acc[mf][2 * p],     aL[mf], rH[0], rH[1]);
                    mma_bf16(acc[mf][2 * p + 1], aL[mf], rH[2], rH[3]);
                }
            }
        }
    }

    // ---- epilogue ----
    const int g   = l >> 2;
    const int tig = l & 3;
    #pragma unroll
    for (int mf = 0; mf < 2; mf++) {
        #pragma unroll
        for (int half = 0; half < 2; half++) {
            const int row = bm + wm * 32 + mf * 16 + g + half * 8;
            #pragma unroll
            for (int nf = 0; nf < 8; nf++) {
                const int col = bn + wn * 64 + nf * 8 + tig * 2;
                float vx = acc[mf][nf][2 * half + 0];
                float vy = acc[mf][nf][2 * half + 1];
                if constexpr (EPI == 3) {
                    float tx = vx + v1[col], ty = vy + v1[col + 1];
                    float sx = (tx > 20.f) ? tx : log1pf(expf(tx));
                    float sy = (ty > 20.f) ? ty : log1pf(expf(ty));
                    vx = expf(-expf(v2[col]) * sx);
                    vy = expf(-expf(v2[col + 1]) * sy);
                }
                if constexpr (WC) {
                    *reinterpret_cast<float2*>(C + (size_t)row * N + col) = make_float2(vx, vy);
                }
                if constexpr (WB) {
                    const size_t o = (size_t)row * ldo + obase + col;
                    __nv_bfloat162 hv = __float22bfloat162_rn(make_float2(vx, vy));
                    float2 hf = __bfloat1622float2(hv);
                    __nv_bfloat162 lv = __float22bfloat162_rn(make_float2(vx - hf.x, vy - hf.y));
                    *reinterpret_cast<__nv_bfloat162*>(Oh + o) = hv;
                    *reinterpret_cast<__nv_bfloat162*>(Ol + o) = lv;
                }
            }
        }
    }
}

// -------------------- fp32 -> bf16 hi/lo strided split ----------------------
__global__ void split_strided_kernel(const float* __restrict__ src,
                                     __nv_bfloat16* __restrict__ hi,
                                     __nv_bfloat16* __restrict__ lo,
                                     int rowlen, int ld, int colofs, int n4)
{
    int i = blockIdx.x * blockDim.x + threadIdx.x;
    if (i >= n4) return;
    float4 v = reinterpret_cast<const float4*>(src)[i];
    int e = i * 4;
    int row = e / rowlen;
    int col = e - row * rowlen;
    size_t o = (size_t)row * ld + colofs + col;
    __nv_bfloat162 h0 = __float22bfloat162_rn(make_float2(v.x, v.y));
    __nv_bfloat162 h1 = __float22bfloat162_rn(make_float2(v.z, v.w));
    float2 f0 = __bfloat1622float2(h0);
    float2 f1 = __bfloat1622float2(h1);
    __nv_bfloat162 l0 = __float22bfloat162_rn(make_float2(v.x - f0.x, v.y - f0.y));
    __nv_bfloat162 l1 = __float22bfloat162_rn(make_float2(v.z - f1.x, v.w - f1.y));
    *reinterpret_cast<__nv_bfloat162*>(hi + o)     = h0;
    *reinterpret_cast<__nv_bfloat162*>(hi + o + 2) = h1;
    *reinterpret_cast<__nv_bfloat162*>(lo + o)     = l0;
    *reinterpret_cast<__nv_bfloat162*>(lo + o + 2) = l1;
}

// -------------------- fp32 [DI x DI] + I -> bf16 hi/lo split ----------------
__global__ void split_eye_kernel(const float* __restrict__ src,
                                 __nv_bfloat16* __restrict__ hi,
                                 __nv_bfloat16* __restrict__ lo)
{
    int i = blockIdx.x * blockDim.x + threadIdx.x;   // float4 index
    if (i >= DI * DI / 4) return;
    float4 v = reinterpret_cast<const float4*>(src)[i];
    int e = i * 4;
    int row = e / DI;
    int col = e - row * DI;
    if (row == col)     v.x += 1.f;
    if (row == col + 1) v.y += 1.f;
    if (row == col + 2) v.z += 1.f;
    if (row == col + 3) v.w += 1.f;
    __nv_bfloat162 h0 = __float22bfloat162_rn(make_float2(v.x, v.y));
    __nv_bfloat162 h1 = __float22bfloat162_rn(make_float2(v.z, v.w));
    float2 f0 = __bfloat1622float2(h0);
    float2 f1 = __bfloat1622float2(h1);
    __nv_bfloat162 l0 = __float22bfloat162_rn(make_float2(v.x - f0.x, v.y - f0.y));
    __nv_bfloat162 l1 = __float22bfloat162_rn(make_float2(v.z - f1.x, v.w - f1.y));
    size_t o = (size_t)e;
    *reinterpret_cast<__nv_bfloat162*>(hi + o)     = h0;
    *reinterpret_cast<__nv_bfloat162*>(hi + o + 2) = h1;
    *reinterpret_cast<__nv_bfloat162*>(lo + o)     = l0;
    *reinterpret_cast<__nv_bfloat162*>(lo + o + 2) = l1;
}

// -------------------- transpose [DI x DI] + split ---------------------------
__global__ void transpose_split_kernel(const float* __restrict__ src,
                                       __nv_bfloat16* __restrict__ hi,
                                       __nv_bfloat16* __restrict__ lo)
{
    __shared__ float t[32][33];
    int x = blockIdx.x * 32 + threadIdx.x;
    int y = blockIdx.y * 32 + threadIdx.y;
    #pragma unroll
    for (int j = 0; j < 32; j += 8)
        t[threadIdx.y + j][threadIdx.x] = src[(size_t)(y + j) * DI + x];
    __syncthreads();
    int ox = blockIdx.y * 32 + threadIdx.x;
    int oy = blockIdx.x * 32 + threadIdx.y;
    #pragma unroll
    for (int j = 0; j < 32; j += 8) {
        float v = t[threadIdx.x][threadIdx.y + j];
        size_t o = (size_t)(oy + j) * DI + ox;
        split1(v, hi[o], lo[o]);
    }
}

// -------------------- conv + bias + SiLU -> x splits ------------------------
__global__ void conv_silu_kernel(const float* __restrict__ w, const float* __restrict__ bias)
{
    int i = blockIdx.x * blockDim.x + threadIdx.x;
    if (i >= M_ * DI) return;
    int c  = i % DI;
    int l  = (i / DI) % L_;
    int bb = i / (DI * L_);
    const float* base = g_xz + (size_t)bb * L_ * TWO_DI + c;
    float acc = bias[c];
    #pragma unroll
    for (int k = 0; k < 4; k++) {
        int ll = l - 3 + k;
        if (ll >= 0) acc = fmaf(w[c * 4 + k], base[(size_t)ll * TWO_DI], acc);
    }
    float v = siluf(acc);
    split1(v, g_x_hi[i], g_x_lo[i]);
}

// ------------------ fused double-scan (cumsum + decay recurrence) -----------
// per channel c, per l: cx += yl; u = cx + yr; st = d*st + u
__global__ void fscan_p1()
{
    int c   = blockIdx.x * blockDim.x + threadIdx.x;
    int seq = blockIdx.y;
    int bb = seq / NCH, ch = seq % NCH;
    size_t ybase = ((size_t)(bb * L_ + ch * CH)) * TWO_DI + c;
    size_t dbase = ((size_t)(bb * L_ + ch * CH)) * DI + c;
    float cx = 0.f, s = 0.f, q = 0.f, P = 1.f;
    #pragma unroll 4
    for (int i = 0; i < CH; i++) {
        float yl = g_y[ybase + (size_t)i * TWO_DI];
        float yr = g_y[ybase + (size_t)i * TWO_DI + DI];
        float d  = g_dc[dbase + (size_t)i * DI];
        cx += yl;
        float u = cx + yr;
        s = fmaf(d, s, u);
        q = fmaf(d, q, 1.f);
        P *= d;
    }
    int idx = seq * DI + c;
    g_sy[idx] = cx; g_pp[idx] = P; g_qq[idx] = q; g_ss[idx] = s;
}
__global__ void fscan_p2()
{
    int i = blockIdx.x * blockDim.x + threadIdx.x;
    if (i >= B_ * DI) return;
    int bb = i / DI, c = i % DI;
    float cx = 0.f, st = 0.f;
    #pragma unroll
    for (int ch = 0; ch < NCH; ch++) {
        int idx = (bb * NCH + ch) * DI + c;
        g_cxin[idx] = cx;
        g_stin[idx] = st;
        st = fmaf(g_pp[idx], st, fmaf(g_qq[idx], cx, g_ss[idx]));
        cx += g_sy[idx];
    }
}
__global__ void fscan_p3(const float* __restrict__ D_ss)  // -> op splits
{
    int c   = blockIdx.x * blockDim.x + threadIdx.x;
    int seq = blockIdx.y;
    int bb = seq / NCH, ch = seq % NCH;
    int gl0 = bb * L_ + ch * CH;
    size_t ybase = (size_t)gl0 * TWO_DI + c;
    size_t dbase = (size_t)gl0 * DI + c;
    float cx = g_cxin[seq * DI + c];
    float st = g_stin[seq * DI + c];
    float dss = D_ss[c];
    #pragma unroll 4
    for (int i = 0; i < CH; i++) {
        float yl = g_y[ybase + (size_t)i * TWO_DI];
        float yr = g_y[ybase + (size_t)i * TWO_DI + DI];
        float d  = g_dc[dbase + (size_t)i * DI];
        cx += yl;
        float u = cx + yr;
        st = fmaf(d, st, u);
        float z = g_xz[(size_t)(gl0 + i) * TWO_DI + DI + c];
        float v = (st + u * dss) * siluf(z);
        size_t oo = dbase + (size_t)i * DI;
        split1(v, g_op_hi[oo], g_op_lo[oo]);
    }
}

// ------------------------------- launcher ----------------------------------
extern "C" void kernel_launch(void* const* d_in, const int* in_sizes, int n_in,
                              void* d_out, int out_size)
{
    const float* h         = (const float*)d_in[0];
    const float* delta     = (const float*)d_in[1];
    const float* in_proj_w = (const float*)d_in[2];
    const float* conv_w    = (const float*)d_in[3];
    const float* conv_b    = (const float*)d_in[4];
    const float* A_real    = (const float*)d_in[5];
    const float* B_w       = (const float*)d_in[6];
    const float* C_w       = (const float*)d_in[7];
    const float* D_w       = (const float*)d_in[8];
    const float* dt_proj_w = (const float*)d_in[9];
    const float* dt_proj_b = (const float*)d_in[10];
    const float* A_log     = (const float*)d_in[11];
    const float* D_ss      = (const float*)d_in[12];
    const float* out_proj_w= (const float*)d_in[13];
    float* out = (float*)d_out;

    float *xz, *y, *dc;
    cudaGetSymbolAddress((void**)&xz, g_xz);
    cudaGetSymbolAddress((void**)&y,  g_y);
    cudaGetSymbolAddress((void**)&dc, g_dc);
    __nv_bfloat16 *hH,*hL,*xH,*xL,*opH,*opL,*dlH,*dlL;
    __nv_bfloat16 *w1H,*w1L,*iaH,*iaL,*idH,*idL,*cwH,*cwL,*btH,*btL,*ttH,*ttL,*wcH,*wcL,*woH,*woL,*dtH,*dtL;
    cudaGetSymbolAddress((void**)&hH,  g_h_hi);  cudaGetSymbolAddress((void**)&hL,  g_h_lo);
    cudaGetSymbolAddress((void**)&xH,  g_x_hi);  cudaGetSymbolAddress((void**)&xL,  g_x_lo);
    cudaGetSymbolAddress((void**)&opH, g_op_hi); cudaGetSymbolAddress((void**)&opL, g_op_lo);
    cudaGetSymbolAddress((void**)&dlH, g_dl_hi); cudaGetSymbolAddress((void**)&dlL, g_dl_lo);
    cudaGetSymbolAddress((void**)&w1H, g_w1_hi); cudaGetSymbolAddress((void**)&w1L, g_w1_lo);
    cudaGetSymbolAddress((void**)&iaH, g_ia_hi); cudaGetSymbolAddress((void**)&iaL, g_ia_lo);
    cudaGetSymbolAddress((void**)&idH, g_id_hi); cudaGetSymbolAddress((void**)&idL, g_id_lo);
    cudaGetSymbolAddress((void**)&cwH, g_cw_hi); cudaGetSymbolAddress((void**)&cwL, g_cw_lo);
    cudaGetSymbolAddress((void**)&btH, g_bt_hi); cudaGetSymbolAddress((void**)&btL, g_bt_lo);
    cudaGetSymbolAddress((void**)&ttH, g_tt_hi); cudaGetSymbolAddress((void**)&ttL, g_tt_lo);
    cudaGetSymbolAddress((void**)&wcH, g_wc_hi); cudaGetSymbolAddress((void**)&wcL, g_wc_lo);
    cudaGetSymbolAddress((void**)&woH, g_wo_hi); cudaGetSymbolAddress((void**)&woL, g_wo_lo);
    cudaGetSymbolAddress((void**)&dtH, g_dt_hi); cudaGetSymbolAddress((void**)&dtL, g_dt_lo);

    constexpr int SMEM = 96 * 1024;
    cudaFuncSetAttribute(gemm_bf16x3<0, false, true>, cudaFuncAttributeMaxDynamicSharedMemorySize, SMEM);
    cudaFuncSetAttribute(gemm_bf16x3<0, true, false>, cudaFuncAttributeMaxDynamicSharedMemorySize, SMEM);
    cudaFuncSetAttribute(gemm_bf16x3<3, false, true>, cudaFuncAttributeMaxDynamicSharedMemorySize, SMEM);

    // ---- fork-join streams (created once; host-side only) ----
    static cudaStream_t s2 = nullptr;
    static cudaEvent_t  eF = nullptr, eJ = nullptr;
    if (s2 == nullptr) {
        cudaStreamCreateWithFlags(&s2, cudaStreamNonBlocking);
        cudaEventCreateWithFlags(&eF, cudaEventDisableTiming);
        cudaEventCreateWithFlags(&eJ, cudaEventDisableTiming);
    }

    auto splitOn = [&](cudaStream_t st, const float* s, __nv_bfloat16* hi_, __nv_bfloat16* lo_,
                       int rowlen, int ld, int colofs, size_t n) {
        int n4 = (int)(n / 4);
        split_strided_kernel<<<(n4 + 255) / 256, 256, 0, st>>>(s, hi_, lo_, rowlen, ld, colofs, n4);
    };

    const int GY = M_ / 128;   // 64
    const dim3 gSeq(DI / 256, B_ * NCH);

    // fork: s2 handles all weight prep
    cudaEventRecord(eF, 0);
    cudaStreamWaitEvent(s2, eF, 0);

    // main-stream inputs for the first big GEMM
    splitOn(0, h,         hH,  hL,  DM, DM, 0, (size_t)M_ * DM);
    splitOn(0, in_proj_w, w1H, w1L, DM, DM, 0, (size_t)TWO_DI * DM);

    // xz = h @ in_proj_w^T   [8192, 4096]
    gemm_bf16x3<0, false, true><<<dim3(TWO_DI / 128, GY), 256, SMEM>>>(
        hH, hL, DM, 0, w1H, w1L, xz, nullptr, nullptr, 0, 0,
        nullptr, nullptr, TWO_DI, DM);

    // ---- s2: weight prep, folds, dt GEMM ----
    splitOn(s2, delta,      dlH, dlL, DTR, DTR, 0, (size_t)M_ * DTR);
    splitOn(s2, dt_proj_w,  dtH, dtL, DTR, DTR, 0, (size_t)DI * DTR);
    splitOn(s2, C_w,        cwH, cwL, DI, DI, 0, (size_t)DI * DI);
    splitOn(s2, out_proj_w, woH, woL, DI, DI, 0, (size_t)DM * DI);
    split_eye_kernel<<<(DI * DI / 4) / 256, 256, 0, s2>>>(A_real, iaH, iaL);               // I + A
    split_eye_kernel<<<(DI * DI / 4) / 256, 256, 0, s2>>>(D_w,    idH, idL);               // I + D
    transpose_split_kernel<<<dim3(DI / 32, DI / 32), dim3(32, 8), 0, s2>>>(B_w, btH, btL); // B_w^T

    // T = C_w B_w
    gemm_bf16x3<0, true, false><<<dim3(DI / 128, DI / 128), 256, SMEM, s2>>>(
        cwH, cwL, DI, 0, btH, btL, nullptr, ttH, ttL, DI, 0,
        nullptr, nullptr, DI, DI);
    // W2 = T (I+A)^T -> wc rows [0, DI)
    gemm_bf16x3<0, true, false><<<dim3(DI / 128, DI / 128), 256, SMEM, s2>>>(
        ttH, ttL, DI, 0, iaH, iaL, nullptr, wcH, wcL, DI, 0,
        nullptr, nullptr, DI, DI);
    // G = (I+D)(I+A)^T -> wc rows [DI, 2*DI)  (obase = DI*DI elements)
    gemm_bf16x3<0, true, false><<<dim3(DI / 128, DI / 128), 256, SMEM, s2>>>(
        idH, idL, DI, 0, iaH, iaL, nullptr, wcH, wcL, DI, DI * DI,
        nullptr, nullptr, DI, DI);
    // decay = exp(-exp(A_log) * softplus(delta @ dt_proj_w^T + b))  (K = 64)
    gemm_bf16x3<3, false, true><<<dim3(DI / 128, GY), 256, SMEM, s2>>>(
        dlH, dlL, DTR, 0, dtH, dtL, dc, nullptr, nullptr, 0, 0,
        dt_proj_b, A_log, DI, DTR);
    cudaEventRecord(eJ, s2);

    // ---- main chain ----
    // conv + SiLU -> x splits
    conv_silu_kernel<<<(M_ * DI) / 256, 256>>>(conv_w, conv_b);

    // join: y GEMM needs [W2;G]; fscan needs dc
    cudaStreamWaitEvent(0, eJ, 0);

    // y = x @ [W2 ; G]^T   (N = 4096, K = 2048)
    gemm_bf16x3<0, false, true><<<dim3(TWO_DI / 128, GY), 256, SMEM>>>(
        xH, xL, DI, 0, wcH, wcL, y, nullptr, nullptr, 0, 0,
        nullptr, nullptr, TWO_DI, DI);

    // fused double-scan; pass3 fuses (+ u*D_ss) * silu(z) -> op splits
    fscan_p1<<<gSeq, 256>>>();
    fscan_p2<<<(B_ * DI + 255) / 256, 256>>>();
    fscan_p3<<<gSeq, 256>>>(D_ss);

    // out = out_pre @ out_proj_w^T  [8192, 1024]
    gemm_bf16x3<0, false, true><<<dim3(DM / 128, GY), 256, SMEM>>>(
        opH, opL, DI, 0, woH, woL, out, nullptr, nullptr, 0, 0,
        nullptr, nullptr, DM, DI);
}

// round 9
// speedup vs baseline: 4.2606x; 1.0074x over previous
#include <cuda_runtime.h>
#include <cuda_bf16.h>
#include <math.h>
#include <stdint.h>

// ---------------------------------------------------------------------------
// Mamba3Block on GB300 — round 9: z-projection moved off the critical path.
//   main: x = h@Wx^T -> conv -> y = x@[W2;G]^T -> fused scan -> out
//   s2:   W2 = (C_w B_w)(I+A)^T
//   s3:   G = (I+D)(I+A)^T ; z = h@Wz^T ; decay GEMM ; out_proj split
// ---------------------------------------------------------------------------

namespace {
constexpr int B_   = 2;
constexpr int L_   = 4096;
constexpr int DM   = 1024;
constexpr int DI   = 2048;
constexpr int M_   = B_ * L_;        // 8192
constexpr int NCH  = 64;
constexpr int CH   = L_ / NCH;       // 64
constexpr int TWO_DI = 2 * DI;       // 4096
constexpr int DTR  = 64;
}

// ------------------------- fp32 scratch ------------------------------------
__device__ float g_xw[(size_t)M_ * DI];       // in_proj x-half (pre-conv)
__device__ float g_z [(size_t)M_ * DI];       // in_proj z-half
__device__ float g_y [(size_t)M_ * TWO_DI];   // [yl | yr]
__device__ float g_dc[(size_t)M_ * DI];
__device__ float g_sy[B_ * NCH * DI];
__device__ float g_pp[B_ * NCH * DI];
__device__ float g_qq[B_ * NCH * DI];
__device__ float g_ss[B_ * NCH * DI];
__device__ float g_cxin[B_ * NCH * DI];
__device__ float g_stin[B_ * NCH * DI];

// ------------------------- bf16 split scratch ------------------------------
__device__ __nv_bfloat16 g_h_hi [(size_t)M_ * DM],   g_h_lo [(size_t)M_ * DM];
__device__ __nv_bfloat16 g_x_hi [(size_t)M_ * DI],   g_x_lo [(size_t)M_ * DI];
__device__ __nv_bfloat16 g_op_hi[(size_t)M_ * DI],   g_op_lo[(size_t)M_ * DI];
__device__ __nv_bfloat16 g_dl_hi[(size_t)M_ * DTR],  g_dl_lo[(size_t)M_ * DTR];
__device__ __nv_bfloat16 g_w1_hi[(size_t)TWO_DI * DM], g_w1_lo[(size_t)TWO_DI * DM];
__device__ __nv_bfloat16 g_ia_hi[(size_t)DI * DI],   g_ia_lo[(size_t)DI * DI];   // I + A_real
__device__ __nv_bfloat16 g_id_hi[(size_t)DI * DI],   g_id_lo[(size_t)DI * DI];   // I + D_w
__device__ __nv_bfloat16 g_cw_hi[(size_t)DI * DI],   g_cw_lo[(size_t)DI * DI];   // C_w
__device__ __nv_bfloat16 g_bt_hi[(size_t)DI * DI],   g_bt_lo[(size_t)DI * DI];   // B_w^T
__device__ __nv_bfloat16 g_tt_hi[(size_t)DI * DI],   g_tt_lo[(size_t)DI * DI];   // T = C_w B_w
__device__ __nv_bfloat16 g_wc_hi[(size_t)TWO_DI * DI], g_wc_lo[(size_t)TWO_DI * DI]; // rows: [W2 ; G]
__device__ __nv_bfloat16 g_wo_hi[(size_t)DM * DI],   g_wo_lo[(size_t)DM * DI];
__device__ __nv_bfloat16 g_dt_hi[(size_t)DI * DTR],  g_dt_lo[(size_t)DI * DTR];

__device__ __forceinline__ float siluf(float v) { return v / (1.f + expf(-v)); }

__device__ __forceinline__ void split1(float v, __nv_bfloat16& h, __nv_bfloat16& l) {
    h = __float2bfloat16(v);
    l = __float2bfloat16(v - __bfloat162float(h));
}

// --------------------------- PTX helpers ------------------------------------
__device__ __forceinline__ uint32_t cvta_smem(const void* p) {
    uint32_t a;
    asm("{ .reg .u64 t; cvta.to.shared.u64 t, %1; cvt.u32.u64 %0, t; }" : "=r"(a) : "l"(p));
    return a;
}
__device__ __forceinline__ void cp16(uint32_t dst, const void* src) {
    asm volatile("cp.async.cg.shared.global [%0], [%1], 16;" :: "r"(dst), "l"(src) : "memory");
}
__device__ __forceinline__ void cp_commit() {
    asm volatile("cp.async.commit_group;" ::: "memory");
}
template<int N>
__device__ __forceinline__ void cp_wait() {
    asm volatile("cp.async.wait_group %0;" :: "n"(N) : "memory");
}
__device__ __forceinline__ void ldsm4(uint32_t* r, uint32_t addr) {
    asm volatile("ldmatrix.sync.aligned.m8n8.x4.shared.b16 {%0,%1,%2,%3}, [%4];"
                 : "=r"(r[0]), "=r"(r[1]), "=r"(r[2]), "=r"(r[3]) : "r"(addr));
}
__device__ __forceinline__ void mma_bf16(float* d, const uint32_t* a, uint32_t b0, uint32_t b1) {
    asm volatile(
        "mma.sync.aligned.m16n8k16.row.col.f32.bf16.bf16.f32 "
        "{%0,%1,%2,%3}, {%4,%5,%6,%7}, {%8,%9}, {%0,%1,%2,%3};"
        : "+f"(d[0]), "+f"(d[1]), "+f"(d[2]), "+f"(d[3])
        : "r"(a[0]), "r"(a[1]), "r"(a[2]), "r"(a[3]), "r"(b0), "r"(b1));
}
#define SW128(o) ((o) ^ (((o) >> 3) & 0x70))

// =====================  mma.sync bf16x3 GEMM  ================================
// C[M,N] = fp32( (Ah+Al)[M,K] @ (Bh+Bl)[N,K]^T ), tile 128x128, BK=32, 3 stages.
// A rows read at (row*lda + abase + k). Smem rows: 128B = [32 hi | 32 lo], SW128.
// EPI: 0 none; 3 decay epilogue exp(-exp(v2)*softplus(acc+v1)).
// WC: write C fp32 [row*N+col]. WB: write bf16 hi/lo split at row*ldo+obase+col.
template<int EPI, bool WB, bool WC>
__global__ __launch_bounds__(256, 2)
void gemm_bf16x3(const __nv_bfloat16* __restrict__ Ah, const __nv_bfloat16* __restrict__ Al,
                 int lda, int abase,
                 const __nv_bfloat16* __restrict__ Bh, const __nv_bfloat16* __restrict__ Bl,
                 float* __restrict__ C,
                 __nv_bfloat16* __restrict__ Oh, __nv_bfloat16* __restrict__ Ol,
                 int ldo, int obase,
                 const float* __restrict__ v1, const float* __restrict__ v2,
                 int N, int K)
{
    constexpr int STAGE_BYTES = 32 * 1024;   // A 16K + B 16K
    extern __shared__ __align__(1024) char sm_raw[];

    const int tid = threadIdx.x;
    const int wid = tid >> 5;
    const int l   = tid & 31;
    const int wm  = wid >> 1;          // 0..3  (M)
    const int wn  = wid & 1;           // 0..1  (N)
    const int bm  = blockIdx.y * 128;
    const int bn  = blockIdx.x * 128;
    const uint32_t sb = cvta_smem(sm_raw);

    const int KT = K >> 5;             // BK = 32

    // ---- cp.async loader ----
    const int ldRow = tid >> 3;        // 0..31
    const int ldCh  = tid & 7;         // chunk within 128B row
    auto load_tile = [&](int kt, int st) {
        const uint32_t aBase = sb + st * STAGE_BYTES;
        const uint32_t bBase = aBase + 16 * 1024;
        const int kof = kt * 32 + (ldCh & 3) * 8;
        const bool lo = ldCh >= 4;
        #pragma unroll
        for (int i = 0; i < 4; i++) {
            const int r = ldRow + i * 32;
            const uint32_t so = SW128((uint32_t)(r * 128 + ldCh * 16));
            const size_t ga = (size_t)(bm + r) * lda + abase + kof;
            const size_t gb = (size_t)(bn + r) * K + kof;
            cp16(aBase + so, (lo ? Al : Ah) + ga);
            cp16(bBase + so, (lo ? Bl : Bh) + gb);
        }
        cp_commit();
    };

    // ---- ldmatrix lane addressing ----
    int aRow[2], aXr[2];
    #pragma unroll
    for (int mf = 0; mf < 2; mf++) {
        aRow[mf] = wm * 32 + mf * 16 + ((l >> 3) & 1) * 8 + (l & 7);
        aXr[mf]  = (aRow[mf] & 7) << 4;
    }
    const int aChunk = ((l >> 4) & 1) * 16;
    int bRow[4], bXr[4];
    #pragma unroll
    for (int p = 0; p < 4; p++) {
        bRow[p] = wn * 64 + p * 16 + ((l >> 4) & 1) * 8 + (l & 7);
        bXr[p]  = (bRow[p] & 7) << 4;
    }
    const int bChunk = ((l >> 3) & 1) * 16;

    float acc[2][8][4];
    #pragma unroll
    for (int mf = 0; mf < 2; mf++)
        #pragma unroll
        for (int nf = 0; nf < 8; nf++)
            #pragma unroll
            for (int k = 0; k < 4; k++) acc[mf][nf][k] = 0.f;

    load_tile(0, 0);
    if (KT > 1) load_tile(1, 1);

    for (int kt = 0; kt < KT; kt++) {
        if (kt + 2 < KT) cp_wait<1>();
        else             cp_wait<0>();
        __syncthreads();
        if (kt + 2 < KT) load_tile(kt + 2, (kt + 2) % 3);

        const uint32_t aBase = sb + (uint32_t)(kt % 3) * STAGE_BYTES;
        const uint32_t bBase = aBase + 16 * 1024;

        #pragma unroll
        for (int s = 0; s < 2; s++) {
            uint32_t aH[2][4], aL[2][4];
            #pragma unroll
            for (int mf = 0; mf < 2; mf++) {
                ldsm4(aH[mf], aBase + aRow[mf] * 128 + (uint32_t)(((0 << 6) | (s << 5) | aChunk) ^ aXr[mf]));
                ldsm4(aL[mf], aBase + aRow[mf] * 128 + (uint32_t)(((1 << 6) | (s << 5) | aChunk) ^ aXr[mf]));
            }
            #pragma unroll
            for (int p = 0; p < 4; p++) {
                uint32_t rH[4], rL[4];
                ldsm4(rH, bBase + bRow[p] * 128 + (uint32_t)(((0 << 6) | (s << 5) | bChunk) ^ bXr[p]));
                ldsm4(rL, bBase + bRow[p] * 128 + (uint32_t)(((1 << 6) | (s << 5) | bChunk) ^ bXr[p]));
                #pragma unroll
                for (int mf = 0; mf < 2; mf++) {
                    mma_bf16(acc[mf][2 * p],     aH[mf], rH[0], rH[1]);
                    mma_bf16(acc[mf][2 * p + 1], aH[mf], rH[2], rH[3]);
                    mma_bf16(acc[mf][2 * p],     aH[mf], rL[0], rL[1]);
                    mma_bf16(acc[mf][2 * p + 1], aH[mf], rL[2], rL[3]);
                    mma_bf16(acc[mf][2 * p],     aL[mf], rH[0], rH[1]);
                    mma_bf16(acc[mf][2 * p + 1], aL[mf], rH[2], rH[3]);
                }
            }
        }
    }

    // ---- epilogue ----
    const int g   = l >> 2;
    const int tig = l & 3;
    #pragma unroll
    for (int mf = 0; mf < 2; mf++) {
        #pragma unroll
        for (int half = 0; half < 2; half++) {
            const int row = bm + wm * 32 + mf * 16 + g + half * 8;
            #pragma unroll
            for (int nf = 0; nf < 8; nf++) {
                const int col = bn + wn * 64 + nf * 8 + tig * 2;
                float vx = acc[mf][nf][2 * half + 0];
                float vy = acc[mf][nf][2 * half + 1];
                if constexpr (EPI == 3) {
                    float tx = vx + v1[col], ty = vy + v1[col + 1];
                    float sx = (tx > 20.f) ? tx : log1pf(expf(tx));
                    float sy = (ty > 20.f) ? ty : log1pf(expf(ty));
                    vx = expf(-expf(v2[col]) * sx);
                    vy = expf(-expf(v2[col + 1]) * sy);
                }
                if constexpr (WC) {
                    *reinterpret_cast<float2*>(C + (size_t)row * N + col) = make_float2(vx, vy);
                }
                if constexpr (WB) {
                    const size_t o = (size_t)row * ldo + obase + col;
                    __nv_bfloat162 hv = __float22bfloat162_rn(make_float2(vx, vy));
                    float2 hf = __bfloat1622float2(hv);
                    __nv_bfloat162 lv = __float22bfloat162_rn(make_float2(vx - hf.x, vy - hf.y));
                    *reinterpret_cast<__nv_bfloat162*>(Oh + o) = hv;
                    *reinterpret_cast<__nv_bfloat162*>(Ol + o) = lv;
                }
            }
        }
    }
}

// -------------------- fp32 -> bf16 hi/lo strided split ----------------------
__global__ void split_strided_kernel(const float* __restrict__ src,
                                     __nv_bfloat16* __restrict__ hi,
                                     __nv_bfloat16* __restrict__ lo,
                                     int rowlen, int ld, int colofs, int n4)
{
    int i = blockIdx.x * blockDim.x + threadIdx.x;
    if (i >= n4) return;
    float4 v = reinterpret_cast<const float4*>(src)[i];
    int e = i * 4;
    int row = e / rowlen;
    int col = e - row * rowlen;
    size_t o = (size_t)row * ld + colofs + col;
    __nv_bfloat162 h0 = __float22bfloat162_rn(make_float2(v.x, v.y));
    __nv_bfloat162 h1 = __float22bfloat162_rn(make_float2(v.z, v.w));
    float2 f0 = __bfloat1622float2(h0);
    float2 f1 = __bfloat1622float2(h1);
    __nv_bfloat162 l0 = __float22bfloat162_rn(make_float2(v.x - f0.x, v.y - f0.y));
    __nv_bfloat162 l1 = __float22bfloat162_rn(make_float2(v.z - f1.x, v.w - f1.y));
    *reinterpret_cast<__nv_bfloat162*>(hi + o)     = h0;
    *reinterpret_cast<__nv_bfloat162*>(hi + o + 2) = h1;
    *reinterpret_cast<__nv_bfloat162*>(lo + o)     = l0;
    *reinterpret_cast<__nv_bfloat162*>(lo + o + 2) = l1;
}

// -------------------- fp32 [DI x DI] + I -> bf16 hi/lo split ----------------
__global__ void split_eye_kernel(const float* __restrict__ src,
                                 __nv_bfloat16* __restrict__ hi,
                                 __nv_bfloat16* __restrict__ lo)
{
    int i = blockIdx.x * blockDim.x + threadIdx.x;   // float4 index
    if (i >= DI * DI / 4) return;
    float4 v = reinterpret_cast<const float4*>(src)[i];
    int e = i * 4;
    int row = e / DI;
    int col = e - row * DI;
    if (row == col)     v.x += 1.f;
    if (row == col + 1) v.y += 1.f;
    if (row == col + 2) v.z += 1.f;
    if (row == col + 3) v.w += 1.f;
    __nv_bfloat162 h0 = __float22bfloat162_rn(make_float2(v.x, v.y));
    __nv_bfloat162 h1 = __float22bfloat162_rn(make_float2(v.z, v.w));
    float2 f0 = __bfloat1622float2(h0);
    float2 f1 = __bfloat1622float2(h1);
    __nv_bfloat162 l0 = __float22bfloat162_rn(make_float2(v.x - f0.x, v.y - f0.y));
    __nv_bfloat162 l1 = __float22bfloat162_rn(make_float2(v.z - f1.x, v.w - f1.y));
    size_t o = (size_t)e;
    *reinterpret_cast<__nv_bfloat162*>(hi + o)     = h0;
    *reinterpret_cast<__nv_bfloat162*>(hi + o + 2) = h1;
    *reinterpret_cast<__nv_bfloat162*>(lo + o)     = l0;
    *reinterpret_cast<__nv_bfloat162*>(lo + o + 2) = l1;
}

// -------------------- transpose [DI x DI] + split ---------------------------
__global__ void transpose_split_kernel(const float* __restrict__ src,
                                       __nv_bfloat16* __restrict__ hi,
                                       __nv_bfloat16* __restrict__ lo)
{
    __shared__ float t[32][33];
    int x = blockIdx.x * 32 + threadIdx.x;
    int y = blockIdx.y * 32 + threadIdx.y;
    #pragma unroll
    for (int j = 0; j < 32; j += 8)
        t[threadIdx.y + j][threadIdx.x] = src[(size_t)(y + j) * DI + x];
    __syncthreads();
    int ox = blockIdx.y * 32 + threadIdx.x;
    int oy = blockIdx.x * 32 + threadIdx.y;
    #pragma unroll
    for (int j = 0; j < 32; j += 8) {
        float v = t[threadIdx.x][threadIdx.y + j];
        size_t o = (size_t)(oy + j) * DI + ox;
        split1(v, hi[o], lo[o]);
    }
}

// -------------------- conv + bias + SiLU -> x splits ------------------------
__global__ void conv_silu_kernel(const float* __restrict__ w, const float* __restrict__ bias)
{
    int i = blockIdx.x * blockDim.x + threadIdx.x;
    if (i >= M_ * DI) return;
    int c  = i % DI;
    int l  = (i / DI) % L_;
    int bb = i / (DI * L_);
    const float* base = g_xw + (size_t)bb * L_ * DI + c;
    float acc = bias[c];
    #pragma unroll
    for (int k = 0; k < 4; k++) {
        int ll = l - 3 + k;
        if (ll >= 0) acc = fmaf(w[c * 4 + k], base[(size_t)ll * DI], acc);
    }
    float v = siluf(acc);
    split1(v, g_x_hi[i], g_x_lo[i]);
}

// ------------------ fused double-scan (cumsum + decay recurrence) -----------
// per channel c, per l: cx += yl; u = cx + yr; st = d*st + u
__global__ void fscan_p1()
{
    int c   = blockIdx.x * blockDim.x + threadIdx.x;
    int seq = blockIdx.y;
    int bb = seq / NCH, ch = seq % NCH;
    size_t ybase = ((size_t)(bb * L_ + ch * CH)) * TWO_DI + c;
    size_t dbase = ((size_t)(bb * L_ + ch * CH)) * DI + c;
    float cx = 0.f, s = 0.f, q = 0.f, P = 1.f;
    #pragma unroll 4
    for (int i = 0; i < CH; i++) {
        float yl = g_y[ybase + (size_t)i * TWO_DI];
        float yr = g_y[ybase + (size_t)i * TWO_DI + DI];
        float d  = g_dc[dbase + (size_t)i * DI];
        cx += yl;
        float u = cx + yr;
        s = fmaf(d, s, u);
        q = fmaf(d, q, 1.f);
        P *= d;
    }
    int idx = seq * DI + c;
    g_sy[idx] = cx; g_pp[idx] = P; g_qq[idx] = q; g_ss[idx] = s;
}
__global__ void fscan_p2()
{
    int i = blockIdx.x * blockDim.x + threadIdx.x;
    if (i >= B_ * DI) return;
    int bb = i / DI, c = i % DI;
    float cx = 0.f, st = 0.f;
    #pragma unroll
    for (int ch = 0; ch < NCH; ch++) {
        int idx = (bb * NCH + ch) * DI + c;
        g_cxin[idx] = cx;
        g_stin[idx] = st;
        st = fmaf(g_pp[idx], st, fmaf(g_qq[idx], cx, g_ss[idx]));
        cx += g_sy[idx];
    }
}
__global__ void fscan_p3(const float* __restrict__ D_ss)  // -> op splits
{
    int c   = blockIdx.x * blockDim.x + threadIdx.x;
    int seq = blockIdx.y;
    int bb = seq / NCH, ch = seq % NCH;
    int gl0 = bb * L_ + ch * CH;
    size_t ybase = (size_t)gl0 * TWO_DI + c;
    size_t dbase = (size_t)gl0 * DI + c;
    float cx = g_cxin[seq * DI + c];
    float st = g_stin[seq * DI + c];
    float dss = D_ss[c];
    #pragma unroll 4
    for (int i = 0; i < CH; i++) {
        float yl = g_y[ybase + (size_t)i * TWO_DI];
        float yr = g_y[ybase + (size_t)i * TWO_DI + DI];
        float d  = g_dc[dbase + (size_t)i * DI];
        cx += yl;
        float u = cx + yr;
        st = fmaf(d, st, u);
        float z = g_z[dbase + (size_t)i * DI];
        float v = (st + u * dss) * siluf(z);
        size_t oo = dbase + (size_t)i * DI;
        split1(v, g_op_hi[oo], g_op_lo[oo]);
    }
}

// ------------------------------- launcher ----------------------------------
extern "C" void kernel_launch(void* const* d_in, const int* in_sizes, int n_in,
                              void* d_out, int out_size)
{
    const float* h         = (const float*)d_in[0];
    const float* delta     = (const float*)d_in[1];
    const float* in_proj_w = (const float*)d_in[2];
    const float* conv_w    = (const float*)d_in[3];
    const float* conv_b    = (const float*)d_in[4];
    const float* A_real    = (const float*)d_in[5];
    const float* B_w       = (const float*)d_in[6];
    const float* C_w       = (const float*)d_in[7];
    const float* D_w       = (const float*)d_in[8];
    const float* dt_proj_w = (const float*)d_in[9];
    const float* dt_proj_b = (const float*)d_in[10];
    const float* A_log     = (const float*)d_in[11];
    const float* D_ss      = (const float*)d_in[12];
    const float* out_proj_w= (const float*)d_in[13];
    float* out = (float*)d_out;

    float *xw, *z, *y, *dc;
    cudaGetSymbolAddress((void**)&xw, g_xw);
    cudaGetSymbolAddress((void**)&z,  g_z);
    cudaGetSymbolAddress((void**)&y,  g_y);
    cudaGetSymbolAddress((void**)&dc, g_dc);
    __nv_bfloat16 *hH,*hL,*xH,*xL,*opH,*opL,*dlH,*dlL;
    __nv_bfloat16 *w1H,*w1L,*iaH,*iaL,*idH,*idL,*cwH,*cwL,*btH,*btL,*ttH,*ttL,*wcH,*wcL,*woH,*woL,*dtH,*dtL;
    cudaGetSymbolAddress((void**)&hH,  g_h_hi);  cudaGetSymbolAddress((void**)&hL,  g_h_lo);
    cudaGetSymbolAddress((void**)&xH,  g_x_hi);  cudaGetSymbolAddress((void**)&xL,  g_x_lo);
    cudaGetSymbolAddress((void**)&opH, g_op_hi); cudaGetSymbolAddress((void**)&opL, g_op_lo);
    cudaGetSymbolAddress((void**)&dlH, g_dl_hi); cudaGetSymbolAddress((void**)&dlL, g_dl_lo);
    cudaGetSymbolAddress((void**)&w1H, g_w1_hi); cudaGetSymbolAddress((void**)&w1L, g_w1_lo);
    cudaGetSymbolAddress((void**)&iaH, g_ia_hi); cudaGetSymbolAddress((void**)&iaL, g_ia_lo);
    cudaGetSymbolAddress((void**)&idH, g_id_hi); cudaGetSymbolAddress((void**)&idL, g_id_lo);
    cudaGetSymbolAddress((void**)&cwH, g_cw_hi); cudaGetSymbolAddress((void**)&cwL, g_cw_lo);
    cudaGetSymbolAddress((void**)&btH, g_bt_hi); cudaGetSymbolAddress((void**)&btL, g_bt_lo);
    cudaGetSymbolAddress((void**)&ttH, g_tt_hi); cudaGetSymbolAddress((void**)&ttL, g_tt_lo);
    cudaGetSymbolAddress((void**)&wcH, g_wc_hi); cudaGetSymbolAddress((void**)&wcL, g_wc_lo);
    cudaGetSymbolAddress((void**)&woH, g_wo_hi); cudaGetSymbolAddress((void**)&woL, g_wo_lo);
    cudaGetSymbolAddress((void**)&dtH, g_dt_hi); cudaGetSymbolAddress((void**)&dtL, g_dt_lo);

    constexpr int SMEM = 96 * 1024;
    cudaFuncSetAttribute(gemm_bf16x3<0, false, true>, cudaFuncAttributeMaxDynamicSharedMemorySize, SMEM);
    cudaFuncSetAttribute(gemm_bf16x3<0, true, false>, cudaFuncAttributeMaxDynamicSharedMemorySize, SMEM);
    cudaFuncSetAttribute(gemm_bf16x3<3, false, true>, cudaFuncAttributeMaxDynamicSharedMemorySize, SMEM);

    // ---- streams / events (created once; host-side only) ----
    static cudaStream_t s2 = nullptr, s3 = nullptr;
    static cudaEvent_t  eF = nullptr, eW1 = nullptr, eW2 = nullptr, eG = nullptr,
                        eZ = nullptr, eDT = nullptr, eWO = nullptr;
    if (s2 == nullptr) {
        cudaStreamCreateWithFlags(&s2, cudaStreamNonBlocking);
        cudaStreamCreateWithFlags(&s3, cudaStreamNonBlocking);
        cudaEventCreateWithFlags(&eF,  cudaEventDisableTiming);
        cudaEventCreateWithFlags(&eW1, cudaEventDisableTiming);
        cudaEventCreateWithFlags(&eW2, cudaEventDisableTiming);
        cudaEventCreateWithFlags(&eG,  cudaEventDisableTiming);
        cudaEventCreateWithFlags(&eZ,  cudaEventDisableTiming);
        cudaEventCreateWithFlags(&eDT, cudaEventDisableTiming);
        cudaEventCreateWithFlags(&eWO, cudaEventDisableTiming);
    }

    auto splitOn = [&](cudaStream_t st, const float* s, __nv_bfloat16* hi_, __nv_bfloat16* lo_,
                       int rowlen, int ld, int colofs, size_t n) {
        int n4 = (int)(n / 4);
        split_strided_kernel<<<(n4 + 255) / 256, 256, 0, st>>>(s, hi_, lo_, rowlen, ld, colofs, n4);
    };

    const int GY = M_ / 128;   // 64
    const dim3 gSeq(DI / 256, B_ * NCH);

    // fork
    cudaEventRecord(eF, 0);
    cudaStreamWaitEvent(s2, eF, 0);
    cudaStreamWaitEvent(s3, eF, 0);

    // ---- main: inputs for the x-GEMM ----
    splitOn(0, h,         hH,  hL,  DM, DM, 0, (size_t)M_ * DM);
    splitOn(0, in_proj_w, w1H, w1L, DM, DM, 0, (size_t)TWO_DI * DM);
    cudaEventRecord(eW1, 0);

    // x = h @ Wx^T  (first DI rows of in_proj_w)
    gemm_bf16x3<0, false, true><<<dim3(DI / 128, GY), 256, SMEM>>>(
        hH, hL, DM, 0, w1H, w1L, xw, nullptr, nullptr, 0, 0,
        nullptr, nullptr, DI, DM);

    // ---- s2: W2 fold chain ----
    splitOn(s2, C_w, cwH, cwL, DI, DI, 0, (size_t)DI * DI);
    transpose_split_kernel<<<dim3(DI / 32, DI / 32), dim3(32, 8), 0, s2>>>(B_w, btH, btL);
    split_eye_kernel<<<(DI * DI / 4) / 256, 256, 0, s2>>>(A_real, iaH, iaL);
    // T = C_w B_w
    gemm_bf16x3<0, true, false><<<dim3(DI / 128, DI / 128), 256, SMEM, s2>>>(
        cwH, cwL, DI, 0, btH, btL, nullptr, ttH, ttL, DI, 0,
        nullptr, nullptr, DI, DI);
    // W2 = T (I+A)^T -> wc rows [0, DI)
    gemm_bf16x3<0, true, false><<<dim3(DI / 128, DI / 128), 256, SMEM, s2>>>(
        ttH, ttL, DI, 0, iaH, iaL, nullptr, wcH, wcL, DI, 0,
        nullptr, nullptr, DI, DI);
    cudaEventRecord(eW2, s2);

    // ---- s3: G fold, z-GEMM, decay, out_proj split ----
    split_eye_kernel<<<(DI * DI / 4) / 256, 256, 0, s3>>>(D_w, idH, idL);
    cudaStreamWaitEvent(s3, eW2, 0);   // needs iaH/iaL ready (produced before eW2) — wait on W2 ev is late;
    // NOTE: eye(A) finishes long before eW2; to avoid over-serialization we
    // instead rely on a dedicated event right after eye(A):
    // (handled below via eG ordering — see launcher structure)
    // G = (I+D)(I+A)^T -> wc rows [DI, 2*DI)
    gemm_bf16x3<0, true, false><<<dim3(DI / 128, DI / 128), 256, SMEM, s3>>>(
        idH, idL, DI, 0, iaH, iaL, nullptr, wcH, wcL, DI, DI * DI,
        nullptr, nullptr, DI, DI);
    cudaEventRecord(eG, s3);
    // z = h @ Wz^T  (rows [DI, 2*DI) of in_proj_w)
    cudaStreamWaitEvent(s3, eW1, 0);
    gemm_bf16x3<0, false, true><<<dim3(DI / 128, GY), 256, SMEM, s3>>>(
        hH, hL, DM, 0, w1H + (size_t)DI * DM, w1L + (size_t)DI * DM, z,
        nullptr, nullptr, 0, 0, nullptr, nullptr, DI, DM);
    cudaEventRecord(eZ, s3);
    // decay inputs + GEMM
    splitOn(s3, delta,     dlH, dlL, DTR, DTR, 0, (size_t)M_ * DTR);
    splitOn(s3, dt_proj_w, dtH, dtL, DTR, DTR, 0, (size_t)DI * DTR);
    gemm_bf16x3<3, false, true><<<dim3(DI / 128, GY), 256, SMEM, s3>>>(
        dlH, dlL, DTR, 0, dtH, dtL, dc, nullptr, nullptr, 0, 0,
        dt_proj_b, A_log, DI, DTR);
    cudaEventRecord(eDT, s3);
    splitOn(s3, out_proj_w, woH, woL, DI, DI, 0, (size_t)DM * DI);
    cudaEventRecord(eWO, s3);

    // ---- main chain continues ----
    conv_silu_kernel<<<(M_ * DI) / 256, 256>>>(conv_w, conv_b);

    // join for y: needs W2 (s2) and G (s3)
    cudaStreamWaitEvent(0, eW2, 0);
    cudaStreamWaitEvent(0, eG, 0);

    // y = x @ [W2 ; G]^T   (N = 4096, K = 2048)
    gemm_bf16x3<0, false, true><<<dim3(TWO_DI / 128, GY), 256, SMEM>>>(
        xH, xL, DI, 0, wcH, wcL, y, nullptr, nullptr, 0, 0,
        nullptr, nullptr, TWO_DI, DI);

    // join for scan: needs dc and z
    cudaStreamWaitEvent(0, eDT, 0);
    cudaStreamWaitEvent(0, eZ, 0);

    // fused double-scan; pass3 fuses (+ u*D_ss) * silu(z) -> op splits
    fscan_p1<<<gSeq, 256>>>();
    fscan_p2<<<(B_ * DI + 255) / 256, 256>>>();
    fscan_p3<<<gSeq, 256>>>(D_ss);

    // join for out: needs wo splits
    cudaStreamWaitEvent(0, eWO, 0);

    // out = out_pre @ out_proj_w^T  [8192, 1024]
    gemm_bf16x3<0, false, true><<<dim3(DM / 128, GY), 256, SMEM>>>(
        opH, opL, DI, 0, woH, woL, out, nullptr, nullptr, 0, 0,
        nullptr, nullptr, DM, DI);
}

// round 11
// speedup vs baseline: 4.4347x; 1.0409x over previous
#include <cuda_runtime.h>
#include <cuda_bf16.h>
#include <math.h>
#include <stdint.h>

// ---------------------------------------------------------------------------
// Mamba3Block on GB300 — round 11: batch-sliced dual pipelines (R10) with the
// stream-capture join fix (all side streams rejoin stream 0 before return).
// ---------------------------------------------------------------------------

namespace {
constexpr int B_   = 2;
constexpr int L_   = 4096;
constexpr int DM   = 1024;
constexpr int DI   = 2048;
constexpr int M_   = B_ * L_;        // 8192
constexpr int NCH  = 64;             // chunks per sequence
constexpr int CH   = L_ / NCH;       // 64
constexpr int TWO_DI = 2 * DI;       // 4096
constexpr int DTR  = 64;
}

// ------------------------- fp32 scratch ------------------------------------
__device__ float g_z [(size_t)M_ * DI];       // in_proj z-half
__device__ float g_y [(size_t)M_ * TWO_DI];   // [yl | yr]
__device__ float g_dc[(size_t)M_ * DI];
__device__ float g_sy[B_ * NCH * DI];
__device__ float g_pp[B_ * NCH * DI];
__device__ float g_qq[B_ * NCH * DI];
__device__ float g_ss[B_ * NCH * DI];

// ------------------------- bf16 split scratch ------------------------------
__device__ __nv_bfloat16 g_h_hi [(size_t)M_ * DM],   g_h_lo [(size_t)M_ * DM];
__device__ __nv_bfloat16 g_xw_hi[(size_t)M_ * DI],   g_xw_lo[(size_t)M_ * DI];  // pre-conv x
__device__ __nv_bfloat16 g_x_hi [(size_t)M_ * DI],   g_x_lo [(size_t)M_ * DI];  // post conv+silu
__device__ __nv_bfloat16 g_op_hi[(size_t)M_ * DI],   g_op_lo[(size_t)M_ * DI];
__device__ __nv_bfloat16 g_dl_hi[(size_t)M_ * DTR],  g_dl_lo[(size_t)M_ * DTR];
__device__ __nv_bfloat16 g_w1_hi[(size_t)TWO_DI * DM], g_w1_lo[(size_t)TWO_DI * DM];
__device__ __nv_bfloat16 g_ia_hi[(size_t)DI * DI],   g_ia_lo[(size_t)DI * DI];   // I + A_real
__device__ __nv_bfloat16 g_id_hi[(size_t)DI * DI],   g_id_lo[(size_t)DI * DI];   // I + D_w
__device__ __nv_bfloat16 g_cw_hi[(size_t)DI * DI],   g_cw_lo[(size_t)DI * DI];   // C_w
__device__ __nv_bfloat16 g_bt_hi[(size_t)DI * DI],   g_bt_lo[(size_t)DI * DI];   // B_w^T
__device__ __nv_bfloat16 g_tt_hi[(size_t)DI * DI],   g_tt_lo[(size_t)DI * DI];   // T = C_w B_w
__device__ __nv_bfloat16 g_wc_hi[(size_t)TWO_DI * DI], g_wc_lo[(size_t)TWO_DI * DI]; // rows: [W2 ; G]
__device__ __nv_bfloat16 g_wo_hi[(size_t)DM * DI],   g_wo_lo[(size_t)DM * DI];
__device__ __nv_bfloat16 g_dt_hi[(size_t)DI * DTR],  g_dt_lo[(size_t)DI * DTR];

__device__ __forceinline__ float siluf(float v) { return v / (1.f + expf(-v)); }

__device__ __forceinline__ void split1(float v, __nv_bfloat16& h, __nv_bfloat16& l) {
    h = __float2bfloat16(v);
    l = __float2bfloat16(v - __bfloat162float(h));
}

// --------------------------- PTX helpers ------------------------------------
__device__ __forceinline__ uint32_t cvta_smem(const void* p) {
    uint32_t a;
    asm("{ .reg .u64 t; cvta.to.shared.u64 t, %1; cvt.u32.u64 %0, t; }" : "=r"(a) : "l"(p));
    return a;
}
__device__ __forceinline__ void cp16(uint32_t dst, const void* src) {
    asm volatile("cp.async.cg.shared.global [%0], [%1], 16;" :: "r"(dst), "l"(src) : "memory");
}
__device__ __forceinline__ void cp_commit() {
    asm volatile("cp.async.commit_group;" ::: "memory");
}
template<int N>
__device__ __forceinline__ void cp_wait() {
    asm volatile("cp.async.wait_group %0;" :: "n"(N) : "memory");
}
__device__ __forceinline__ void ldsm4(uint32_t* r, uint32_t addr) {
    asm volatile("ldmatrix.sync.aligned.m8n8.x4.shared.b16 {%0,%1,%2,%3}, [%4];"
                 : "=r"(r[0]), "=r"(r[1]), "=r"(r[2]), "=r"(r[3]) : "r"(addr));
}
__device__ __forceinline__ void mma_bf16(float* d, const uint32_t* a, uint32_t b0, uint32_t b1) {
    asm volatile(
        "mma.sync.aligned.m16n8k16.row.col.f32.bf16.bf16.f32 "
        "{%0,%1,%2,%3}, {%4,%5,%6,%7}, {%8,%9}, {%0,%1,%2,%3};"
        : "+f"(d[0]), "+f"(d[1]), "+f"(d[2]), "+f"(d[3])
        : "r"(a[0]), "r"(a[1]), "r"(a[2]), "r"(a[3]), "r"(b0), "r"(b1));
}
#define SW128(o) ((o) ^ (((o) >> 3) & 0x70))

// =====================  mma.sync bf16x3 GEMM  ================================
template<int EPI, bool WB, bool WC>
__global__ __launch_bounds__(256, 2)
void gemm_bf16x3(const __nv_bfloat16* __restrict__ Ah, const __nv_bfloat16* __restrict__ Al,
                 int lda, int abase,
                 const __nv_bfloat16* __restrict__ Bh, const __nv_bfloat16* __restrict__ Bl,
                 float* __restrict__ C,
                 __nv_bfloat16* __restrict__ Oh, __nv_bfloat16* __restrict__ Ol,
                 int ldo, int obase,
                 const float* __restrict__ v1, const float* __restrict__ v2,
                 int N, int K)
{
    constexpr int STAGE_BYTES = 32 * 1024;   // A 16K + B 16K
    extern __shared__ __align__(1024) char sm_raw[];

    const int tid = threadIdx.x;
    const int wid = tid >> 5;
    const int l   = tid & 31;
    const int wm  = wid >> 1;
    const int wn  = wid & 1;
    const int bm  = blockIdx.y * 128;
    const int bn  = blockIdx.x * 128;
    const uint32_t sb = cvta_smem(sm_raw);

    const int KT = K >> 5;

    const int ldRow = tid >> 3;
    const int ldCh  = tid & 7;
    auto load_tile = [&](int kt, int st) {
        const uint32_t aBase = sb + st * STAGE_BYTES;
        const uint32_t bBase = aBase + 16 * 1024;
        const int kof = kt * 32 + (ldCh & 3) * 8;
        const bool lo = ldCh >= 4;
        #pragma unroll
        for (int i = 0; i < 4; i++) {
            const int r = ldRow + i * 32;
            const uint32_t so = SW128((uint32_t)(r * 128 + ldCh * 16));
            const size_t ga = (size_t)(bm + r) * lda + abase + kof;
            const size_t gb = (size_t)(bn + r) * K + kof;
            cp16(aBase + so, (lo ? Al : Ah) + ga);
            cp16(bBase + so, (lo ? Bl : Bh) + gb);
        }
        cp_commit();
    };

    int aRow[2], aXr[2];
    #pragma unroll
    for (int mf = 0; mf < 2; mf++) {
        aRow[mf] = wm * 32 + mf * 16 + ((l >> 3) & 1) * 8 + (l & 7);
        aXr[mf]  = (aRow[mf] & 7) << 4;
    }
    const int aChunk = ((l >> 4) & 1) * 16;
    int bRow[4], bXr[4];
    #pragma unroll
    for (int p = 0; p < 4; p++) {
        bRow[p] = wn * 64 + p * 16 + ((l >> 4) & 1) * 8 + (l & 7);
        bXr[p]  = (bRow[p] & 7) << 4;
    }
    const int bChunk = ((l >> 3) & 1) * 16;

    float acc[2][8][4];
    #pragma unroll
    for (int mf = 0; mf < 2; mf++)
        #pragma unroll
        for (int nf = 0; nf < 8; nf++)
            #pragma unroll
            for (int k = 0; k < 4; k++) acc[mf][nf][k] = 0.f;

    load_tile(0, 0);
    if (KT > 1) load_tile(1, 1);

    for (int kt = 0; kt < KT; kt++) {
        if (kt + 2 < KT) cp_wait<1>();
        else             cp_wait<0>();
        __syncthreads();
        if (kt + 2 < KT) load_tile(kt + 2, (kt + 2) % 3);

        const uint32_t aBase = sb + (uint32_t)(kt % 3) * STAGE_BYTES;
        const uint32_t bBase = aBase + 16 * 1024;

        #pragma unroll
        for (int s = 0; s < 2; s++) {
            uint32_t aH[2][4], aL[2][4];
            #pragma unroll
            for (int mf = 0; mf < 2; mf++) {
                ldsm4(aH[mf], aBase + aRow[mf] * 128 + (uint32_t)(((0 << 6) | (s << 5) | aChunk) ^ aXr[mf]));
                ldsm4(aL[mf], aBase + aRow[mf] * 128 + (uint32_t)(((1 << 6) | (s << 5) | aChunk) ^ aXr[mf]));
            }
            #pragma unroll
            for (int p = 0; p < 4; p++) {
                uint32_t rH[4], rL[4];
                ldsm4(rH, bBase + bRow[p] * 128 + (uint32_t)(((0 << 6) | (s << 5) | bChunk) ^ bXr[p]));
                ldsm4(rL, bBase + bRow[p] * 128 + (uint32_t)(((1 << 6) | (s << 5) | bChunk) ^ bXr[p]));
                #pragma unroll
                for (int mf = 0; mf < 2; mf++) {
                    mma_bf16(acc[mf][2 * p],     aH[mf], rH[0], rH[1]);
                    mma_bf16(acc[mf][2 * p + 1], aH[mf], rH[2], rH[3]);
                    mma_bf16(acc[mf][2 * p],     aH[mf], rL[0], rL[1]);
                    mma_bf16(acc[mf][2 * p + 1], aH[mf], rL[2], rL[3]);
                    mma_bf16(acc[mf][2 * p],     aL[mf], rH[0], rH[1]);
                    mma_bf16(acc[mf][2 * p + 1], aL[mf], rH[2], rH[3]);
                }
            }
        }
    }

    const int g   = l >> 2;
    const int tig = l & 3;
    #pragma unroll
    for (int mf = 0; mf < 2; mf++) {
        #pragma unroll
        for (int half = 0; half < 2; half++) {
            const int row = bm + wm * 32 + mf * 16 + g + half * 8;
            #pragma unroll
            for (int nf = 0; nf < 8; nf++) {
                const int col = bn + wn * 64 + nf * 8 + tig * 2;
                float vx = acc[mf][nf][2 * half + 0];
                float vy = acc[mf][nf][2 * half + 1];
                if constexpr (EPI == 3) {
                    float tx = vx + v1[col], ty = vy + v1[col + 1];
                    float sx = (tx > 20.f) ? tx : log1pf(expf(tx));
                    float sy = (ty > 20.f) ? ty : log1pf(expf(ty));
                    vx = expf(-expf(v2[col]) * sx);
                    vy = expf(-expf(v2[col + 1]) * sy);
                }
                if constexpr (WC) {
                    *reinterpret_cast<float2*>(C + (size_t)row * N + col) = make_float2(vx, vy);
                }
                if constexpr (WB) {
                    const size_t o = (size_t)row * ldo + obase + col;
                    __nv_bfloat162 hv = __float22bfloat162_rn(make_float2(vx, vy));
                    float2 hf = __bfloat1622float2(hv);
                    __nv_bfloat162 lv = __float22bfloat162_rn(make_float2(vx - hf.x, vy - hf.y));
                    *reinterpret_cast<__nv_bfloat162*>(Oh + o) = hv;
                    *reinterpret_cast<__nv_bfloat162*>(Ol + o) = lv;
                }
            }
        }
    }
}

// -------------------- fp32 -> bf16 hi/lo strided split ----------------------
__global__ void split_strided_kernel(const float* __restrict__ src,
                                     __nv_bfloat16* __restrict__ hi,
                                     __nv_bfloat16* __restrict__ lo,
                                     int rowlen, int ld, int colofs, int n4)
{
    int i = blockIdx.x * blockDim.x + threadIdx.x;
    if (i >= n4) return;
    float4 v = reinterpret_cast<const float4*>(src)[i];
    int e = i * 4;
    int row = e / rowlen;
    int col = e - row * rowlen;
    size_t o = (size_t)row * ld + colofs + col;
    __nv_bfloat162 h0 = __float22bfloat162_rn(make_float2(v.x, v.y));
    __nv_bfloat162 h1 = __float22bfloat162_rn(make_float2(v.z, v.w));
    float2 f0 = __bfloat1622float2(h0);
    float2 f1 = __bfloat1622float2(h1);
    __nv_bfloat162 l0 = __float22bfloat162_rn(make_float2(v.x - f0.x, v.y - f0.y));
    __nv_bfloat162 l1 = __float22bfloat162_rn(make_float2(v.z - f1.x, v.w - f1.y));
    *reinterpret_cast<__nv_bfloat162*>(hi + o)     = h0;
    *reinterpret_cast<__nv_bfloat162*>(hi + o + 2) = h1;
    *reinterpret_cast<__nv_bfloat162*>(lo + o)     = l0;
    *reinterpret_cast<__nv_bfloat162*>(lo + o + 2) = l1;
}

// -------------------- fp32 [DI x DI] + I -> bf16 hi/lo split ----------------
__global__ void split_eye_kernel(const float* __restrict__ src,
                                 __nv_bfloat16* __restrict__ hi,
                                 __nv_bfloat16* __restrict__ lo)
{
    int i = blockIdx.x * blockDim.x + threadIdx.x;
    if (i >= DI * DI / 4) return;
    float4 v = reinterpret_cast<const float4*>(src)[i];
    int e = i * 4;
    int row = e / DI;
    int col = e - row * DI;
    if (row == col)     v.x += 1.f;
    if (row == col + 1) v.y += 1.f;
    if (row == col + 2) v.z += 1.f;
    if (row == col + 3) v.w += 1.f;
    __nv_bfloat162 h0 = __float22bfloat162_rn(make_float2(v.x, v.y));
    __nv_bfloat162 h1 = __float22bfloat162_rn(make_float2(v.z, v.w));
    float2 f0 = __bfloat1622float2(h0);
    float2 f1 = __bfloat1622float2(h1);
    __nv_bfloat162 l0 = __float22bfloat162_rn(make_float2(v.x - f0.x, v.y - f0.y));
    __nv_bfloat162 l1 = __float22bfloat162_rn(make_float2(v.z - f1.x, v.w - f1.y));
    size_t o = (size_t)e;
    *reinterpret_cast<__nv_bfloat162*>(hi + o)     = h0;
    *reinterpret_cast<__nv_bfloat162*>(hi + o + 2) = h1;
    *reinterpret_cast<__nv_bfloat162*>(lo + o)     = l0;
    *reinterpret_cast<__nv_bfloat162*>(lo + o + 2) = l1;
}

// -------------------- transpose [DI x DI] + split ---------------------------
__global__ void transpose_split_kernel(const float* __restrict__ src,
                                       __nv_bfloat16* __restrict__ hi,
                                       __nv_bfloat16* __restrict__ lo)
{
    __shared__ float t[32][33];
    int x = blockIdx.x * 32 + threadIdx.x;
    int y = blockIdx.y * 32 + threadIdx.y;
    #pragma unroll
    for (int j = 0; j < 32; j += 8)
        t[threadIdx.y + j][threadIdx.x] = src[(size_t)(y + j) * DI + x];
    __syncthreads();
    int ox = blockIdx.y * 32 + threadIdx.x;
    int oy = blockIdx.x * 32 + threadIdx.y;
    #pragma unroll
    for (int j = 0; j < 32; j += 8) {
        float v = t[threadIdx.x][threadIdx.y + j];
        size_t o = (size_t)(oy + j) * DI + ox;
        split1(v, hi[o], lo[o]);
    }
}

// -------------------- conv + bias + SiLU (batch slice) ----------------------
__global__ void conv_silu_kernel(const float* __restrict__ w, const float* __restrict__ bias, int bb)
{
    int i = blockIdx.x * blockDim.x + threadIdx.x;
    if (i >= L_ * DI) return;
    int c = i % DI;
    int l = i / DI;
    float acc = bias[c];
    #pragma unroll
    for (int k = 0; k < 4; k++) {
        int ll = l - 3 + k;
        if (ll >= 0) {
            size_t o = (size_t)(bb * L_ + ll) * DI + c;
            float xv = __bfloat162float(g_xw_hi[o]) + __bfloat162float(g_xw_lo[o]);
            acc = fmaf(w[c * 4 + k], xv, acc);
        }
    }
    float v = siluf(acc);
    size_t oo = (size_t)(bb * L_ + l) * DI + c;
    split1(v, g_x_hi[oo], g_x_lo[oo]);
}

// ------------------ fused double-scan (cumsum + decay recurrence) -----------
__global__ void fscan_p1(int bb)
{
    int c  = blockIdx.x * blockDim.x + threadIdx.x;
    int ch = blockIdx.y;
    size_t ybase = ((size_t)(bb * L_ + ch * CH)) * TWO_DI + c;
    size_t dbase = ((size_t)(bb * L_ + ch * CH)) * DI + c;
    float cx = 0.f, s = 0.f, q = 0.f, P = 1.f;
    #pragma unroll 4
    for (int i = 0; i < CH; i++) {
        float yl = g_y[ybase + (size_t)i * TWO_DI];
        float yr = g_y[ybase + (size_t)i * TWO_DI + DI];
        float d  = g_dc[dbase + (size_t)i * DI];
        cx += yl;
        float u = cx + yr;
        s = fmaf(d, s, u);
        q = fmaf(d, q, 1.f);
        P *= d;
    }
    int idx = (bb * NCH + ch) * DI + c;
    g_sy[idx] = cx; g_pp[idx] = P; g_qq[idx] = q; g_ss[idx] = s;
}
// pass 3 re-derives its chunk carry from summaries (merged pass 2), then
// replays with the fused (+ u*D_ss) * silu(z) epilogue -> op splits
__global__ void fscan_p3(const float* __restrict__ D_ss, int bb)
{
    int c  = blockIdx.x * blockDim.x + threadIdx.x;
    int ch = blockIdx.y;
    float cx = 0.f, st = 0.f;
    for (int p = 0; p < ch; p++) {
        int idx = (bb * NCH + p) * DI + c;
        st = fmaf(g_pp[idx], st, fmaf(g_qq[idx], cx, g_ss[idx]));
        cx += g_sy[idx];
    }
    int gl0 = bb * L_ + ch * CH;
    size_t ybase = (size_t)gl0 * TWO_DI + c;
    size_t dbase = (size_t)gl0 * DI + c;
    float dss = D_ss[c];
    #pragma unroll 4
    for (int i = 0; i < CH; i++) {
        float yl = g_y[ybase + (size_t)i * TWO_DI];
        float yr = g_y[ybase + (size_t)i * TWO_DI + DI];
        float d  = g_dc[dbase + (size_t)i * DI];
        cx += yl;
        float u = cx + yr;
        st = fmaf(d, st, u);
        float z = g_z[dbase + (size_t)i * DI];
        float v = (st + u * dss) * siluf(z);
        size_t oo = dbase + (size_t)i * DI;
        split1(v, g_op_hi[oo], g_op_lo[oo]);
    }
}

// ------------------------------- launcher ----------------------------------
extern "C" void kernel_launch(void* const* d_in, const int* in_sizes, int n_in,
                              void* d_out, int out_size)
{
    const float* h         = (const float*)d_in[0];
    const float* delta     = (const float*)d_in[1];
    const float* in_proj_w = (const float*)d_in[2];
    const float* conv_w    = (const float*)d_in[3];
    const float* conv_b    = (const float*)d_in[4];
    const float* A_real    = (const float*)d_in[5];
    const float* B_w       = (const float*)d_in[6];
    const float* C_w       = (const float*)d_in[7];
    const float* D_w       = (const float*)d_in[8];
    const float* dt_proj_w = (const float*)d_in[9];
    const float* dt_proj_b = (const float*)d_in[10];
    const float* A_log     = (const float*)d_in[11];
    const float* D_ss      = (const float*)d_in[12];
    const float* out_proj_w= (const float*)d_in[13];
    float* out = (float*)d_out;

    float *z, *y, *dc;
    cudaGetSymbolAddress((void**)&z,  g_z);
    cudaGetSymbolAddress((void**)&y,  g_y);
    cudaGetSymbolAddress((void**)&dc, g_dc);
    __nv_bfloat16 *hH,*hL,*xwH,*xwL,*xH,*xL,*opH,*opL,*dlH,*dlL;
    __nv_bfloat16 *w1H,*w1L,*iaH,*iaL,*idH,*idL,*cwH,*cwL,*btH,*btL,*ttH,*ttL,*wcH,*wcL,*woH,*woL,*dtH,*dtL;
    cudaGetSymbolAddress((void**)&hH,  g_h_hi);  cudaGetSymbolAddress((void**)&hL,  g_h_lo);
    cudaGetSymbolAddress((void**)&xwH, g_xw_hi); cudaGetSymbolAddress((void**)&xwL, g_xw_lo);
    cudaGetSymbolAddress((void**)&xH,  g_x_hi);  cudaGetSymbolAddress((void**)&xL,  g_x_lo);
    cudaGetSymbolAddress((void**)&opH, g_op_hi); cudaGetSymbolAddress((void**)&opL, g_op_lo);
    cudaGetSymbolAddress((void**)&dlH, g_dl_hi); cudaGetSymbolAddress((void**)&dlL, g_dl_lo);
    cudaGetSymbolAddress((void**)&w1H, g_w1_hi); cudaGetSymbolAddress((void**)&w1L, g_w1_lo);
    cudaGetSymbolAddress((void**)&iaH, g_ia_hi); cudaGetSymbolAddress((void**)&iaL, g_ia_lo);
    cudaGetSymbolAddress((void**)&idH, g_id_hi); cudaGetSymbolAddress((void**)&idL, g_id_lo);
    cudaGetSymbolAddress((void**)&cwH, g_cw_hi); cudaGetSymbolAddress((void**)&cwL, g_cw_lo);
    cudaGetSymbolAddress((void**)&btH, g_bt_hi); cudaGetSymbolAddress((void**)&btL, g_bt_lo);
    cudaGetSymbolAddress((void**)&ttH, g_tt_hi); cudaGetSymbolAddress((void**)&ttL, g_tt_lo);
    cudaGetSymbolAddress((void**)&wcH, g_wc_hi); cudaGetSymbolAddress((void**)&wcL, g_wc_lo);
    cudaGetSymbolAddress((void**)&woH, g_wo_hi); cudaGetSymbolAddress((void**)&woL, g_wo_lo);
    cudaGetSymbolAddress((void**)&dtH, g_dt_hi); cudaGetSymbolAddress((void**)&dtL, g_dt_lo);

    constexpr int SMEM = 96 * 1024;
    cudaFuncSetAttribute(gemm_bf16x3<0, false, true>, cudaFuncAttributeMaxDynamicSharedMemorySize, SMEM);
    cudaFuncSetAttribute(gemm_bf16x3<0, true, false>, cudaFuncAttributeMaxDynamicSharedMemorySize, SMEM);
    cudaFuncSetAttribute(gemm_bf16x3<3, false, true>, cudaFuncAttributeMaxDynamicSharedMemorySize, SMEM);

    // ---- streams / events (created once; host-side only) ----
    static cudaStream_t m1 = nullptr, s2 = nullptr, s3 = nullptr;
    static cudaEvent_t  eF = nullptr, eHW = nullptr, eIA = nullptr, eW2 = nullptr,
                        eG = nullptr, eZ = nullptr, eDT = nullptr, eWO = nullptr,
                        eX0 = nullptr, eP1 = nullptr;
    if (m1 == nullptr) {
        cudaStreamCreateWithFlags(&m1, cudaStreamNonBlocking);
        cudaStreamCreateWithFlags(&s2, cudaStreamNonBlocking);
        cudaStreamCreateWithFlags(&s3, cudaStreamNonBlocking);
        cudaEventCreateWithFlags(&eF,  cudaEventDisableTiming);
        cudaEventCreateWithFlags(&eHW, cudaEventDisableTiming);
        cudaEventCreateWithFlags(&eIA, cudaEventDisableTiming);
        cudaEventCreateWithFlags(&eW2, cudaEventDisableTiming);
        cudaEventCreateWithFlags(&eG,  cudaEventDisableTiming);
        cudaEventCreateWithFlags(&eZ,  cudaEventDisableTiming);
        cudaEventCreateWithFlags(&eDT, cudaEventDisableTiming);
        cudaEventCreateWithFlags(&eWO, cudaEventDisableTiming);
        cudaEventCreateWithFlags(&eX0, cudaEventDisableTiming);
        cudaEventCreateWithFlags(&eP1, cudaEventDisableTiming);
    }

    auto splitOn = [&](cudaStream_t st, const float* s, __nv_bfloat16* hi_, __nv_bfloat16* lo_,
                       int rowlen, int ld, int colofs, size_t n) {
        int n4 = (int)(n / 4);
        split_strided_kernel<<<(n4 + 255) / 256, 256, 0, st>>>(s, hi_, lo_, rowlen, ld, colofs, n4);
    };

    const int GYH = L_ / 128;             // 32 M-tiles per batch slice
    const dim3 gScan(DI / 256, NCH);

    // fork
    cudaEventRecord(eF, 0);
    cudaStreamWaitEvent(m1, eF, 0);
    cudaStreamWaitEvent(s2, eF, 0);
    cudaStreamWaitEvent(s3, eF, 0);

    // launches 0..4, then x0 GEMM at ncu slot #5
    splitOn(0, h,         hH,  hL,  DM, DM, 0, (size_t)M_ * DM);            // 0
    splitOn(0, in_proj_w, w1H, w1L, DM, DM, 0, (size_t)TWO_DI * DM);        // 1
    cudaEventRecord(eHW, 0);
    splitOn(s2, C_w, cwH, cwL, DI, DI, 0, (size_t)DI * DI);                 // 2
    transpose_split_kernel<<<dim3(DI / 32, DI / 32), dim3(32, 8), 0, s2>>>(B_w, btH, btL); // 3
    split_eye_kernel<<<(DI * DI / 4) / 256, 256, 0, s2>>>(A_real, iaH, iaL);               // 4
    cudaEventRecord(eIA, s2);

    // 5: x0 = h[b0] @ Wx^T -> xw splits (batch 0)
    gemm_bf16x3<0, true, false><<<dim3(DI / 128, GYH), 256, SMEM>>>(
        hH, hL, DM, 0, w1H, w1L, nullptr, xwH, xwL, DI, 0,
        nullptr, nullptr, DI, DM);
    cudaEventRecord(eX0, 0);

    // s2: T = C_w B_w ; W2 = T (I+A)^T -> wc rows [0, DI)
    gemm_bf16x3<0, true, false><<<dim3(DI / 128, DI / 128), 256, SMEM, s2>>>(
        cwH, cwL, DI, 0, btH, btL, nullptr, ttH, ttL, DI, 0,
        nullptr, nullptr, DI, DI);
    gemm_bf16x3<0, true, false><<<dim3(DI / 128, DI / 128), 256, SMEM, s2>>>(
        ttH, ttL, DI, 0, iaH, iaL, nullptr, wcH, wcL, DI, 0,
        nullptr, nullptr, DI, DI);
    cudaEventRecord(eW2, s2);

    // s3: G = (I+D)(I+A)^T -> wc rows [DI, 2*DI) ; z ; decay ; wo split
    split_eye_kernel<<<(DI * DI / 4) / 256, 256, 0, s3>>>(D_w, idH, idL);
    cudaStreamWaitEvent(s3, eIA, 0);
    gemm_bf16x3<0, true, false><<<dim3(DI / 128, DI / 128), 256, SMEM, s3>>>(
        idH, idL, DI, 0, iaH, iaL, nullptr, wcH, wcL, DI, DI * DI,
        nullptr, nullptr, DI, DI);
    cudaEventRecord(eG, s3);
    cudaStreamWaitEvent(s3, eHW, 0);
    gemm_bf16x3<0, false, true><<<dim3(DI / 128, M_ / 128), 256, SMEM, s3>>>(
        hH, hL, DM, 0, w1H + (size_t)DI * DM, w1L + (size_t)DI * DM, z,
        nullptr, nullptr, 0, 0, nullptr, nullptr, DI, DM);
    cudaEventRecord(eZ, s3);
    splitOn(s3, delta,     dlH, dlL, DTR, DTR, 0, (size_t)M_ * DTR);
    splitOn(s3, dt_proj_w, dtH, dtL, DTR, DTR, 0, (size_t)DI * DTR);
    gemm_bf16x3<3, false, true><<<dim3(DI / 128, M_ / 128), 256, SMEM, s3>>>(
        dlH, dlL, DTR, 0, dtH, dtL, dc, nullptr, nullptr, 0, 0,
        dt_proj_b, A_log, DI, DTR);
    cudaEventRecord(eDT, s3);
    splitOn(s3, out_proj_w, woH, woL, DI, DI, 0, (size_t)DM * DI);
    cudaEventRecord(eWO, s3);

    // ---- pipe 1 (batch 1) on m1, staggered after x0 ----
    cudaStreamWaitEvent(m1, eHW, 0);
    cudaStreamWaitEvent(m1, eX0, 0);
    gemm_bf16x3<0, true, false><<<dim3(DI / 128, GYH), 256, SMEM, m1>>>(
        hH + (size_t)L_ * DM, hL + (size_t)L_ * DM, DM, 0, w1H, w1L, nullptr,
        xwH + (size_t)L_ * DI, xwL + (size_t)L_ * DI, DI, 0,
        nullptr, nullptr, DI, DM);
    conv_silu_kernel<<<(L_ * DI) / 256, 256, 0, m1>>>(conv_w, conv_b, 1);
    cudaStreamWaitEvent(m1, eW2, 0);
    cudaStreamWaitEvent(m1, eG, 0);
    gemm_bf16x3<0, false, true><<<dim3(TWO_DI / 128, GYH), 256, SMEM, m1>>>(
        xH + (size_t)L_ * DI, xL + (size_t)L_ * DI, DI, 0, wcH, wcL,
        y + (size_t)L_ * TWO_DI, nullptr, nullptr, 0, 0,
        nullptr, nullptr, TWO_DI, DI);
    cudaStreamWaitEvent(m1, eDT, 0);
    fscan_p1<<<gScan, 256, 0, m1>>>(1);
    cudaStreamWaitEvent(m1, eZ, 0);
    fscan_p3<<<gScan, 256, 0, m1>>>(D_ss, 1);
    cudaStreamWaitEvent(m1, eWO, 0);
    gemm_bf16x3<0, false, true><<<dim3(DM / 128, GYH), 256, SMEM, m1>>>(
        opH + (size_t)L_ * DI, opL + (size_t)L_ * DI, DI, 0, woH, woL,
        out + (size_t)L_ * DM, nullptr, nullptr, 0, 0,
        nullptr, nullptr, DM, DI);
    cudaEventRecord(eP1, m1);

    // ---- pipe 0 (batch 0) on default stream ----
    conv_silu_kernel<<<(L_ * DI) / 256, 256>>>(conv_w, conv_b, 0);
    cudaStreamWaitEvent(0, eW2, 0);
    cudaStreamWaitEvent(0, eG, 0);
    gemm_bf16x3<0, false, true><<<dim3(TWO_DI / 128, GYH), 256, SMEM>>>(
        xH, xL, DI, 0, wcH, wcL, y, nullptr, nullptr, 0, 0,
        nullptr, nullptr, TWO_DI, DI);
    cudaStreamWaitEvent(0, eDT, 0);
    fscan_p1<<<gScan, 256>>>(0);
    cudaStreamWaitEvent(0, eZ, 0);
    fscan_p3<<<gScan, 256>>>(D_ss, 0);
    cudaStreamWaitEvent(0, eWO, 0);
    gemm_bf16x3<0, false, true><<<dim3(DM / 128, GYH), 256, SMEM>>>(
        opH, opL, DI, 0, woH, woL, out, nullptr, nullptr, 0, 0,
        nullptr, nullptr, DM, DI);

    // join pipe 1 back into the capturing stream
    cudaStreamWaitEvent(0, eP1, 0);
}